// round 1
// baseline (speedup 1.0000x reference)
#include <cuda_runtime.h>
#include <math.h>

#define B_      2048
#define N_NUCP  4
#define N_ELECP 16
#define N_PARTP 20
#define N_NODES (B_ * N_PARTP)   // 40960
#define N_EROWS (B_ * N_ELECP)   // 32768
#define E_      307200
#define D_      64
#define K_      128
#define EMB_    256
#define LOG2F_  0.69314718055994530942f

// ---- scratch (static __device__ arrays; no allocation allowed) ----
__device__ float g_hx[N_NODES * K_];          // 40960*128  (~21 MB)
__device__ float g_z[3 * N_EROWS * K_];       // 3*32768*128 (~50 MB)
__device__ int   g_list[3 * E_];
__device__ int   g_cnt[4];

// ============================================================
// K1: zero z channels + counters
// ============================================================
__global__ void k_zero() {
    int i = blockIdx.x * blockDim.x + threadIdx.x;
    const int n4 = 3 * N_EROWS * K_ / 4;
    if (i < n4) ((float4*)g_z)[i] = make_float4(0.f, 0.f, 0.f, 0.f);
    if (i < 4) g_cnt[i] = 0;
}

// ============================================================
// K2: bin edges by type, dropping edges whose receiver is a nucleus
// slot: 0 = same (e_type 3), 1 = anti (4), 2 = nuc (1)
// ============================================================
__global__ void k_bin(const int* __restrict__ e_type,
                      const int* __restrict__ receivers) {
    int e = blockIdx.x * blockDim.x + threadIdx.x;
    if (e >= E_) return;
    int r = receivers[e];
    if ((r % N_PARTP) < N_NUCP) return;   // receiver is a nucleus -> z row discarded
    int ty = e_type[e];
    int slot = (ty == 3) ? 0 : ((ty == 4) ? 1 : 2);
    int pos = atomicAdd(&g_cnt[slot], 1);
    g_list[slot * E_ + pos] = e;
}

// ============================================================
// K3: hx nucleus rows (plain copy)
// ============================================================
__global__ void k_hx_nuc(const float* __restrict__ nuc) {
    int i = blockIdx.x * blockDim.x + threadIdx.x;   // float4 index
    const int n4 = B_ * N_NUCP * K_ / 4;
    if (i >= n4) return;
    int k4  = i & (K_ / 4 - 1);   // 32 float4 per row
    int row = i >> 5;             // b*4 + p
    int b = row >> 2, p = row & 3;
    ((float4*)g_hx)[((size_t)(b * N_PARTP + p)) * (K_ / 4) + k4] =
        ((const float4*)nuc)[i];
}

// ============================================================
// K4: hx electron rows: elec @ h_W + h_b   [32768x256]@[256x128]
// BM=64 BN=128 BK=32, 256 threads, 4x8 micro-tile
// ============================================================
__global__ void __launch_bounds__(256)
k_hx_gemm(const float* __restrict__ elec,
          const float* __restrict__ hW,
          const float* __restrict__ hb) {
    __shared__ __align__(16) float sA[64 * 32];
    __shared__ __align__(16) float sB[32 * 128];
    int tid = threadIdx.x;
    int tx = tid & 15, ty = tid >> 4;
    int m0 = blockIdx.x * 64;
    float acc[4][8];
#pragma unroll
    for (int i = 0; i < 4; i++)
#pragma unroll
        for (int j = 0; j < 8; j++) acc[i][j] = 0.f;

    for (int k0 = 0; k0 < EMB_; k0 += 32) {
#pragma unroll
        for (int r = 0; r < 2; r++) {
            int idx = tid + r * 256;        // 512 float4 total
            int row = idx >> 3, c4 = idx & 7;
            ((float4*)sA)[idx] =
                ((const float4*)(elec + (size_t)(m0 + row) * EMB_ + k0))[c4];
        }
#pragma unroll
        for (int r = 0; r < 4; r++) {
            int idx = tid + r * 256;        // 1024 float4 total
            int row = idx >> 5, c4 = idx & 31;
            ((float4*)sB)[idx] = ((const float4*)(hW + (size_t)(k0 + row) * K_))[c4];
        }
        __syncthreads();
#pragma unroll
        for (int kk = 0; kk < 32; kk += 4) {
            float4 a4[4];
#pragma unroll
            for (int i = 0; i < 4; i++)
                a4[i] = *(const float4*)&sA[(ty * 4 + i) * 32 + kk];
#pragma unroll
            for (int q = 0; q < 4; q++) {
                float4 b0 = *(const float4*)&sB[(kk + q) * 128 + tx * 8];
                float4 b1 = *(const float4*)&sB[(kk + q) * 128 + tx * 8 + 4];
#pragma unroll
                for (int i = 0; i < 4; i++) {
                    float av = (q == 0) ? a4[i].x : (q == 1) ? a4[i].y
                               : (q == 2) ? a4[i].z : a4[i].w;
                    acc[i][0] += av * b0.x; acc[i][1] += av * b0.y;
                    acc[i][2] += av * b0.z; acc[i][3] += av * b0.w;
                    acc[i][4] += av * b1.x; acc[i][5] += av * b1.y;
                    acc[i][6] += av * b1.z; acc[i][7] += av * b1.w;
                }
            }
        }
        __syncthreads();
    }
#pragma unroll
    for (int i = 0; i < 4; i++) {
        int m = m0 + ty * 4 + i;
        int node = (m / N_ELECP) * N_PARTP + N_NUCP + (m % N_ELECP);
#pragma unroll
        for (int j = 0; j < 8; j++) {
            int n = tx * 8 + j;
            g_hx[(size_t)node * K_ + n] = acc[i][j] + hb[n];
        }
    }
}

// ============================================================
// K5: per-type edge MLP + gather*multiply + atomic scatter
// one block = 64 edges of one type; dynamic smem ~83 KB
// ============================================================
struct EdgeParams {
    const float* W1[3]; const float* b1[3];
    const float* W2[3]; const float* b2[3];
};

__global__ void __launch_bounds__(256)
k_edge(EdgeParams P,
       const float* __restrict__ dist,
       const int* __restrict__ senders,
       const int* __restrict__ receivers) {
    extern __shared__ __align__(16) float sm[];
    float* sX  = sm;               // 4096 floats
    float* sH  = sm + 4096;        // 4096
    float* sW1 = sm + 8192;        // 4096
    float* sW2 = sm + 12288;       // 8192
    float* sb1 = sm + 20480;       // 64
    float* sb2 = sm + 20544;       // 128
    int* sSend = (int*)(sm + 20672);  // 64
    int* sZrow = (int*)(sm + 20736);  // 64
    int* sEdge = (int*)(sm + 20800);  // 64  -> total 20864 floats = 83456 B
    float* sWE = sm;               // overlay: 64*128 floats over sX+sH

    int t = blockIdx.y;
    int cnt = g_cnt[t];
    int e0 = blockIdx.x * 64;
    if (e0 >= cnt) return;
    int ne = min(64, cnt - e0);
    int tid = threadIdx.x;
    int tx = tid & 15, ty = tid >> 4;

    // edge metadata
    if (tid < 64) {
        int eid = 0, sv = 0, zr = 0;
        if (tid < ne) {
            eid = g_list[t * E_ + e0 + tid];
            sv  = senders[eid];
            int r = receivers[eid];
            zr  = (r / N_PARTP) * N_ELECP + (r % N_PARTP) - N_NUCP;
        }
        sEdge[tid] = eid; sSend[tid] = sv; sZrow[tid] = zr;
    }
    // weights into smem
    {
        const float* W1 = P.W1[t]; const float* W2 = P.W2[t];
#pragma unroll
        for (int r = 0; r < 4; r++)
            ((float4*)sW1)[tid + r * 256] = ((const float4*)W1)[tid + r * 256];
#pragma unroll
        for (int r = 0; r < 8; r++)
            ((float4*)sW2)[tid + r * 256] = ((const float4*)W2)[tid + r * 256];
        if (tid < 64)  sb1[tid] = P.b1[t][tid];
        if (tid < 128) sb2[tid] = P.b2[t][tid];
    }
    __syncthreads();   // sEdge ready

    // X tile: 64 rows x 64 floats (16 float4/row)
#pragma unroll
    for (int r = 0; r < 4; r++) {
        int idx = tid + r * 256;
        int row = idx >> 4, c4 = idx & 15;
        float4 v = make_float4(0.f, 0.f, 0.f, 0.f);
        if (row < ne)
            v = ((const float4*)(dist + (size_t)sEdge[row] * D_))[c4];
        ((float4*)sX)[idx] = v;
    }
    __syncthreads();

    // ---- stage 1: H = ssp(X @ W1 + b1), 64x64, 4x4/thread ----
    float acc1[4][4];
#pragma unroll
    for (int i = 0; i < 4; i++)
#pragma unroll
        for (int j = 0; j < 4; j++) acc1[i][j] = 0.f;
#pragma unroll
    for (int kk = 0; kk < 64; kk += 4) {
        float4 a4[4];
#pragma unroll
        for (int i = 0; i < 4; i++)
            a4[i] = *(const float4*)&sX[(ty * 4 + i) * 64 + kk];
#pragma unroll
        for (int q = 0; q < 4; q++) {
            float4 b0 = ((const float4*)sW1)[(kk + q) * 16 + tx];
#pragma unroll
            for (int i = 0; i < 4; i++) {
                float av = (q == 0) ? a4[i].x : (q == 1) ? a4[i].y
                           : (q == 2) ? a4[i].z : a4[i].w;
                acc1[i][0] += av * b0.x; acc1[i][1] += av * b0.y;
                acc1[i][2] += av * b0.z; acc1[i][3] += av * b0.w;
            }
        }
    }
#pragma unroll
    for (int i = 0; i < 4; i++)
#pragma unroll
        for (int j = 0; j < 4; j++) {
            float x = acc1[i][j] + sb1[tx * 4 + j];
            float v = fmaxf(x, 0.f) + log1pf(expf(-fabsf(x))) - LOG2F_;
            sH[(ty * 4 + i) * 64 + tx * 4 + j] = v;
        }
    __syncthreads();

    // ---- stage 2: WE = H @ W2 + b2, 64x128, 4x8/thread ----
    float acc2[4][8];
#pragma unroll
    for (int i = 0; i < 4; i++)
#pragma unroll
        for (int j = 0; j < 8; j++) acc2[i][j] = 0.f;
#pragma unroll
    for (int kk = 0; kk < 64; kk += 4) {
        float4 a4[4];
#pragma unroll
        for (int i = 0; i < 4; i++)
            a4[i] = *(const float4*)&sH[(ty * 4 + i) * 64 + kk];
#pragma unroll
        for (int q = 0; q < 4; q++) {
            float4 b0 = *(const float4*)&sW2[(kk + q) * 128 + tx * 8];
            float4 b1 = *(const float4*)&sW2[(kk + q) * 128 + tx * 8 + 4];
#pragma unroll
            for (int i = 0; i < 4; i++) {
                float av = (q == 0) ? a4[i].x : (q == 1) ? a4[i].y
                           : (q == 2) ? a4[i].z : a4[i].w;
                acc2[i][0] += av * b0.x; acc2[i][1] += av * b0.y;
                acc2[i][2] += av * b0.z; acc2[i][3] += av * b0.w;
                acc2[i][4] += av * b1.x; acc2[i][5] += av * b1.y;
                acc2[i][6] += av * b1.z; acc2[i][7] += av * b1.w;
            }
        }
    }
    __syncthreads();   // done reading sX/sH; safe to overlay
#pragma unroll
    for (int i = 0; i < 4; i++)
#pragma unroll
        for (int j = 0; j < 8; j++)
            sWE[(ty * 4 + i) * 128 + tx * 8 + j] = acc2[i][j] + sb2[tx * 8 + j];
    __syncthreads();

    // ---- epilogue: weh = WE * hx[sender]; atomic scatter into z[t] ----
    float* zbase = g_z + (size_t)t * N_EROWS * K_;
    int k = tid & 127;
    int half = tid >> 7;   // 0 or 1 -> 2 edges per iteration
#pragma unroll 4
    for (int rep = 0; rep < 32; rep++) {
        int e = rep * 2 + half;
        if (e < ne) {
            float v = sWE[e * 128 + k] * g_hx[(size_t)sSend[e] * K_ + k];
            atomicAdd(zbase + (size_t)sZrow[e] * K_ + k, v);
        }
    }
}

// ============================================================
// K6: out = elec + [z0|z1|z2] @ [g_same;g_anti;g_n] + Σb
// [32768x384]@[384x256], BM=64 BN=128 BK=32
// ============================================================
__global__ void __launch_bounds__(256)
k_out(const float* __restrict__ elec,
      const float* __restrict__ gW0, const float* __restrict__ gW1,
      const float* __restrict__ gW2,
      const float* __restrict__ gb0, const float* __restrict__ gb1,
      const float* __restrict__ gb2,
      float* __restrict__ out) {
    __shared__ __align__(16) float sA[64 * 32];
    __shared__ __align__(16) float sB[32 * 128];
    int tid = threadIdx.x;
    int tx = tid & 15, ty = tid >> 4;
    int m0 = blockIdx.x * 64;
    int n0 = blockIdx.y * 128;
    float acc[4][8];
#pragma unroll
    for (int i = 0; i < 4; i++)
#pragma unroll
        for (int j = 0; j < 8; j++) acc[i][j] = 0.f;

    for (int k0 = 0; k0 < 384; k0 += 32) {
        int t = k0 >> 7;
        int kc = k0 & 127;
        const float* zsrc = g_z + (size_t)t * N_EROWS * K_;
        const float* gW = (t == 0) ? gW0 : ((t == 1) ? gW1 : gW2);
#pragma unroll
        for (int r = 0; r < 2; r++) {
            int idx = tid + r * 256;
            int row = idx >> 3, c4 = idx & 7;
            ((float4*)sA)[idx] =
                ((const float4*)(zsrc + (size_t)(m0 + row) * K_ + kc))[c4];
        }
#pragma unroll
        for (int r = 0; r < 4; r++) {
            int idx = tid + r * 256;
            int row = idx >> 5, c4 = idx & 31;
            ((float4*)sB)[idx] =
                ((const float4*)(gW + (size_t)(kc + row) * EMB_ + n0))[c4];
        }
        __syncthreads();
#pragma unroll
        for (int kk = 0; kk < 32; kk += 4) {
            float4 a4[4];
#pragma unroll
            for (int i = 0; i < 4; i++)
                a4[i] = *(const float4*)&sA[(ty * 4 + i) * 32 + kk];
#pragma unroll
            for (int q = 0; q < 4; q++) {
                float4 b0 = *(const float4*)&sB[(kk + q) * 128 + tx * 8];
                float4 b1 = *(const float4*)&sB[(kk + q) * 128 + tx * 8 + 4];
#pragma unroll
                for (int i = 0; i < 4; i++) {
                    float av = (q == 0) ? a4[i].x : (q == 1) ? a4[i].y
                               : (q == 2) ? a4[i].z : a4[i].w;
                    acc[i][0] += av * b0.x; acc[i][1] += av * b0.y;
                    acc[i][2] += av * b0.z; acc[i][3] += av * b0.w;
                    acc[i][4] += av * b1.x; acc[i][5] += av * b1.y;
                    acc[i][6] += av * b1.z; acc[i][7] += av * b1.w;
                }
            }
        }
        __syncthreads();
    }
#pragma unroll
    for (int i = 0; i < 4; i++) {
        int m = m0 + ty * 4 + i;
#pragma unroll
        for (int j = 0; j < 8; j++) {
            int n = n0 + tx * 8 + j;
            float bsum = gb0[n] + gb1[n] + gb2[n];
            out[(size_t)m * EMB_ + n] = elec[(size_t)m * EMB_ + n] + acc[i][j] + bsum;
        }
    }
}

// ============================================================
// launch
// ============================================================
extern "C" void kernel_launch(void* const* d_in, const int* in_sizes, int n_in,
                              void* d_out, int out_size) {
    const float* nuc       = (const float*)d_in[0];
    const float* elec      = (const float*)d_in[1];
    const float* dist      = (const float*)d_in[2];
    const int*   e_type    = (const int*)d_in[3];
    const int*   senders   = (const int*)d_in[4];
    const int*   receivers = (const int*)d_in[5];
    // slot order: 0 = same, 1 = anti, 2 = nuc (matches e_type 3/4/1 mapping)
    EdgeParams P;
    P.W1[0] = (const float*)d_in[6];  P.b1[0] = (const float*)d_in[7];
    P.W2[0] = (const float*)d_in[8];  P.b2[0] = (const float*)d_in[9];
    P.W1[1] = (const float*)d_in[10]; P.b1[1] = (const float*)d_in[11];
    P.W2[1] = (const float*)d_in[12]; P.b2[1] = (const float*)d_in[13];
    P.W1[2] = (const float*)d_in[14]; P.b1[2] = (const float*)d_in[15];
    P.W2[2] = (const float*)d_in[16]; P.b2[2] = (const float*)d_in[17];
    const float* hW  = (const float*)d_in[18];
    const float* hb  = (const float*)d_in[19];
    const float* gsW = (const float*)d_in[20];
    const float* gsb = (const float*)d_in[21];
    const float* gaW = (const float*)d_in[22];
    const float* gab = (const float*)d_in[23];
    const float* gnW = (const float*)d_in[24];
    const float* gnb = (const float*)d_in[25];
    float* out = (float*)d_out;

    const int EDGE_SMEM = 83456;
    cudaFuncSetAttribute(k_edge, cudaFuncAttributeMaxDynamicSharedMemorySize,
                         EDGE_SMEM);

    k_zero<<<(3 * N_EROWS * K_ / 4 + 255) / 256, 256>>>();
    k_bin<<<(E_ + 255) / 256, 256>>>(e_type, receivers);
    k_hx_nuc<<<(B_ * N_NUCP * K_ / 4 + 255) / 256, 256>>>(nuc);
    k_hx_gemm<<<N_EROWS / 64, 256>>>(elec, hW, hb);
    dim3 ge((E_ + 63) / 64, 3);
    k_edge<<<ge, 256, EDGE_SMEM>>>(P, dist, senders, receivers);
    dim3 go(N_EROWS / 64, 2);
    k_out<<<go, 256>>>(elec, gsW, gaW, gnW, gsb, gab, gnb, out);
}

// round 4
// speedup vs baseline: 1.4757x; 1.4757x over previous
#include <cuda_runtime.h>
#include <cuda_bf16.h>
#include <math.h>
#include <stdint.h>

#define B_      2048
#define N_NUCP  4
#define N_ELECP 16
#define N_PARTP 20
#define N_NODES (B_ * N_PARTP)   // 40960
#define N_EROWS (B_ * N_ELECP)   // 32768
#define E_      307200
#define D_      64
#define K_      128
#define EMB_    256
#define LOG2F_  0.69314718055994530942f

// ---- scratch (static __device__ arrays; no allocation allowed) ----
__device__ float g_hx[N_NODES * K_];          // ~21 MB
__device__ float g_z[3 * N_EROWS * K_];       // ~50 MB
__device__ int   g_list[3 * E_];
__device__ int   g_cnt[4];

// ============================================================
// helpers: bf16 split + bf16 tensor mma
// ============================================================
__device__ __forceinline__ void splitbf(float x, __nv_bfloat16& h, __nv_bfloat16& l) {
    h = __float2bfloat16(x);
    l = __float2bfloat16(x - __bfloat162float(h));
}

__device__ __forceinline__ void mma16816(float* c, const uint32_t* a, const uint32_t* b) {
    asm volatile(
        "mma.sync.aligned.m16n8k16.row.col.f32.bf16.bf16.f32 "
        "{%0,%1,%2,%3}, {%4,%5,%6,%7}, {%8,%9}, {%0,%1,%2,%3};"
        : "+f"(c[0]), "+f"(c[1]), "+f"(c[2]), "+f"(c[3])
        : "r"(a[0]), "r"(a[1]), "r"(a[2]), "r"(a[3]), "r"(b[0]), "r"(b[1]));
}

// ============================================================
// K1: zero z channels + counters
// ============================================================
__global__ void k_zero() {
    int i = blockIdx.x * blockDim.x + threadIdx.x;
    const int n4 = 3 * N_EROWS * K_ / 4;
    if (i < n4) ((float4*)g_z)[i] = make_float4(0.f, 0.f, 0.f, 0.f);
    if (i < 4) g_cnt[i] = 0;
}

// ============================================================
// K2: bin edges by type, dropping edges whose receiver is a nucleus
// slot: 0 = same (e_type 3), 1 = anti (4), 2 = nuc (1)
// ============================================================
__global__ void k_bin(const int* __restrict__ e_type,
                      const int* __restrict__ receivers) {
    int e = blockIdx.x * blockDim.x + threadIdx.x;
    if (e >= E_) return;
    int r = receivers[e];
    if ((r % N_PARTP) < N_NUCP) return;
    int ty = e_type[e];
    int slot = (ty == 3) ? 0 : ((ty == 4) ? 1 : 2);
    int pos = atomicAdd(&g_cnt[slot], 1);
    g_list[slot * E_ + pos] = e;
}

// ============================================================
// K3: hx nucleus rows (plain copy)
// ============================================================
__global__ void k_hx_nuc(const float* __restrict__ nuc) {
    int i = blockIdx.x * blockDim.x + threadIdx.x;
    const int n4 = B_ * N_NUCP * K_ / 4;
    if (i >= n4) return;
    int k4  = i & (K_ / 4 - 1);
    int row = i >> 5;
    int b = row >> 2, p = row & 3;
    ((float4*)g_hx)[((size_t)(b * N_PARTP + p)) * (K_ / 4) + k4] =
        ((const float4*)nuc)[i];
}

// ============================================================
// K4: hx electron rows via bf16-split tensor mma (3-pass)
// C[32768x128] = elec[32768x256] @ hW[256x128] + hb
// BM=128 BN=64 BK=32, 256 thr, warps 4(m)x2(n), warp tile 32x32
// ============================================================
#define SA_ 40   // padded smem row stride (bf16 units) for BK=32

__global__ void __launch_bounds__(256)
k_hx_mma(const float* __restrict__ elec,
         const float* __restrict__ hW,
         const float* __restrict__ hb) {
    __shared__ __align__(16) __nv_bfloat16 sAh[128 * SA_], sAl[128 * SA_];
    __shared__ __align__(16) __nv_bfloat16 sBh[64 * SA_],  sBl[64 * SA_];
    __shared__ float sBias[64];
    int tid = threadIdx.x, lane = tid & 31, w = tid >> 5;
    int wm = (w & 3) * 32, wn = (w >> 2) * 32;
    int g = lane >> 2, t = lane & 3;
    int m0 = blockIdx.x * 128, n0 = blockIdx.y * 64;
    if (tid < 64) sBias[tid] = hb[n0 + tid];

    float acc[2][4][4];
#pragma unroll
    for (int a = 0; a < 2; a++)
#pragma unroll
        for (int b = 0; b < 4; b++)
#pragma unroll
            for (int c = 0; c < 4; c++) acc[a][b][c] = 0.f;

    float4 pA[4]; float pB[8];

    // prefetch iter 0
    {
        const float* Ab = elec + (size_t)m0 * EMB_;
#pragma unroll
        for (int r = 0; r < 4; r++) {
            int idx = tid + r * 256, row = idx >> 3, c4 = idx & 7;
            pA[r] = *(const float4*)(Ab + (size_t)row * EMB_ + c4 * 4);
        }
#pragma unroll
        for (int r = 0; r < 8; r++) {
            int idx = tid + r * 256, n = idx & 63, k = idx >> 6;
            pB[r] = hW[(size_t)k * K_ + n0 + n];
        }
    }

    for (int it = 0; it < 8; it++) {
        __syncthreads();
        // store smem (split)
#pragma unroll
        for (int r = 0; r < 4; r++) {
            int idx = tid + r * 256, row = idx >> 3, c = (idx & 7) * 4;
            float4 v = pA[r];
            __nv_bfloat16 h0, l0, h1, l1, h2, l2, h3, l3;
            splitbf(v.x, h0, l0); splitbf(v.y, h1, l1);
            splitbf(v.z, h2, l2); splitbf(v.w, h3, l3);
            *(__nv_bfloat162*)&sAh[row * SA_ + c]     = __halves2bfloat162(h0, h1);
            *(__nv_bfloat162*)&sAh[row * SA_ + c + 2] = __halves2bfloat162(h2, h3);
            *(__nv_bfloat162*)&sAl[row * SA_ + c]     = __halves2bfloat162(l0, l1);
            *(__nv_bfloat162*)&sAl[row * SA_ + c + 2] = __halves2bfloat162(l2, l3);
        }
#pragma unroll
        for (int r = 0; r < 8; r++) {
            int idx = tid + r * 256, n = idx & 63, k = idx >> 6;
            __nv_bfloat16 h, l; splitbf(pB[r], h, l);
            sBh[n * SA_ + k] = h; sBl[n * SA_ + k] = l;
        }
        __syncthreads();
        // prefetch next
        if (it < 7) {
            int k0 = (it + 1) * 32;
            const float* Ab = elec + (size_t)m0 * EMB_ + k0;
#pragma unroll
            for (int r = 0; r < 4; r++) {
                int idx = tid + r * 256, row = idx >> 3, c4 = idx & 7;
                pA[r] = *(const float4*)(Ab + (size_t)row * EMB_ + c4 * 4);
            }
#pragma unroll
            for (int r = 0; r < 8; r++) {
                int idx = tid + r * 256, n = idx & 63, k = idx >> 6;
                pB[r] = hW[(size_t)(k0 + k) * K_ + n0 + n];
            }
        }
        // compute: 2 k16 steps
#pragma unroll
        for (int s = 0; s < 2; s++) {
            int kb = s * 16;
            uint32_t ah[2][4], al[2][4], bh[4][2], bl[4][2];
#pragma unroll
            for (int mt = 0; mt < 2; mt++) {
                int r0 = wm + mt * 16 + g;
                ah[mt][0] = *(uint32_t*)&sAh[r0 * SA_ + kb + 2 * t];
                ah[mt][1] = *(uint32_t*)&sAh[(r0 + 8) * SA_ + kb + 2 * t];
                ah[mt][2] = *(uint32_t*)&sAh[r0 * SA_ + kb + 8 + 2 * t];
                ah[mt][3] = *(uint32_t*)&sAh[(r0 + 8) * SA_ + kb + 8 + 2 * t];
                al[mt][0] = *(uint32_t*)&sAl[r0 * SA_ + kb + 2 * t];
                al[mt][1] = *(uint32_t*)&sAl[(r0 + 8) * SA_ + kb + 2 * t];
                al[mt][2] = *(uint32_t*)&sAl[r0 * SA_ + kb + 8 + 2 * t];
                al[mt][3] = *(uint32_t*)&sAl[(r0 + 8) * SA_ + kb + 8 + 2 * t];
            }
#pragma unroll
            for (int nt = 0; nt < 4; nt++) {
                int n = wn + nt * 8 + g;
                bh[nt][0] = *(uint32_t*)&sBh[n * SA_ + kb + 2 * t];
                bh[nt][1] = *(uint32_t*)&sBh[n * SA_ + kb + 8 + 2 * t];
                bl[nt][0] = *(uint32_t*)&sBl[n * SA_ + kb + 2 * t];
                bl[nt][1] = *(uint32_t*)&sBl[n * SA_ + kb + 8 + 2 * t];
            }
#pragma unroll
            for (int mt = 0; mt < 2; mt++)
#pragma unroll
                for (int nt = 0; nt < 4; nt++) {
                    mma16816(acc[mt][nt], ah[mt], bh[nt]);
                    mma16816(acc[mt][nt], ah[mt], bl[nt]);
                    mma16816(acc[mt][nt], al[mt], bh[nt]);
                }
        }
    }
    // epilogue -> g_hx with node remap
#pragma unroll
    for (int mt = 0; mt < 2; mt++) {
        int r0 = m0 + wm + mt * 16 + g;
        int r1 = r0 + 8;
        int node0 = (r0 >> 4) * N_PARTP + N_NUCP + (r0 & 15);
        int node1 = (r1 >> 4) * N_PARTP + N_NUCP + (r1 & 15);
#pragma unroll
        for (int nt = 0; nt < 4; nt++) {
            int cn = n0 + wn + nt * 8 + 2 * t;
            float bs0 = sBias[cn - n0], bs1 = sBias[cn - n0 + 1];
            float2 o0 = make_float2(acc[mt][nt][0] + bs0, acc[mt][nt][1] + bs1);
            float2 o1 = make_float2(acc[mt][nt][2] + bs0, acc[mt][nt][3] + bs1);
            *(float2*)(g_hx + (size_t)node0 * K_ + cn) = o0;
            *(float2*)(g_hx + (size_t)node1 * K_ + cn) = o1;
        }
    }
}

// ============================================================
// K5: per-type edge MLP (fp32) + gather*multiply + atomic scatter
// ============================================================
struct EdgeParams {
    const float* W1[3]; const float* b1[3];
    const float* W2[3]; const float* b2[3];
};

__global__ void __launch_bounds__(256)
k_edge(EdgeParams P,
       const float* __restrict__ dist,
       const int* __restrict__ senders,
       const int* __restrict__ receivers) {
    extern __shared__ __align__(16) float sm[];
    float* sX  = sm;               // 4096 floats
    float* sH  = sm + 4096;        // 4096
    float* sW1 = sm + 8192;        // 4096
    float* sW2 = sm + 12288;       // 8192
    float* sb1 = sm + 20480;       // 64
    float* sb2 = sm + 20544;       // 128
    int* sSend = (int*)(sm + 20672);  // 64
    int* sZrow = (int*)(sm + 20736);  // 64
    int* sEdge = (int*)(sm + 20800);  // 64  -> total 20864 floats

    int t = blockIdx.y;
    int cnt = g_cnt[t];
    int e0 = blockIdx.x * 64;
    if (e0 >= cnt) return;
    int ne = min(64, cnt - e0);
    int tid = threadIdx.x;
    int tx = tid & 15, ty = tid >> 4;

    if (tid < 64) {
        int eid = 0, sv = 0, zr = 0;
        if (tid < ne) {
            eid = g_list[t * E_ + e0 + tid];
            sv  = senders[eid];
            int r = receivers[eid];
            zr  = (r / N_PARTP) * N_ELECP + (r % N_PARTP) - N_NUCP;
        }
        sEdge[tid] = eid; sSend[tid] = sv; sZrow[tid] = zr;
    }
    {
        const float* W1 = P.W1[t]; const float* W2 = P.W2[t];
#pragma unroll
        for (int r = 0; r < 4; r++)
            ((float4*)sW1)[tid + r * 256] = ((const float4*)W1)[tid + r * 256];
#pragma unroll
        for (int r = 0; r < 8; r++)
            ((float4*)sW2)[tid + r * 256] = ((const float4*)W2)[tid + r * 256];
        if (tid < 64)  sb1[tid] = P.b1[t][tid];
        if (tid < 128) sb2[tid] = P.b2[t][tid];
    }
    __syncthreads();

#pragma unroll
    for (int r = 0; r < 4; r++) {
        int idx = tid + r * 256;
        int row = idx >> 4, c4 = idx & 15;
        float4 v = make_float4(0.f, 0.f, 0.f, 0.f);
        if (row < ne)
            v = ((const float4*)(dist + (size_t)sEdge[row] * D_))[c4];
        ((float4*)sX)[idx] = v;
    }
    __syncthreads();

    // stage 1: H = ssp(X @ W1 + b1)
    float acc1[4][4];
#pragma unroll
    for (int i = 0; i < 4; i++)
#pragma unroll
        for (int j = 0; j < 4; j++) acc1[i][j] = 0.f;
#pragma unroll
    for (int kk = 0; kk < 64; kk += 4) {
        float4 a4[4];
#pragma unroll
        for (int i = 0; i < 4; i++)
            a4[i] = *(const float4*)&sX[(ty * 4 + i) * 64 + kk];
#pragma unroll
        for (int q = 0; q < 4; q++) {
            float4 b0 = ((const float4*)sW1)[(kk + q) * 16 + tx];
#pragma unroll
            for (int i = 0; i < 4; i++) {
                float av = (q == 0) ? a4[i].x : (q == 1) ? a4[i].y
                           : (q == 2) ? a4[i].z : a4[i].w;
                acc1[i][0] += av * b0.x; acc1[i][1] += av * b0.y;
                acc1[i][2] += av * b0.z; acc1[i][3] += av * b0.w;
            }
        }
    }
#pragma unroll
    for (int i = 0; i < 4; i++)
#pragma unroll
        for (int j = 0; j < 4; j++) {
            float x = acc1[i][j] + sb1[tx * 4 + j];
            float v = fmaxf(x, 0.f) + log1pf(expf(-fabsf(x))) - LOG2F_;
            sH[(ty * 4 + i) * 64 + tx * 4 + j] = v;
        }
    __syncthreads();

    // stage 2: WE = H @ W2 + b2 (in regs)
    float acc2[4][8];
#pragma unroll
    for (int i = 0; i < 4; i++)
#pragma unroll
        for (int j = 0; j < 8; j++) acc2[i][j] = 0.f;
#pragma unroll
    for (int kk = 0; kk < 64; kk += 4) {
        float4 a4[4];
#pragma unroll
        for (int i = 0; i < 4; i++)
            a4[i] = *(const float4*)&sH[(ty * 4 + i) * 64 + kk];
#pragma unroll
        for (int q = 0; q < 4; q++) {
            float4 b0 = *(const float4*)&sW2[(kk + q) * 128 + tx * 8];
            float4 b1 = *(const float4*)&sW2[(kk + q) * 128 + tx * 8 + 4];
#pragma unroll
            for (int i = 0; i < 4; i++) {
                float av = (q == 0) ? a4[i].x : (q == 1) ? a4[i].y
                           : (q == 2) ? a4[i].z : a4[i].w;
                acc2[i][0] += av * b0.x; acc2[i][1] += av * b0.y;
                acc2[i][2] += av * b0.z; acc2[i][3] += av * b0.w;
                acc2[i][4] += av * b1.x; acc2[i][5] += av * b1.y;
                acc2[i][6] += av * b1.z; acc2[i][7] += av * b1.w;
            }
        }
    }

    // epilogue straight from registers: weh = (acc2+b2) * hx[sender]; atomic scatter
    float* zbase = g_z + (size_t)t * N_EROWS * K_;
#pragma unroll
    for (int i = 0; i < 4; i++) {
        int e = ty * 4 + i;
        if (e < ne) {
            const float4* hx = (const float4*)(g_hx + (size_t)sSend[e] * K_ + tx * 8);
            float4 h0 = hx[0], h1 = hx[1];
            float* zp = zbase + (size_t)sZrow[e] * K_ + tx * 8;
            atomicAdd(zp + 0, (acc2[i][0] + sb2[tx * 8 + 0]) * h0.x);
            atomicAdd(zp + 1, (acc2[i][1] + sb2[tx * 8 + 1]) * h0.y);
            atomicAdd(zp + 2, (acc2[i][2] + sb2[tx * 8 + 2]) * h0.z);
            atomicAdd(zp + 3, (acc2[i][3] + sb2[tx * 8 + 3]) * h0.w);
            atomicAdd(zp + 4, (acc2[i][4] + sb2[tx * 8 + 4]) * h1.x);
            atomicAdd(zp + 5, (acc2[i][5] + sb2[tx * 8 + 5]) * h1.y);
            atomicAdd(zp + 6, (acc2[i][6] + sb2[tx * 8 + 6]) * h1.z);
            atomicAdd(zp + 7, (acc2[i][7] + sb2[tx * 8 + 7]) * h1.w);
        }
    }
}

// ============================================================
// K6: out = elec + [z0|z1|z2] @ [g..] + Σb  via bf16-split mma
// BM=128 BN=64 BK=32, K=384 (12 iters across 3 z buffers)
// ============================================================
__global__ void __launch_bounds__(256)
k_out_mma(const float* __restrict__ elec,
          const float* __restrict__ gW0, const float* __restrict__ gW1,
          const float* __restrict__ gW2,
          const float* __restrict__ gb0, const float* __restrict__ gb1,
          const float* __restrict__ gb2,
          float* __restrict__ out) {
    __shared__ __align__(16) __nv_bfloat16 sAh[128 * SA_], sAl[128 * SA_];
    __shared__ __align__(16) __nv_bfloat16 sBh[64 * SA_],  sBl[64 * SA_];
    __shared__ float sBias[64];
    int tid = threadIdx.x, lane = tid & 31, w = tid >> 5;
    int wm = (w & 3) * 32, wn = (w >> 2) * 32;
    int g = lane >> 2, t = lane & 3;
    int m0 = blockIdx.x * 128, n0 = blockIdx.y * 64;
    if (tid < 64)
        sBias[tid] = gb0[n0 + tid] + gb1[n0 + tid] + gb2[n0 + tid];

    float acc[2][4][4];
#pragma unroll
    for (int a = 0; a < 2; a++)
#pragma unroll
        for (int b = 0; b < 4; b++)
#pragma unroll
            for (int c = 0; c < 4; c++) acc[a][b][c] = 0.f;

    float4 pA[4]; float pB[8];
    // prefetch iter 0 (tsel=0, kc=0)
    {
        const float* Az = g_z + (size_t)m0 * K_;
#pragma unroll
        for (int r = 0; r < 4; r++) {
            int idx = tid + r * 256, row = idx >> 3, c4 = idx & 7;
            pA[r] = *(const float4*)(Az + (size_t)row * K_ + c4 * 4);
        }
#pragma unroll
        for (int r = 0; r < 8; r++) {
            int idx = tid + r * 256, n = idx & 63, k = idx >> 6;
            pB[r] = gW0[(size_t)k * EMB_ + n0 + n];
        }
    }

    for (int it = 0; it < 12; it++) {
        __syncthreads();
#pragma unroll
        for (int r = 0; r < 4; r++) {
            int idx = tid + r * 256, row = idx >> 3, c = (idx & 7) * 4;
            float4 v = pA[r];
            __nv_bfloat16 h0, l0, h1, l1, h2, l2, h3, l3;
            splitbf(v.x, h0, l0); splitbf(v.y, h1, l1);
            splitbf(v.z, h2, l2); splitbf(v.w, h3, l3);
            *(__nv_bfloat162*)&sAh[row * SA_ + c]     = __halves2bfloat162(h0, h1);
            *(__nv_bfloat162*)&sAh[row * SA_ + c + 2] = __halves2bfloat162(h2, h3);
            *(__nv_bfloat162*)&sAl[row * SA_ + c]     = __halves2bfloat162(l0, l1);
            *(__nv_bfloat162*)&sAl[row * SA_ + c + 2] = __halves2bfloat162(l2, l3);
        }
#pragma unroll
        for (int r = 0; r < 8; r++) {
            int idx = tid + r * 256, n = idx & 63, k = idx >> 6;
            __nv_bfloat16 h, l; splitbf(pB[r], h, l);
            sBh[n * SA_ + k] = h; sBl[n * SA_ + k] = l;
        }
        __syncthreads();
        if (it < 11) {
            int k0 = (it + 1) * 32;
            int tsel = k0 >> 7, kc = k0 & 127;
            const float* Az = g_z + (size_t)tsel * N_EROWS * K_ +
                              (size_t)m0 * K_ + kc;
            const float* Bw = (tsel == 0) ? gW0 : ((tsel == 1) ? gW1 : gW2);
#pragma unroll
            for (int r = 0; r < 4; r++) {
                int idx = tid + r * 256, row = idx >> 3, c4 = idx & 7;
                pA[r] = *(const float4*)(Az + (size_t)row * K_ + c4 * 4);
            }
#pragma unroll
            for (int r = 0; r < 8; r++) {
                int idx = tid + r * 256, n = idx & 63, k = idx >> 6;
                pB[r] = Bw[(size_t)(kc + k) * EMB_ + n0 + n];
            }
        }
#pragma unroll
        for (int s = 0; s < 2; s++) {
            int kb = s * 16;
            uint32_t ah[2][4], al[2][4], bh[4][2], bl[4][2];
#pragma unroll
            for (int mt = 0; mt < 2; mt++) {
                int r0 = wm + mt * 16 + g;
                ah[mt][0] = *(uint32_t*)&sAh[r0 * SA_ + kb + 2 * t];
                ah[mt][1] = *(uint32_t*)&sAh[(r0 + 8) * SA_ + kb + 2 * t];
                ah[mt][2] = *(uint32_t*)&sAh[r0 * SA_ + kb + 8 + 2 * t];
                ah[mt][3] = *(uint32_t*)&sAh[(r0 + 8) * SA_ + kb + 8 + 2 * t];
                al[mt][0] = *(uint32_t*)&sAl[r0 * SA_ + kb + 2 * t];
                al[mt][1] = *(uint32_t*)&sAl[(r0 + 8) * SA_ + kb + 2 * t];
                al[mt][2] = *(uint32_t*)&sAl[r0 * SA_ + kb + 8 + 2 * t];
                al[mt][3] = *(uint32_t*)&sAl[(r0 + 8) * SA_ + kb + 8 + 2 * t];
            }
#pragma unroll
            for (int nt = 0; nt < 4; nt++) {
                int n = wn + nt * 8 + g;
                bh[nt][0] = *(uint32_t*)&sBh[n * SA_ + kb + 2 * t];
                bh[nt][1] = *(uint32_t*)&sBh[n * SA_ + kb + 8 + 2 * t];
                bl[nt][0] = *(uint32_t*)&sBl[n * SA_ + kb + 2 * t];
                bl[nt][1] = *(uint32_t*)&sBl[n * SA_ + kb + 8 + 2 * t];
            }
#pragma unroll
            for (int mt = 0; mt < 2; mt++)
#pragma unroll
                for (int nt = 0; nt < 4; nt++) {
                    mma16816(acc[mt][nt], ah[mt], bh[nt]);
                    mma16816(acc[mt][nt], ah[mt], bl[nt]);
                    mma16816(acc[mt][nt], al[mt], bh[nt]);
                }
        }
    }
#pragma unroll
    for (int mt = 0; mt < 2; mt++) {
        int r0 = m0 + wm + mt * 16 + g;
        int r1 = r0 + 8;
#pragma unroll
        for (int nt = 0; nt < 4; nt++) {
            int cn = n0 + wn + nt * 8 + 2 * t;
            float2 e0 = *(const float2*)(elec + (size_t)r0 * EMB_ + cn);
            float2 e1 = *(const float2*)(elec + (size_t)r1 * EMB_ + cn);
            float bs0 = sBias[cn - n0], bs1 = sBias[cn - n0 + 1];
            float2 o0 = make_float2(acc[mt][nt][0] + e0.x + bs0,
                                    acc[mt][nt][1] + e0.y + bs1);
            float2 o1 = make_float2(acc[mt][nt][2] + e1.x + bs0,
                                    acc[mt][nt][3] + e1.y + bs1);
            *(float2*)(out + (size_t)r0 * EMB_ + cn) = o0;
            *(float2*)(out + (size_t)r1 * EMB_ + cn) = o1;
        }
    }
}

// ============================================================
// launch
// ============================================================
extern "C" void kernel_launch(void* const* d_in, const int* in_sizes, int n_in,
                              void* d_out, int out_size) {
    const float* nuc       = (const float*)d_in[0];
    const float* elec      = (const float*)d_in[1];
    const float* dist      = (const float*)d_in[2];
    const int*   e_type    = (const int*)d_in[3];
    const int*   senders   = (const int*)d_in[4];
    const int*   receivers = (const int*)d_in[5];
    EdgeParams P;
    P.W1[0] = (const float*)d_in[6];  P.b1[0] = (const float*)d_in[7];
    P.W2[0] = (const float*)d_in[8];  P.b2[0] = (const float*)d_in[9];
    P.W1[1] = (const float*)d_in[10]; P.b1[1] = (const float*)d_in[11];
    P.W2[1] = (const float*)d_in[12]; P.b2[1] = (const float*)d_in[13];
    P.W1[2] = (const float*)d_in[14]; P.b1[2] = (const float*)d_in[15];
    P.W2[2] = (const float*)d_in[16]; P.b2[2] = (const float*)d_in[17];
    const float* hW  = (const float*)d_in[18];
    const float* hb  = (const float*)d_in[19];
    const float* gsW = (const float*)d_in[20];
    const float* gsb = (const float*)d_in[21];
    const float* gaW = (const float*)d_in[22];
    const float* gab = (const float*)d_in[23];
    const float* gnW = (const float*)d_in[24];
    const float* gnb = (const float*)d_in[25];
    float* out = (float*)d_out;

    const int EDGE_SMEM = 83456;
    cudaFuncSetAttribute(k_edge, cudaFuncAttributeMaxDynamicSharedMemorySize,
                         EDGE_SMEM);

    k_zero<<<(3 * N_EROWS * K_ / 4 + 255) / 256, 256>>>();
    k_bin<<<(E_ + 255) / 256, 256>>>(e_type, receivers);
    k_hx_nuc<<<(B_ * N_NUCP * K_ / 4 + 255) / 256, 256>>>(nuc);
    dim3 gh(N_EROWS / 128, K_ / 64);
    k_hx_mma<<<gh, 256>>>(elec, hW, hb);
    dim3 ge((E_ + 63) / 64, 3);
    k_edge<<<ge, 256, EDGE_SMEM>>>(P, dist, senders, receivers);
    dim3 go(N_EROWS / 128, EMB_ / 64);
    k_out_mma<<<go, 256>>>(elec, gsW, gaW, gnW, gsb, gab, gnb, out);
}

// round 6
// speedup vs baseline: 1.8769x; 1.2718x over previous
#include <cuda_runtime.h>
#include <cuda_bf16.h>
#include <math.h>
#include <stdint.h>

#define B_      2048
#define N_NUCP  4
#define N_ELECP 16
#define N_PARTP 20
#define N_NODES (B_ * N_PARTP)   // 40960
#define N_EROWS (B_ * N_ELECP)   // 32768
#define E_      307200
#define D_      64
#define K_      128
#define EMB_    256
#define LOG2F_  0.69314718055994530942f

// ---- scratch (static __device__ arrays; no allocation allowed) ----
__device__ float g_hx[N_NODES * K_];          // ~21 MB
__device__ float g_z[3 * N_EROWS * K_];       // ~50 MB
__device__ int   g_list[3 * E_];
__device__ int   g_cnt[4];

// ============================================================
// helpers: bf16 split + bf16 tensor mma + vector RED
// ============================================================
__device__ __forceinline__ void splitbf(float x, __nv_bfloat16& h, __nv_bfloat16& l) {
    h = __float2bfloat16(x);
    l = __float2bfloat16(x - __bfloat162float(h));
}

__device__ __forceinline__ void mma16816(float* c, const uint32_t* a, const uint32_t* b) {
    asm volatile(
        "mma.sync.aligned.m16n8k16.row.col.f32.bf16.bf16.f32 "
        "{%0,%1,%2,%3}, {%4,%5,%6,%7}, {%8,%9}, {%0,%1,%2,%3};"
        : "+f"(c[0]), "+f"(c[1]), "+f"(c[2]), "+f"(c[3])
        : "r"(a[0]), "r"(a[1]), "r"(a[2]), "r"(a[3]), "r"(b[0]), "r"(b[1]));
}

__device__ __forceinline__ void red2(float* p, float x, float y) {
    asm volatile("red.global.add.v2.f32 [%0], {%1,%2};"
                 :: "l"(p), "f"(x), "f"(y) : "memory");
}

// ============================================================
// K1: zero z channels + counters
// ============================================================
__global__ void k_zero() {
    int i = blockIdx.x * blockDim.x + threadIdx.x;
    const int n4 = 3 * N_EROWS * K_ / 4;
    if (i < n4) ((float4*)g_z)[i] = make_float4(0.f, 0.f, 0.f, 0.f);
    if (i < 4) g_cnt[i] = 0;
}

// ============================================================
// K2: bin edges by type, dropping edges whose receiver is a nucleus
// slot: 0 = same (e_type 3), 1 = anti (4), 2 = nuc (1)
// ============================================================
__global__ void k_bin(const int* __restrict__ e_type,
                      const int* __restrict__ receivers) {
    int e = blockIdx.x * blockDim.x + threadIdx.x;
    if (e >= E_) return;
    int r = receivers[e];
    if ((r % N_PARTP) < N_NUCP) return;
    int ty = e_type[e];
    int slot = (ty == 3) ? 0 : ((ty == 4) ? 1 : 2);
    int pos = atomicAdd(&g_cnt[slot], 1);
    g_list[slot * E_ + pos] = e;
}

// ============================================================
// K3: hx nucleus rows (plain copy)
// ============================================================
__global__ void k_hx_nuc(const float* __restrict__ nuc) {
    int i = blockIdx.x * blockDim.x + threadIdx.x;
    const int n4 = B_ * N_NUCP * K_ / 4;
    if (i >= n4) return;
    int k4  = i & (K_ / 4 - 1);
    int row = i >> 5;
    int b = row >> 2, p = row & 3;
    ((float4*)g_hx)[((size_t)(b * N_PARTP + p)) * (K_ / 4) + k4] =
        ((const float4*)nuc)[i];
}

// ============================================================
// K4: hx electron rows via bf16-split tensor mma (3-pass)  [verified R4]
// ============================================================
#define SA_ 40   // padded smem row stride (bf16) for BK=32

__global__ void __launch_bounds__(256)
k_hx_mma(const float* __restrict__ elec,
         const float* __restrict__ hW,
         const float* __restrict__ hb) {
    __shared__ __align__(16) __nv_bfloat16 sAh[128 * SA_], sAl[128 * SA_];
    __shared__ __align__(16) __nv_bfloat16 sBh[64 * SA_],  sBl[64 * SA_];
    __shared__ float sBias[64];
    int tid = threadIdx.x, lane = tid & 31, w = tid >> 5;
    int wm = (w & 3) * 32, wn = (w >> 2) * 32;
    int g = lane >> 2, t = lane & 3;
    int m0 = blockIdx.x * 128, n0 = blockIdx.y * 64;
    if (tid < 64) sBias[tid] = hb[n0 + tid];

    float acc[2][4][4];
#pragma unroll
    for (int a = 0; a < 2; a++)
#pragma unroll
        for (int b = 0; b < 4; b++)
#pragma unroll
            for (int c = 0; c < 4; c++) acc[a][b][c] = 0.f;

    float4 pA[4]; float pB[8];
    {
        const float* Ab = elec + (size_t)m0 * EMB_;
#pragma unroll
        for (int r = 0; r < 4; r++) {
            int idx = tid + r * 256, row = idx >> 3, c4 = idx & 7;
            pA[r] = *(const float4*)(Ab + (size_t)row * EMB_ + c4 * 4);
        }
#pragma unroll
        for (int r = 0; r < 8; r++) {
            int idx = tid + r * 256, n = idx & 63, k = idx >> 6;
            pB[r] = hW[(size_t)k * K_ + n0 + n];
        }
    }

    for (int it = 0; it < 8; it++) {
        __syncthreads();
#pragma unroll
        for (int r = 0; r < 4; r++) {
            int idx = tid + r * 256, row = idx >> 3, c = (idx & 7) * 4;
            float4 v = pA[r];
            __nv_bfloat16 h0, l0, h1, l1, h2, l2, h3, l3;
            splitbf(v.x, h0, l0); splitbf(v.y, h1, l1);
            splitbf(v.z, h2, l2); splitbf(v.w, h3, l3);
            *(__nv_bfloat162*)&sAh[row * SA_ + c]     = __halves2bfloat162(h0, h1);
            *(__nv_bfloat162*)&sAh[row * SA_ + c + 2] = __halves2bfloat162(h2, h3);
            *(__nv_bfloat162*)&sAl[row * SA_ + c]     = __halves2bfloat162(l0, l1);
            *(__nv_bfloat162*)&sAl[row * SA_ + c + 2] = __halves2bfloat162(l2, l3);
        }
#pragma unroll
        for (int r = 0; r < 8; r++) {
            int idx = tid + r * 256, n = idx & 63, k = idx >> 6;
            __nv_bfloat16 h, l; splitbf(pB[r], h, l);
            sBh[n * SA_ + k] = h; sBl[n * SA_ + k] = l;
        }
        __syncthreads();
        if (it < 7) {
            int k0 = (it + 1) * 32;
            const float* Ab = elec + (size_t)m0 * EMB_ + k0;
#pragma unroll
            for (int r = 0; r < 4; r++) {
                int idx = tid + r * 256, row = idx >> 3, c4 = idx & 7;
                pA[r] = *(const float4*)(Ab + (size_t)row * EMB_ + c4 * 4);
            }
#pragma unroll
            for (int r = 0; r < 8; r++) {
                int idx = tid + r * 256, n = idx & 63, k = idx >> 6;
                pB[r] = hW[(size_t)(k0 + k) * K_ + n0 + n];
            }
        }
#pragma unroll
        for (int s = 0; s < 2; s++) {
            int kb = s * 16;
            uint32_t ah[2][4], al[2][4], bh[4][2], bl[4][2];
#pragma unroll
            for (int mt = 0; mt < 2; mt++) {
                int r0 = wm + mt * 16 + g;
                ah[mt][0] = *(uint32_t*)&sAh[r0 * SA_ + kb + 2 * t];
                ah[mt][1] = *(uint32_t*)&sAh[(r0 + 8) * SA_ + kb + 2 * t];
                ah[mt][2] = *(uint32_t*)&sAh[r0 * SA_ + kb + 8 + 2 * t];
                ah[mt][3] = *(uint32_t*)&sAh[(r0 + 8) * SA_ + kb + 8 + 2 * t];
                al[mt][0] = *(uint32_t*)&sAl[r0 * SA_ + kb + 2 * t];
                al[mt][1] = *(uint32_t*)&sAl[(r0 + 8) * SA_ + kb + 2 * t];
                al[mt][2] = *(uint32_t*)&sAl[r0 * SA_ + kb + 8 + 2 * t];
                al[mt][3] = *(uint32_t*)&sAl[(r0 + 8) * SA_ + kb + 8 + 2 * t];
            }
#pragma unroll
            for (int nt = 0; nt < 4; nt++) {
                int n = wn + nt * 8 + g;
                bh[nt][0] = *(uint32_t*)&sBh[n * SA_ + kb + 2 * t];
                bh[nt][1] = *(uint32_t*)&sBh[n * SA_ + kb + 8 + 2 * t];
                bl[nt][0] = *(uint32_t*)&sBl[n * SA_ + kb + 2 * t];
                bl[nt][1] = *(uint32_t*)&sBl[n * SA_ + kb + 8 + 2 * t];
            }
#pragma unroll
            for (int mt = 0; mt < 2; mt++)
#pragma unroll
                for (int nt = 0; nt < 4; nt++) {
                    mma16816(acc[mt][nt], ah[mt], bh[nt]);
                    mma16816(acc[mt][nt], ah[mt], bl[nt]);
                    mma16816(acc[mt][nt], al[mt], bh[nt]);
                }
        }
    }
#pragma unroll
    for (int mt = 0; mt < 2; mt++) {
        int r0 = m0 + wm + mt * 16 + g;
        int r1 = r0 + 8;
        int node0 = (r0 >> 4) * N_PARTP + N_NUCP + (r0 & 15);
        int node1 = (r1 >> 4) * N_PARTP + N_NUCP + (r1 & 15);
#pragma unroll
        for (int nt = 0; nt < 4; nt++) {
            int cn = n0 + wn + nt * 8 + 2 * t;
            float bs0 = sBias[cn - n0], bs1 = sBias[cn - n0 + 1];
            float2 o0 = make_float2(acc[mt][nt][0] + bs0, acc[mt][nt][1] + bs1);
            float2 o1 = make_float2(acc[mt][nt][2] + bs0, acc[mt][nt][3] + bs1);
            *(float2*)(g_hx + (size_t)node0 * K_ + cn) = o0;
            *(float2*)(g_hx + (size_t)node1 * K_ + cn) = o1;
        }
    }
}

// ============================================================
// K5: edge MLP via bf16-split mma + gather*multiply + RED scatter
// 64 edges/block, 256 threads (8 warps), smem ~75 KB, stride 72
// ============================================================
#define SE_ 72   // padded smem row stride (bf16) for K=64

struct EdgeParams {
    const float* W1[3]; const float* b1[3];
    const float* W2[3]; const float* b2[3];
};

__global__ void __launch_bounds__(256)
k_edge(EdgeParams P,
       const float* __restrict__ dist,
       const int* __restrict__ senders,
       const int* __restrict__ receivers) {
    extern __shared__ __align__(16) char smc[];
    // bf16 regions
    __nv_bfloat16* sXh  = (__nv_bfloat16*)(smc);           // 64*72 (overlaid by Hh)
    __nv_bfloat16* sXl  = (__nv_bfloat16*)(smc + 9216);    // 64*72 (overlaid by Hl)
    __nv_bfloat16* sW1h = (__nv_bfloat16*)(smc + 18432);   // 64*72 [n][k]
    __nv_bfloat16* sW1l = (__nv_bfloat16*)(smc + 27648);
    __nv_bfloat16* sW2h = (__nv_bfloat16*)(smc + 36864);   // 128*72 [n][k]
    __nv_bfloat16* sW2l = (__nv_bfloat16*)(smc + 55296);
    float* sb1 = (float*)(smc + 73728);   // 64
    float* sb2 = (float*)(smc + 73984);   // 128
    int* sSend = (int*)(smc + 74496);     // 64
    int* sZrow = (int*)(smc + 74752);     // 64  -> total 75008 B
    __nv_bfloat16* sHh = sXh;
    __nv_bfloat16* sHl = sXl;

    int ty_ = blockIdx.y;
    int cnt = g_cnt[ty_];
    int e0 = blockIdx.x * 64;
    if (e0 >= cnt) return;
    int ne = min(64, cnt - e0);
    int tid = threadIdx.x, lane = tid & 31, w = tid >> 5;
    int g = lane >> 2, t = lane & 3;

    // ---- metadata ----
    if (tid < 64) {
        int sv = 0, zr = 0, eid = 0;
        if (tid < ne) {
            eid = g_list[ty_ * E_ + e0 + tid];
            sv  = senders[eid];
            int r = receivers[eid];
            zr  = (r / N_PARTP) * N_ELECP + (r % N_PARTP) - N_NUCP;
        }
        sSend[tid] = sv; sZrow[tid] = zr;
        // stash eid temporarily in the (not yet loaded) sb2 region
        ((int*)sb2)[tid] = eid;
    }
    __syncthreads();   // eids visible for X load

    // ---- X tile: 64 rows x 64 fp32 -> split into sXh/sXl ----
#pragma unroll
    for (int r = 0; r < 4; r++) {
        int idx = tid + r * 256;           // 1024 float4 total
        int row = idx >> 4, c4 = idx & 15;
        float4 v = make_float4(0.f, 0.f, 0.f, 0.f);
        if (row < ne) {
            int eid = ((int*)sb2)[row];
            v = ((const float4*)(dist + (size_t)eid * D_))[c4];
        }
        int c = c4 * 4;
        __nv_bfloat16 h0, l0, h1, l1, h2, l2, h3, l3;
        splitbf(v.x, h0, l0); splitbf(v.y, h1, l1);
        splitbf(v.z, h2, l2); splitbf(v.w, h3, l3);
        *(__nv_bfloat162*)&sXh[row * SE_ + c]     = __halves2bfloat162(h0, h1);
        *(__nv_bfloat162*)&sXh[row * SE_ + c + 2] = __halves2bfloat162(h2, h3);
        *(__nv_bfloat162*)&sXl[row * SE_ + c]     = __halves2bfloat162(l0, l1);
        *(__nv_bfloat162*)&sXl[row * SE_ + c + 2] = __halves2bfloat162(l2, l3);
    }
    __syncthreads();   // done reading eid from sb2 region

    // ---- weights: W1[k=64][n=64] -> sW1[n][k]; W2[k=64][n=128] -> sW2[n][k] ----
    {
        const float* W1 = P.W1[ty_]; const float* W2 = P.W2[ty_];
#pragma unroll
        for (int r = 0; r < 16; r++) {
            int idx = tid + r * 256;       // 4096
            int k = idx >> 6, n = idx & 63;
            __nv_bfloat16 h, l; splitbf(W1[idx], h, l);
            sW1h[n * SE_ + k] = h; sW1l[n * SE_ + k] = l;
        }
#pragma unroll
        for (int r = 0; r < 32; r++) {
            int idx = tid + r * 256;       // 8192
            int k = idx >> 7, n = idx & 127;
            __nv_bfloat16 h, l; splitbf(W2[idx], h, l);
            sW2h[n * SE_ + k] = h; sW2l[n * SE_ + k] = l;
        }
        if (tid < 64)  sb1[tid] = P.b1[ty_][tid];
        if (tid < 128) sb2[tid] = P.b2[ty_][tid];
    }
    __syncthreads();

    // ---- stage 1: H = ssp(X @ W1 + b1)  (64x64), warps 2(m) x 4(n=16) ----
    int wm1 = (w & 1) * 32, wn1 = (w >> 1) * 16;
    float acc1[2][2][4];
#pragma unroll
    for (int a = 0; a < 2; a++)
#pragma unroll
        for (int b = 0; b < 2; b++)
#pragma unroll
            for (int c = 0; c < 4; c++) acc1[a][b][c] = 0.f;
#pragma unroll
    for (int s = 0; s < 4; s++) {
        int kb = s * 16;
        uint32_t ah[2][4], al[2][4], bh[2][2], bl[2][2];
#pragma unroll
        for (int mt = 0; mt < 2; mt++) {
            int r0 = wm1 + mt * 16 + g;
            ah[mt][0] = *(uint32_t*)&sXh[r0 * SE_ + kb + 2 * t];
            ah[mt][1] = *(uint32_t*)&sXh[(r0 + 8) * SE_ + kb + 2 * t];
            ah[mt][2] = *(uint32_t*)&sXh[r0 * SE_ + kb + 8 + 2 * t];
            ah[mt][3] = *(uint32_t*)&sXh[(r0 + 8) * SE_ + kb + 8 + 2 * t];
            al[mt][0] = *(uint32_t*)&sXl[r0 * SE_ + kb + 2 * t];
            al[mt][1] = *(uint32_t*)&sXl[(r0 + 8) * SE_ + kb + 2 * t];
            al[mt][2] = *(uint32_t*)&sXl[r0 * SE_ + kb + 8 + 2 * t];
            al[mt][3] = *(uint32_t*)&sXl[(r0 + 8) * SE_ + kb + 8 + 2 * t];
        }
#pragma unroll
        for (int nt = 0; nt < 2; nt++) {
            int n = wn1 + nt * 8 + g;
            bh[nt][0] = *(uint32_t*)&sW1h[n * SE_ + kb + 2 * t];
            bh[nt][1] = *(uint32_t*)&sW1h[n * SE_ + kb + 8 + 2 * t];
            bl[nt][0] = *(uint32_t*)&sW1l[n * SE_ + kb + 2 * t];
            bl[nt][1] = *(uint32_t*)&sW1l[n * SE_ + kb + 8 + 2 * t];
        }
#pragma unroll
        for (int mt = 0; mt < 2; mt++)
#pragma unroll
            for (int nt = 0; nt < 2; nt++) {
                mma16816(acc1[mt][nt], ah[mt], bh[nt]);
                mma16816(acc1[mt][nt], ah[mt], bl[nt]);
                mma16816(acc1[mt][nt], al[mt], bh[nt]);
            }
    }
    __syncthreads();   // all reads of sX done; safe to overlay H

    // ssp + split + write H (overlay over sX)
#pragma unroll
    for (int mt = 0; mt < 2; mt++) {
#pragma unroll
        for (int nt = 0; nt < 2; nt++) {
            int col = wn1 + nt * 8 + 2 * t;
            float b0 = sb1[col], b1v = sb1[col + 1];
            int r0 = wm1 + mt * 16 + g;
#pragma unroll
            for (int hr = 0; hr < 2; hr++) {
                int row = r0 + hr * 8;
                float x0 = acc1[mt][nt][hr * 2 + 0] + b0;
                float x1 = acc1[mt][nt][hr * 2 + 1] + b1v;
                float v0 = fmaxf(x0, 0.f) + log1pf(expf(-fabsf(x0))) - LOG2F_;
                float v1 = fmaxf(x1, 0.f) + log1pf(expf(-fabsf(x1))) - LOG2F_;
                __nv_bfloat16 h0, l0, h1, l1;
                splitbf(v0, h0, l0); splitbf(v1, h1, l1);
                *(__nv_bfloat162*)&sHh[row * SE_ + col] = __halves2bfloat162(h0, h1);
                *(__nv_bfloat162*)&sHl[row * SE_ + col] = __halves2bfloat162(l0, l1);
            }
        }
    }
    __syncthreads();

    // ---- stage 2: WE = H @ W2 + b2  (64x128), warps 2(m) x 4(n=32) ----
    int wm2 = (w & 1) * 32, wn2 = (w >> 1) * 32;
    float acc2[2][4][4];
#pragma unroll
    for (int a = 0; a < 2; a++)
#pragma unroll
        for (int b = 0; b < 4; b++)
#pragma unroll
            for (int c = 0; c < 4; c++) acc2[a][b][c] = 0.f;
#pragma unroll
    for (int s = 0; s < 4; s++) {
        int kb = s * 16;
        uint32_t ah[2][4], al[2][4], bh[4][2], bl[4][2];
#pragma unroll
        for (int mt = 0; mt < 2; mt++) {
            int r0 = wm2 + mt * 16 + g;
            ah[mt][0] = *(uint32_t*)&sHh[r0 * SE_ + kb + 2 * t];
            ah[mt][1] = *(uint32_t*)&sHh[(r0 + 8) * SE_ + kb + 2 * t];
            ah[mt][2] = *(uint32_t*)&sHh[r0 * SE_ + kb + 8 + 2 * t];
            ah[mt][3] = *(uint32_t*)&sHh[(r0 + 8) * SE_ + kb + 8 + 2 * t];
            al[mt][0] = *(uint32_t*)&sHl[r0 * SE_ + kb + 2 * t];
            al[mt][1] = *(uint32_t*)&sHl[(r0 + 8) * SE_ + kb + 2 * t];
            al[mt][2] = *(uint32_t*)&sHl[r0 * SE_ + kb + 8 + 2 * t];
            al[mt][3] = *(uint32_t*)&sHl[(r0 + 8) * SE_ + kb + 8 + 2 * t];
        }
#pragma unroll
        for (int nt = 0; nt < 4; nt++) {
            int n = wn2 + nt * 8 + g;
            bh[nt][0] = *(uint32_t*)&sW2h[n * SE_ + kb + 2 * t];
            bh[nt][1] = *(uint32_t*)&sW2h[n * SE_ + kb + 8 + 2 * t];
            bl[nt][0] = *(uint32_t*)&sW2l[n * SE_ + kb + 2 * t];
            bl[nt][1] = *(uint32_t*)&sW2l[n * SE_ + kb + 8 + 2 * t];
        }
#pragma unroll
        for (int mt = 0; mt < 2; mt++)
#pragma unroll
            for (int nt = 0; nt < 4; nt++) {
                mma16816(acc2[mt][nt], ah[mt], bh[nt]);
                mma16816(acc2[mt][nt], ah[mt], bl[nt]);
                mma16816(acc2[mt][nt], al[mt], bh[nt]);
            }
    }

    // ---- epilogue: weh = (WE + b2) * hx[sender]; vector RED scatter ----
    float* zbase = g_z + (size_t)ty_ * N_EROWS * K_;
#pragma unroll
    for (int mt = 0; mt < 2; mt++) {
#pragma unroll
        for (int hr = 0; hr < 2; hr++) {
            int e = wm2 + mt * 16 + g + hr * 8;
            if (e < ne) {
                int sv = sSend[e], zr = sZrow[e];
                const float* hx = g_hx + (size_t)sv * K_;
                float* zp = zbase + (size_t)zr * K_;
#pragma unroll
                for (int nt = 0; nt < 4; nt++) {
                    int col = wn2 + nt * 8 + 2 * t;
                    float2 h2 = *(const float2*)(hx + col);
                    float v0 = (acc2[mt][nt][hr * 2 + 0] + sb2[col])     * h2.x;
                    float v1 = (acc2[mt][nt][hr * 2 + 1] + sb2[col + 1]) * h2.y;
                    red2(zp + col, v0, v1);
                }
            }
        }
    }
}

// ============================================================
// K6: out = elec + [z0|z1|z2] @ [g..] + Σb  via bf16-split mma  [verified R4]
// ============================================================
__global__ void __launch_bounds__(256)
k_out_mma(const float* __restrict__ elec,
          const float* __restrict__ gW0, const float* __restrict__ gW1,
          const float* __restrict__ gW2,
          const float* __restrict__ gb0, const float* __restrict__ gb1,
          const float* __restrict__ gb2,
          float* __restrict__ out) {
    __shared__ __align__(16) __nv_bfloat16 sAh[128 * SA_], sAl[128 * SA_];
    __shared__ __align__(16) __nv_bfloat16 sBh[64 * SA_],  sBl[64 * SA_];
    __shared__ float sBias[64];
    int tid = threadIdx.x, lane = tid & 31, w = tid >> 5;
    int wm = (w & 3) * 32, wn = (w >> 2) * 32;
    int g = lane >> 2, t = lane & 3;
    int m0 = blockIdx.x * 128, n0 = blockIdx.y * 64;
    if (tid < 64)
        sBias[tid] = gb0[n0 + tid] + gb1[n0 + tid] + gb2[n0 + tid];

    float acc[2][4][4];
#pragma unroll
    for (int a = 0; a < 2; a++)
#pragma unroll
        for (int b = 0; b < 4; b++)
#pragma unroll
            for (int c = 0; c < 4; c++) acc[a][b][c] = 0.f;

    float4 pA[4]; float pB[8];
    {
        const float* Az = g_z + (size_t)m0 * K_;
#pragma unroll
        for (int r = 0; r < 4; r++) {
            int idx = tid + r * 256, row = idx >> 3, c4 = idx & 7;
            pA[r] = *(const float4*)(Az + (size_t)row * K_ + c4 * 4);
        }
#pragma unroll
        for (int r = 0; r < 8; r++) {
            int idx = tid + r * 256, n = idx & 63, k = idx >> 6;
            pB[r] = gW0[(size_t)k * EMB_ + n0 + n];
        }
    }

    for (int it = 0; it < 12; it++) {
        __syncthreads();
#pragma unroll
        for (int r = 0; r < 4; r++) {
            int idx = tid + r * 256, row = idx >> 3, c = (idx & 7) * 4;
            float4 v = pA[r];
            __nv_bfloat16 h0, l0, h1, l1, h2, l2, h3, l3;
            splitbf(v.x, h0, l0); splitbf(v.y, h1, l1);
            splitbf(v.z, h2, l2); splitbf(v.w, h3, l3);
            *(__nv_bfloat162*)&sAh[row * SA_ + c]     = __halves2bfloat162(h0, h1);
            *(__nv_bfloat162*)&sAh[row * SA_ + c + 2] = __halves2bfloat162(h2, h3);
            *(__nv_bfloat162*)&sAl[row * SA_ + c]     = __halves2bfloat162(l0, l1);
            *(__nv_bfloat162*)&sAl[row * SA_ + c + 2] = __halves2bfloat162(l2, l3);
        }
#pragma unroll
        for (int r = 0; r < 8; r++) {
            int idx = tid + r * 256, n = idx & 63, k = idx >> 6;
            __nv_bfloat16 h, l; splitbf(pB[r], h, l);
            sBh[n * SA_ + k] = h; sBl[n * SA_ + k] = l;
        }
        __syncthreads();
        if (it < 11) {
            int k0 = (it + 1) * 32;
            int tsel = k0 >> 7, kc = k0 & 127;
            const float* Az = g_z + (size_t)tsel * N_EROWS * K_ +
                              (size_t)m0 * K_ + kc;
            const float* Bw = (tsel == 0) ? gW0 : ((tsel == 1) ? gW1 : gW2);
#pragma unroll
            for (int r = 0; r < 4; r++) {
                int idx = tid + r * 256, row = idx >> 3, c4 = idx & 7;
                pA[r] = *(const float4*)(Az + (size_t)row * K_ + c4 * 4);
            }
#pragma unroll
            for (int r = 0; r < 8; r++) {
                int idx = tid + r * 256, n = idx & 63, k = idx >> 6;
                pB[r] = Bw[(size_t)(kc + k) * EMB_ + n0 + n];
            }
        }
#pragma unroll
        for (int s = 0; s < 2; s++) {
            int kb = s * 16;
            uint32_t ah[2][4], al[2][4], bh[4][2], bl[4][2];
#pragma unroll
            for (int mt = 0; mt < 2; mt++) {
                int r0 = wm + mt * 16 + g;
                ah[mt][0] = *(uint32_t*)&sAh[r0 * SA_ + kb + 2 * t];
                ah[mt][1] = *(uint32_t*)&sAh[(r0 + 8) * SA_ + kb + 2 * t];
                ah[mt][2] = *(uint32_t*)&sAh[r0 * SA_ + kb + 8 + 2 * t];
                ah[mt][3] = *(uint32_t*)&sAh[(r0 + 8) * SA_ + kb + 8 + 2 * t];
                al[mt][0] = *(uint32_t*)&sAl[r0 * SA_ + kb + 2 * t];
                al[mt][1] = *(uint32_t*)&sAl[(r0 + 8) * SA_ + kb + 2 * t];
                al[mt][2] = *(uint32_t*)&sAl[r0 * SA_ + kb + 8 + 2 * t];
                al[mt][3] = *(uint32_t*)&sAl[(r0 + 8) * SA_ + kb + 8 + 2 * t];
            }
#pragma unroll
            for (int nt = 0; nt < 4; nt++) {
                int n = wn + nt * 8 + g;
                bh[nt][0] = *(uint32_t*)&sBh[n * SA_ + kb + 2 * t];
                bh[nt][1] = *(uint32_t*)&sBh[n * SA_ + kb + 8 + 2 * t];
                bl[nt][0] = *(uint32_t*)&sBl[n * SA_ + kb + 2 * t];
                bl[nt][1] = *(uint32_t*)&sBl[n * SA_ + kb + 8 + 2 * t];
            }
#pragma unroll
            for (int mt = 0; mt < 2; mt++)
#pragma unroll
                for (int nt = 0; nt < 4; nt++) {
                    mma16816(acc[mt][nt], ah[mt], bh[nt]);
                    mma16816(acc[mt][nt], ah[mt], bl[nt]);
                    mma16816(acc[mt][nt], al[mt], bh[nt]);
                }
        }
    }
#pragma unroll
    for (int mt = 0; mt < 2; mt++) {
        int r0 = m0 + wm + mt * 16 + g;
        int r1 = r0 + 8;
#pragma unroll
        for (int nt = 0; nt < 4; nt++) {
            int cn = n0 + wn + nt * 8 + 2 * t;
            float2 e0 = *(const float2*)(elec + (size_t)r0 * EMB_ + cn);
            float2 e1 = *(const float2*)(elec + (size_t)r1 * EMB_ + cn);
            float bs0 = sBias[cn - n0], bs1 = sBias[cn - n0 + 1];
            float2 o0 = make_float2(acc[mt][nt][0] + e0.x + bs0,
                                    acc[mt][nt][1] + e0.y + bs1);
            float2 o1 = make_float2(acc[mt][nt][2] + e1.x + bs0,
                                    acc[mt][nt][3] + e1.y + bs1);
            *(float2*)(out + (size_t)r0 * EMB_ + cn) = o0;
            *(float2*)(out + (size_t)r1 * EMB_ + cn) = o1;
        }
    }
}

// ============================================================
// launch
// ============================================================
extern "C" void kernel_launch(void* const* d_in, const int* in_sizes, int n_in,
                              void* d_out, int out_size) {
    const float* nuc       = (const float*)d_in[0];
    const float* elec      = (const float*)d_in[1];
    const float* dist      = (const float*)d_in[2];
    const int*   e_type    = (const int*)d_in[3];
    const int*   senders   = (const int*)d_in[4];
    const int*   receivers = (const int*)d_in[5];
    EdgeParams P;
    P.W1[0] = (const float*)d_in[6];  P.b1[0] = (const float*)d_in[7];
    P.W2[0] = (const float*)d_in[8];  P.b2[0] = (const float*)d_in[9];
    P.W1[1] = (const float*)d_in[10]; P.b1[1] = (const float*)d_in[11];
    P.W2[1] = (const float*)d_in[12]; P.b2[1] = (const float*)d_in[13];
    P.W1[2] = (const float*)d_in[14]; P.b1[2] = (const float*)d_in[15];
    P.W2[2] = (const float*)d_in[16]; P.b2[2] = (const float*)d_in[17];
    const float* hW  = (const float*)d_in[18];
    const float* hb  = (const float*)d_in[19];
    const float* gsW = (const float*)d_in[20];
    const float* gsb = (const float*)d_in[21];
    const float* gaW = (const float*)d_in[22];
    const float* gab = (const float*)d_in[23];
    const float* gnW = (const float*)d_in[24];
    const float* gnb = (const float*)d_in[25];
    float* out = (float*)d_out;

    const int EDGE_SMEM = 75008;
    cudaFuncSetAttribute(k_edge, cudaFuncAttributeMaxDynamicSharedMemorySize,
                         EDGE_SMEM);

    k_zero<<<(3 * N_EROWS * K_ / 4 + 255) / 256, 256>>>();
    k_bin<<<(E_ + 255) / 256, 256>>>(e_type, receivers);
    k_hx_nuc<<<(B_ * N_NUCP * K_ / 4 + 255) / 256, 256>>>(nuc);
    dim3 gh(N_EROWS / 128, K_ / 64);
    k_hx_mma<<<gh, 256>>>(elec, hW, hb);
    dim3 ge((E_ + 63) / 64, 3);
    k_edge<<<ge, 256, EDGE_SMEM>>>(P, dist, senders, receivers);
    dim3 go(N_EROWS / 128, EMB_ / 64);
    k_out_mma<<<go, 256>>>(elec, gsW, gaW, gnW, gsb, gab, gnb, out);
}

// round 8
// speedup vs baseline: 2.2492x; 1.1984x over previous
#include <cuda_runtime.h>
#include <cuda_bf16.h>
#include <math.h>
#include <stdint.h>

#define B_      2048
#define N_NUCP  4
#define N_ELECP 16
#define N_PARTP 20
#define N_NODES (B_ * N_PARTP)   // 40960
#define N_EROWS (B_ * N_ELECP)   // 32768
#define E_      307200
#define D_      64
#define K_      128
#define EMB_    256
#define LOG2F_  0.69314718055994530942f

// ---- scratch (static __device__ arrays; no allocation allowed) ----
__device__ float g_hx[N_NODES * K_];          // ~21 MB
__device__ float g_z[3 * N_EROWS * K_];       // ~50 MB
__device__ int   g_list[3 * E_];
__device__ int   g_cnt[4];

// ============================================================
// helpers: bf16 split + bf16 tensor mma + vector RED
// ============================================================
__device__ __forceinline__ void splitbf(float x, __nv_bfloat16& h, __nv_bfloat16& l) {
    h = __float2bfloat16(x);
    l = __float2bfloat16(x - __bfloat162float(h));
}

__device__ __forceinline__ void mma16816(float* c, const uint32_t* a, const uint32_t* b) {
    asm volatile(
        "mma.sync.aligned.m16n8k16.row.col.f32.bf16.bf16.f32 "
        "{%0,%1,%2,%3}, {%4,%5,%6,%7}, {%8,%9}, {%0,%1,%2,%3};"
        : "+f"(c[0]), "+f"(c[1]), "+f"(c[2]), "+f"(c[3])
        : "r"(a[0]), "r"(a[1]), "r"(a[2]), "r"(a[3]), "r"(b[0]), "r"(b[1]));
}

__device__ __forceinline__ void red2(float* p, float x, float y) {
    asm volatile("red.global.add.v2.f32 [%0], {%1,%2};"
                 :: "l"(p), "f"(x), "f"(y) : "memory");
}

// ============================================================
// K1: zero z channels + counters
// ============================================================
__global__ void k_zero() {
    int i = blockIdx.x * blockDim.x + threadIdx.x;
    const int n4 = 3 * N_EROWS * K_ / 4;
    if (i < n4) ((float4*)g_z)[i] = make_float4(0.f, 0.f, 0.f, 0.f);
    if (i < 4) g_cnt[i] = 0;
}

// ============================================================
// K2: bin edges by type, dropping edges whose receiver is a nucleus
// slot: 0 = same (e_type 3), 1 = anti (4), 2 = nuc (1)
// ============================================================
__global__ void k_bin(const int* __restrict__ e_type,
                      const int* __restrict__ receivers) {
    int e = blockIdx.x * blockDim.x + threadIdx.x;
    if (e >= E_) return;
    int r = receivers[e];
    if ((r % N_PARTP) < N_NUCP) return;
    int ty = e_type[e];
    int slot = (ty == 3) ? 0 : ((ty == 4) ? 1 : 2);
    int pos = atomicAdd(&g_cnt[slot], 1);
    g_list[slot * E_ + pos] = e;
}

// ============================================================
// K3: hx nucleus rows (plain copy)
// ============================================================
__global__ void k_hx_nuc(const float* __restrict__ nuc) {
    int i = blockIdx.x * blockDim.x + threadIdx.x;
    const int n4 = B_ * N_NUCP * K_ / 4;
    if (i >= n4) return;
    int k4  = i & (K_ / 4 - 1);
    int row = i >> 5;
    int b = row >> 2, p = row & 3;
    ((float4*)g_hx)[((size_t)(b * N_PARTP + p)) * (K_ / 4) + k4] =
        ((const float4*)nuc)[i];
}

// ============================================================
// K4: hx electron rows via bf16-split tensor mma (3-pass)  [verified R4]
// ============================================================
#define SA_ 40   // padded smem row stride (bf16) for BK=32

__global__ void __launch_bounds__(256)
k_hx_mma(const float* __restrict__ elec,
         const float* __restrict__ hW,
         const float* __restrict__ hb) {
    __shared__ __align__(16) __nv_bfloat16 sAh[128 * SA_], sAl[128 * SA_];
    __shared__ __align__(16) __nv_bfloat16 sBh[64 * SA_],  sBl[64 * SA_];
    __shared__ float sBias[64];
    int tid = threadIdx.x, lane = tid & 31, w = tid >> 5;
    int wm = (w & 3) * 32, wn = (w >> 2) * 32;
    int g = lane >> 2, t = lane & 3;
    int m0 = blockIdx.x * 128, n0 = blockIdx.y * 64;
    if (tid < 64) sBias[tid] = hb[n0 + tid];

    float acc[2][4][4];
#pragma unroll
    for (int a = 0; a < 2; a++)
#pragma unroll
        for (int b = 0; b < 4; b++)
#pragma unroll
            for (int c = 0; c < 4; c++) acc[a][b][c] = 0.f;

    float4 pA[4]; float pB[8];
    {
        const float* Ab = elec + (size_t)m0 * EMB_;
#pragma unroll
        for (int r = 0; r < 4; r++) {
            int idx = tid + r * 256, row = idx >> 3, c4 = idx & 7;
            pA[r] = *(const float4*)(Ab + (size_t)row * EMB_ + c4 * 4);
        }
#pragma unroll
        for (int r = 0; r < 8; r++) {
            int idx = tid + r * 256, n = idx & 63, k = idx >> 6;
            pB[r] = hW[(size_t)k * K_ + n0 + n];
        }
    }

    for (int it = 0; it < 8; it++) {
        __syncthreads();
#pragma unroll
        for (int r = 0; r < 4; r++) {
            int idx = tid + r * 256, row = idx >> 3, c = (idx & 7) * 4;
            float4 v = pA[r];
            __nv_bfloat16 h0, l0, h1, l1, h2, l2, h3, l3;
            splitbf(v.x, h0, l0); splitbf(v.y, h1, l1);
            splitbf(v.z, h2, l2); splitbf(v.w, h3, l3);
            *(__nv_bfloat162*)&sAh[row * SA_ + c]     = __halves2bfloat162(h0, h1);
            *(__nv_bfloat162*)&sAh[row * SA_ + c + 2] = __halves2bfloat162(h2, h3);
            *(__nv_bfloat162*)&sAl[row * SA_ + c]     = __halves2bfloat162(l0, l1);
            *(__nv_bfloat162*)&sAl[row * SA_ + c + 2] = __halves2bfloat162(l2, l3);
        }
#pragma unroll
        for (int r = 0; r < 8; r++) {
            int idx = tid + r * 256, n = idx & 63, k = idx >> 6;
            __nv_bfloat16 h, l; splitbf(pB[r], h, l);
            sBh[n * SA_ + k] = h; sBl[n * SA_ + k] = l;
        }
        __syncthreads();
        if (it < 7) {
            int k0 = (it + 1) * 32;
            const float* Ab = elec + (size_t)m0 * EMB_ + k0;
#pragma unroll
            for (int r = 0; r < 4; r++) {
                int idx = tid + r * 256, row = idx >> 3, c4 = idx & 7;
                pA[r] = *(const float4*)(Ab + (size_t)row * EMB_ + c4 * 4);
            }
#pragma unroll
            for (int r = 0; r < 8; r++) {
                int idx = tid + r * 256, n = idx & 63, k = idx >> 6;
                pB[r] = hW[(size_t)(k0 + k) * K_ + n0 + n];
            }
        }
#pragma unroll
        for (int s = 0; s < 2; s++) {
            int kb = s * 16;
            uint32_t ah[2][4], al[2][4], bh[4][2], bl[4][2];
#pragma unroll
            for (int mt = 0; mt < 2; mt++) {
                int r0 = wm + mt * 16 + g;
                ah[mt][0] = *(uint32_t*)&sAh[r0 * SA_ + kb + 2 * t];
                ah[mt][1] = *(uint32_t*)&sAh[(r0 + 8) * SA_ + kb + 2 * t];
                ah[mt][2] = *(uint32_t*)&sAh[r0 * SA_ + kb + 8 + 2 * t];
                ah[mt][3] = *(uint32_t*)&sAh[(r0 + 8) * SA_ + kb + 8 + 2 * t];
                al[mt][0] = *(uint32_t*)&sAl[r0 * SA_ + kb + 2 * t];
                al[mt][1] = *(uint32_t*)&sAl[(r0 + 8) * SA_ + kb + 2 * t];
                al[mt][2] = *(uint32_t*)&sAl[r0 * SA_ + kb + 8 + 2 * t];
                al[mt][3] = *(uint32_t*)&sAl[(r0 + 8) * SA_ + kb + 8 + 2 * t];
            }
#pragma unroll
            for (int nt = 0; nt < 4; nt++) {
                int n = wn + nt * 8 + g;
                bh[nt][0] = *(uint32_t*)&sBh[n * SA_ + kb + 2 * t];
                bh[nt][1] = *(uint32_t*)&sBh[n * SA_ + kb + 8 + 2 * t];
                bl[nt][0] = *(uint32_t*)&sBl[n * SA_ + kb + 2 * t];
                bl[nt][1] = *(uint32_t*)&sBl[n * SA_ + kb + 8 + 2 * t];
            }
#pragma unroll
            for (int mt = 0; mt < 2; mt++)
#pragma unroll
                for (int nt = 0; nt < 4; nt++) {
                    mma16816(acc[mt][nt], ah[mt], bh[nt]);
                    mma16816(acc[mt][nt], ah[mt], bl[nt]);
                    mma16816(acc[mt][nt], al[mt], bh[nt]);
                }
        }
    }
#pragma unroll
    for (int mt = 0; mt < 2; mt++) {
        int r0 = m0 + wm + mt * 16 + g;
        int r1 = r0 + 8;
        int node0 = (r0 >> 4) * N_PARTP + N_NUCP + (r0 & 15);
        int node1 = (r1 >> 4) * N_PARTP + N_NUCP + (r1 & 15);
#pragma unroll
        for (int nt = 0; nt < 4; nt++) {
            int cn = n0 + wn + nt * 8 + 2 * t;
            float bs0 = sBias[cn - n0], bs1 = sBias[cn - n0 + 1];
            float2 o0 = make_float2(acc[mt][nt][0] + bs0, acc[mt][nt][1] + bs1);
            float2 o1 = make_float2(acc[mt][nt][2] + bs0, acc[mt][nt][3] + bs1);
            *(float2*)(g_hx + (size_t)node0 * K_ + cn) = o0;
            *(float2*)(g_hx + (size_t)node1 * K_ + cn) = o1;
        }
    }
}

// ============================================================
// K5: PERSISTENT edge MLP via bf16-split mma; weights loaded ONCE
// per block; grid-stride over 64-edge tiles of one type.
// ============================================================
#define SE_ 72           // padded smem row stride (bf16) for K=64
#define EDGE_BLOCKS 96   // blocks per type (x3 types)

struct EdgeParams {
    const float* W1[3]; const float* b1[3];
    const float* W2[3]; const float* b2[3];
};

__global__ void __launch_bounds__(256)
k_edge(EdgeParams P,
       const float* __restrict__ dist,
       const int* __restrict__ senders,
       const int* __restrict__ receivers) {
    extern __shared__ __align__(16) char smc[];
    __nv_bfloat16* sXh  = (__nv_bfloat16*)(smc);           // 64*72 (overlaid by Hh)
    __nv_bfloat16* sXl  = (__nv_bfloat16*)(smc + 9216);    // 64*72 (overlaid by Hl)
    __nv_bfloat16* sW1h = (__nv_bfloat16*)(smc + 18432);   // 64*72 [n][k]
    __nv_bfloat16* sW1l = (__nv_bfloat16*)(smc + 27648);
    __nv_bfloat16* sW2h = (__nv_bfloat16*)(smc + 36864);   // 128*72 [n][k]
    __nv_bfloat16* sW2l = (__nv_bfloat16*)(smc + 55296);
    float* sb1 = (float*)(smc + 73728);   // 64
    float* sb2 = (float*)(smc + 73984);   // 128
    int* sSend = (int*)(smc + 74496);     // 64
    int* sZrow = (int*)(smc + 74752);     // 64
    int* sEid  = (int*)(smc + 75008);     // 64  -> total 75264 B
    __nv_bfloat16* sHh = sXh;
    __nv_bfloat16* sHl = sXl;

    int ty_ = blockIdx.y;
    int cnt = g_cnt[ty_];
    int tid = threadIdx.x, lane = tid & 31, w = tid >> 5;
    int g = lane >> 2, t = lane & 3;

    // ---- weights ONCE per block (k-fastest: conflict-free smem stores) ----
    {
        const float* W1 = P.W1[ty_]; const float* W2 = P.W2[ty_];
#pragma unroll
        for (int r = 0; r < 16; r++) {
            int idx = tid + r * 256;       // 4096 = 64n x 64k
            int n = idx >> 6, k = idx & 63;
            __nv_bfloat16 h, l; splitbf(W1[k * D_ + n], h, l);
            sW1h[n * SE_ + k] = h; sW1l[n * SE_ + k] = l;
        }
#pragma unroll
        for (int r = 0; r < 32; r++) {
            int idx = tid + r * 256;       // 8192 = 128n x 64k
            int n = idx >> 6, k = idx & 63;
            __nv_bfloat16 h, l; splitbf(W2[k * K_ + n], h, l);
            sW2h[n * SE_ + k] = h; sW2l[n * SE_ + k] = l;
        }
        if (tid < 64)  sb1[tid] = P.b1[ty_][tid];
        if (tid < 128) sb2[tid] = P.b2[ty_][tid];
    }

    int wm1 = (w & 1) * 32, wn1 = (w >> 1) * 16;   // stage-1 layout
    int wm2 = (w & 1) * 32, wn2 = (w >> 1) * 32;   // stage-2 layout
    float* zbase = g_z + (size_t)ty_ * N_EROWS * K_;

    for (int e0 = blockIdx.x * 64; e0 < cnt; e0 += EDGE_BLOCKS * 64) {
        int ne = min(64, cnt - e0);
        __syncthreads();   // weights ready (1st iter) / prior-iter readers done

        // ---- metadata ----
        if (tid < 64) {
            int sv = 0, zr = 0, eid = 0;
            if (tid < ne) {
                eid = g_list[ty_ * E_ + e0 + tid];
                sv  = senders[eid];
                int r = receivers[eid];
                zr  = (r / N_PARTP) * N_ELECP + (r % N_PARTP) - N_NUCP;
            }
            sSend[tid] = sv; sZrow[tid] = zr; sEid[tid] = eid;
        }
        __syncthreads();

        // ---- X tile: 64 rows x 64 fp32 -> split into sXh/sXl ----
#pragma unroll
        for (int r = 0; r < 4; r++) {
            int idx = tid + r * 256;           // 1024 float4 total
            int row = idx >> 4, c4 = idx & 15;
            float4 v = make_float4(0.f, 0.f, 0.f, 0.f);
            if (row < ne)
                v = ((const float4*)(dist + (size_t)sEid[row] * D_))[c4];
            int c = c4 * 4;
            __nv_bfloat16 h0, l0, h1, l1, h2, l2, h3, l3;
            splitbf(v.x, h0, l0); splitbf(v.y, h1, l1);
            splitbf(v.z, h2, l2); splitbf(v.w, h3, l3);
            *(__nv_bfloat162*)&sXh[row * SE_ + c]     = __halves2bfloat162(h0, h1);
            *(__nv_bfloat162*)&sXh[row * SE_ + c + 2] = __halves2bfloat162(h2, h3);
            *(__nv_bfloat162*)&sXl[row * SE_ + c]     = __halves2bfloat162(l0, l1);
            *(__nv_bfloat162*)&sXl[row * SE_ + c + 2] = __halves2bfloat162(l2, l3);
        }
        __syncthreads();

        // ---- stage 1: H = ssp(X @ W1 + b1)  (64x64), warps 2(m) x 4(n=16) ----
        float acc1[2][2][4];
#pragma unroll
        for (int a = 0; a < 2; a++)
#pragma unroll
            for (int b = 0; b < 2; b++)
#pragma unroll
                for (int c = 0; c < 4; c++) acc1[a][b][c] = 0.f;
#pragma unroll
        for (int s = 0; s < 4; s++) {
            int kb = s * 16;
            uint32_t ah[2][4], al[2][4], bh[2][2], bl[2][2];
#pragma unroll
            for (int mt = 0; mt < 2; mt++) {
                int r0 = wm1 + mt * 16 + g;
                ah[mt][0] = *(uint32_t*)&sXh[r0 * SE_ + kb + 2 * t];
                ah[mt][1] = *(uint32_t*)&sXh[(r0 + 8) * SE_ + kb + 2 * t];
                ah[mt][2] = *(uint32_t*)&sXh[r0 * SE_ + kb + 8 + 2 * t];
                ah[mt][3] = *(uint32_t*)&sXh[(r0 + 8) * SE_ + kb + 8 + 2 * t];
                al[mt][0] = *(uint32_t*)&sXl[r0 * SE_ + kb + 2 * t];
                al[mt][1] = *(uint32_t*)&sXl[(r0 + 8) * SE_ + kb + 2 * t];
                al[mt][2] = *(uint32_t*)&sXl[r0 * SE_ + kb + 8 + 2 * t];
                al[mt][3] = *(uint32_t*)&sXl[(r0 + 8) * SE_ + kb + 8 + 2 * t];
            }
#pragma unroll
            for (int nt = 0; nt < 2; nt++) {
                int n = wn1 + nt * 8 + g;
                bh[nt][0] = *(uint32_t*)&sW1h[n * SE_ + kb + 2 * t];
                bh[nt][1] = *(uint32_t*)&sW1h[n * SE_ + kb + 8 + 2 * t];
                bl[nt][0] = *(uint32_t*)&sW1l[n * SE_ + kb + 2 * t];
                bl[nt][1] = *(uint32_t*)&sW1l[n * SE_ + kb + 8 + 2 * t];
            }
#pragma unroll
            for (int mt = 0; mt < 2; mt++)
#pragma unroll
                for (int nt = 0; nt < 2; nt++) {
                    mma16816(acc1[mt][nt], ah[mt], bh[nt]);
                    mma16816(acc1[mt][nt], ah[mt], bl[nt]);
                    mma16816(acc1[mt][nt], al[mt], bh[nt]);
                }
        }
        __syncthreads();   // all reads of sX done; safe to overlay H

        // ssp + split + write H (overlay over sX)
#pragma unroll
        for (int mt = 0; mt < 2; mt++) {
#pragma unroll
            for (int nt = 0; nt < 2; nt++) {
                int col = wn1 + nt * 8 + 2 * t;
                float b0 = sb1[col], b1v = sb1[col + 1];
                int r0 = wm1 + mt * 16 + g;
#pragma unroll
                for (int hr = 0; hr < 2; hr++) {
                    int row = r0 + hr * 8;
                    float x0 = acc1[mt][nt][hr * 2 + 0] + b0;
                    float x1 = acc1[mt][nt][hr * 2 + 1] + b1v;
                    float v0 = fmaxf(x0, 0.f) + log1pf(expf(-fabsf(x0))) - LOG2F_;
                    float v1 = fmaxf(x1, 0.f) + log1pf(expf(-fabsf(x1))) - LOG2F_;
                    __nv_bfloat16 h0, l0, h1, l1;
                    splitbf(v0, h0, l0); splitbf(v1, h1, l1);
                    *(__nv_bfloat162*)&sHh[row * SE_ + col] = __halves2bfloat162(h0, h1);
                    *(__nv_bfloat162*)&sHl[row * SE_ + col] = __halves2bfloat162(l0, l1);
                }
            }
        }
        __syncthreads();

        // ---- stage 2: WE = H @ W2 + b2  (64x128), warps 2(m) x 4(n=32) ----
        float acc2[2][4][4];
#pragma unroll
        for (int a = 0; a < 2; a++)
#pragma unroll
            for (int b = 0; b < 4; b++)
#pragma unroll
                for (int c = 0; c < 4; c++) acc2[a][b][c] = 0.f;
#pragma unroll
        for (int s = 0; s < 4; s++) {
            int kb = s * 16;
            uint32_t ah[2][4], al[2][4], bh[4][2], bl[4][2];
#pragma unroll
            for (int mt = 0; mt < 2; mt++) {
                int r0 = wm2 + mt * 16 + g;
                ah[mt][0] = *(uint32_t*)&sHh[r0 * SE_ + kb + 2 * t];
                ah[mt][1] = *(uint32_t*)&sHh[(r0 + 8) * SE_ + kb + 2 * t];
                ah[mt][2] = *(uint32_t*)&sHh[r0 * SE_ + kb + 8 + 2 * t];
                ah[mt][3] = *(uint32_t*)&sHh[(r0 + 8) * SE_ + kb + 8 + 2 * t];
                al[mt][0] = *(uint32_t*)&sHl[r0 * SE_ + kb + 2 * t];
                al[mt][1] = *(uint32_t*)&sHl[(r0 + 8) * SE_ + kb + 2 * t];
                al[mt][2] = *(uint32_t*)&sHl[r0 * SE_ + kb + 8 + 2 * t];
                al[mt][3] = *(uint32_t*)&sHl[(r0 + 8) * SE_ + kb + 8 + 2 * t];
            }
#pragma unroll
            for (int nt = 0; nt < 4; nt++) {
                int n = wn2 + nt * 8 + g;
                bh[nt][0] = *(uint32_t*)&sW2h[n * SE_ + kb + 2 * t];
                bh[nt][1] = *(uint32_t*)&sW2h[n * SE_ + kb + 8 + 2 * t];
                bl[nt][0] = *(uint32_t*)&sW2l[n * SE_ + kb + 2 * t];
                bl[nt][1] = *(uint32_t*)&sW2l[n * SE_ + kb + 8 + 2 * t];
            }
#pragma unroll
            for (int mt = 0; mt < 2; mt++)
#pragma unroll
                for (int nt = 0; nt < 4; nt++) {
                    mma16816(acc2[mt][nt], ah[mt], bh[nt]);
                    mma16816(acc2[mt][nt], ah[mt], bl[nt]);
                    mma16816(acc2[mt][nt], al[mt], bh[nt]);
                }
        }

        // ---- epilogue: weh = (WE + b2) * hx[sender]; vector RED scatter ----
#pragma unroll
        for (int mt = 0; mt < 2; mt++) {
#pragma unroll
            for (int hr = 0; hr < 2; hr++) {
                int e = wm2 + mt * 16 + g + hr * 8;
                if (e < ne) {
                    int sv = sSend[e], zr = sZrow[e];
                    const float* hx = g_hx + (size_t)sv * K_;
                    float* zp = zbase + (size_t)zr * K_;
#pragma unroll
                    for (int nt = 0; nt < 4; nt++) {
                        int col = wn2 + nt * 8 + 2 * t;
                        float2 h2 = *(const float2*)(hx + col);
                        float v0 = (acc2[mt][nt][hr * 2 + 0] + sb2[col])     * h2.x;
                        float v1 = (acc2[mt][nt][hr * 2 + 1] + sb2[col + 1]) * h2.y;
                        red2(zp + col, v0, v1);
                    }
                }
            }
        }
    }
}

// ============================================================
// K6: out = elec + [z0|z1|z2] @ [g..] + Σb  via bf16-split mma  [verified R4]
// ============================================================
__global__ void __launch_bounds__(256)
k_out_mma(const float* __restrict__ elec,
          const float* __restrict__ gW0, const float* __restrict__ gW1,
          const float* __restrict__ gW2,
          const float* __restrict__ gb0, const float* __restrict__ gb1,
          const float* __restrict__ gb2,
          float* __restrict__ out) {
    __shared__ __align__(16) __nv_bfloat16 sAh[128 * SA_], sAl[128 * SA_];
    __shared__ __align__(16) __nv_bfloat16 sBh[64 * SA_],  sBl[64 * SA_];
    __shared__ float sBias[64];
    int tid = threadIdx.x, lane = tid & 31, w = tid >> 5;
    int wm = (w & 3) * 32, wn = (w >> 2) * 32;
    int g = lane >> 2, t = lane & 3;
    int m0 = blockIdx.x * 128, n0 = blockIdx.y * 64;
    if (tid < 64)
        sBias[tid] = gb0[n0 + tid] + gb1[n0 + tid] + gb2[n0 + tid];

    float acc[2][4][4];
#pragma unroll
    for (int a = 0; a < 2; a++)
#pragma unroll
        for (int b = 0; b < 4; b++)
#pragma unroll
            for (int c = 0; c < 4; c++) acc[a][b][c] = 0.f;

    float4 pA[4]; float pB[8];
    {
        const float* Az = g_z + (size_t)m0 * K_;
#pragma unroll
        for (int r = 0; r < 4; r++) {
            int idx = tid + r * 256, row = idx >> 3, c4 = idx & 7;
            pA[r] = *(const float4*)(Az + (size_t)row * K_ + c4 * 4);
        }
#pragma unroll
        for (int r = 0; r < 8; r++) {
            int idx = tid + r * 256, n = idx & 63, k = idx >> 6;
            pB[r] = gW0[(size_t)k * EMB_ + n0 + n];
        }
    }

    for (int it = 0; it < 12; it++) {
        __syncthreads();
#pragma unroll
        for (int r = 0; r < 4; r++) {
            int idx = tid + r * 256, row = idx >> 3, c = (idx & 7) * 4;
            float4 v = pA[r];
            __nv_bfloat16 h0, l0, h1, l1, h2, l2, h3, l3;
            splitbf(v.x, h0, l0); splitbf(v.y, h1, l1);
            splitbf(v.z, h2, l2); splitbf(v.w, h3, l3);
            *(__nv_bfloat162*)&sAh[row * SA_ + c]     = __halves2bfloat162(h0, h1);
            *(__nv_bfloat162*)&sAh[row * SA_ + c + 2] = __halves2bfloat162(h2, h3);
            *(__nv_bfloat162*)&sAl[row * SA_ + c]     = __halves2bfloat162(l0, l1);
            *(__nv_bfloat162*)&sAl[row * SA_ + c + 2] = __halves2bfloat162(l2, l3);
        }
#pragma unroll
        for (int r = 0; r < 8; r++) {
            int idx = tid + r * 256, n = idx & 63, k = idx >> 6;
            __nv_bfloat16 h, l; splitbf(pB[r], h, l);
            sBh[n * SA_ + k] = h; sBl[n * SA_ + k] = l;
        }
        __syncthreads();
        if (it < 11) {
            int k0 = (it + 1) * 32;
            int tsel = k0 >> 7, kc = k0 & 127;
            const float* Az = g_z + (size_t)tsel * N_EROWS * K_ +
                              (size_t)m0 * K_ + kc;
            const float* Bw = (tsel == 0) ? gW0 : ((tsel == 1) ? gW1 : gW2);
#pragma unroll
            for (int r = 0; r < 4; r++) {
                int idx = tid + r * 256, row = idx >> 3, c4 = idx & 7;
                pA[r] = *(const float4*)(Az + (size_t)row * K_ + c4 * 4);
            }
#pragma unroll
            for (int r = 0; r < 8; r++) {
                int idx = tid + r * 256, n = idx & 63, k = idx >> 6;
                pB[r] = Bw[(size_t)(kc + k) * EMB_ + n0 + n];
            }
        }
#pragma unroll
        for (int s = 0; s < 2; s++) {
            int kb = s * 16;
            uint32_t ah[2][4], al[2][4], bh[4][2], bl[4][2];
#pragma unroll
            for (int mt = 0; mt < 2; mt++) {
                int r0 = wm + mt * 16 + g;
                ah[mt][0] = *(uint32_t*)&sAh[r0 * SA_ + kb + 2 * t];
                ah[mt][1] = *(uint32_t*)&sAh[(r0 + 8) * SA_ + kb + 2 * t];
                ah[mt][2] = *(uint32_t*)&sAh[r0 * SA_ + kb + 8 + 2 * t];
                ah[mt][3] = *(uint32_t*)&sAh[(r0 + 8) * SA_ + kb + 8 + 2 * t];
                al[mt][0] = *(uint32_t*)&sAl[r0 * SA_ + kb + 2 * t];
                al[mt][1] = *(uint32_t*)&sAl[(r0 + 8) * SA_ + kb + 2 * t];
                al[mt][2] = *(uint32_t*)&sAl[r0 * SA_ + kb + 8 + 2 * t];
                al[mt][3] = *(uint32_t*)&sAl[(r0 + 8) * SA_ + kb + 8 + 2 * t];
            }
#pragma unroll
            for (int nt = 0; nt < 4; nt++) {
                int n = wn + nt * 8 + g;
                bh[nt][0] = *(uint32_t*)&sBh[n * SA_ + kb + 2 * t];
                bh[nt][1] = *(uint32_t*)&sBh[n * SA_ + kb + 8 + 2 * t];
                bl[nt][0] = *(uint32_t*)&sBl[n * SA_ + kb + 2 * t];
                bl[nt][1] = *(uint32_t*)&sBl[n * SA_ + kb + 8 + 2 * t];
            }
#pragma unroll
            for (int mt = 0; mt < 2; mt++)
#pragma unroll
                for (int nt = 0; nt < 4; nt++) {
                    mma16816(acc[mt][nt], ah[mt], bh[nt]);
                    mma16816(acc[mt][nt], ah[mt], bl[nt]);
                    mma16816(acc[mt][nt], al[mt], bh[nt]);
                }
        }
    }
#pragma unroll
    for (int mt = 0; mt < 2; mt++) {
        int r0 = m0 + wm + mt * 16 + g;
        int r1 = r0 + 8;
#pragma unroll
        for (int nt = 0; nt < 4; nt++) {
            int cn = n0 + wn + nt * 8 + 2 * t;
            float2 e0 = *(const float2*)(elec + (size_t)r0 * EMB_ + cn);
            float2 e1 = *(const float2*)(elec + (size_t)r1 * EMB_ + cn);
            float bs0 = sBias[cn - n0], bs1 = sBias[cn - n0 + 1];
            float2 o0 = make_float2(acc[mt][nt][0] + e0.x + bs0,
                                    acc[mt][nt][1] + e0.y + bs1);
            float2 o1 = make_float2(acc[mt][nt][2] + e1.x + bs0,
                                    acc[mt][nt][3] + e1.y + bs1);
            *(float2*)(out + (size_t)r0 * EMB_ + cn) = o0;
            *(float2*)(out + (size_t)r1 * EMB_ + cn) = o1;
        }
    }
}

// ============================================================
// launch
// ============================================================
extern "C" void kernel_launch(void* const* d_in, const int* in_sizes, int n_in,
                              void* d_out, int out_size) {
    const float* nuc       = (const float*)d_in[0];
    const float* elec      = (const float*)d_in[1];
    const float* dist      = (const float*)d_in[2];
    const int*   e_type    = (const int*)d_in[3];
    const int*   senders   = (const int*)d_in[4];
    const int*   receivers = (const int*)d_in[5];
    EdgeParams P;
    P.W1[0] = (const float*)d_in[6];  P.b1[0] = (const float*)d_in[7];
    P.W2[0] = (const float*)d_in[8];  P.b2[0] = (const float*)d_in[9];
    P.W1[1] = (const float*)d_in[10]; P.b1[1] = (const float*)d_in[11];
    P.W2[1] = (const float*)d_in[12]; P.b2[1] = (const float*)d_in[13];
    P.W1[2] = (const float*)d_in[14]; P.b1[2] = (const float*)d_in[15];
    P.W2[2] = (const float*)d_in[16]; P.b2[2] = (const float*)d_in[17];
    const float* hW  = (const float*)d_in[18];
    const float* hb  = (const float*)d_in[19];
    const float* gsW = (const float*)d_in[20];
    const float* gsb = (const float*)d_in[21];
    const float* gaW = (const float*)d_in[22];
    const float* gab = (const float*)d_in[23];
    const float* gnW = (const float*)d_in[24];
    const float* gnb = (const float*)d_in[25];
    float* out = (float*)d_out;

    const int EDGE_SMEM = 75264;
    cudaFuncSetAttribute(k_edge, cudaFuncAttributeMaxDynamicSharedMemorySize,
                         EDGE_SMEM);

    k_zero<<<(3 * N_EROWS * K_ / 4 + 255) / 256, 256>>>();
    k_bin<<<(E_ + 255) / 256, 256>>>(e_type, receivers);
    k_hx_nuc<<<(B_ * N_NUCP * K_ / 4 + 255) / 256, 256>>>(nuc);
    dim3 gh(N_EROWS / 128, K_ / 64);
    k_hx_mma<<<gh, 256>>>(elec, hW, hb);
    dim3 ge(EDGE_BLOCKS, 3);
    k_edge<<<ge, 256, EDGE_SMEM>>>(P, dist, senders, receivers);
    dim3 go(N_EROWS / 128, EMB_ / 64);
    k_out_mma<<<go, 256>>>(elec, gsW, gaW, gnW, gsb, gab, gnb, out);
}

// round 12
// speedup vs baseline: 2.3299x; 1.0359x over previous
#include <cuda_runtime.h>
#include <cuda_bf16.h>
#include <math.h>
#include <stdint.h>

#define B_      2048
#define N_NUCP  4
#define N_ELECP 16
#define N_PARTP 20
#define N_NODES (B_ * N_PARTP)   // 40960
#define N_EROWS (B_ * N_ELECP)   // 32768
#define E_      307200
#define D_      64
#define K_      128
#define EMB_    256
#define LOG2F_  0.69314718055994530942f

// ---- scratch (static __device__ arrays; no allocation allowed) ----
__device__ float g_hx[N_NODES * K_];          // ~21 MB
__device__ float g_z[3 * N_EROWS * K_];       // ~50 MB
__device__ int   g_list[3 * E_];
__device__ int   g_cnt[4];

// ============================================================
// helpers
// ============================================================
__device__ __forceinline__ void splitbf(float x, __nv_bfloat16& h, __nv_bfloat16& l) {
    h = __float2bfloat16(x);
    l = __float2bfloat16(x - __bfloat162float(h));
}

__device__ __forceinline__ void mma16816(float* c, const uint32_t* a, const uint32_t* b) {
    asm volatile(
        "mma.sync.aligned.m16n8k16.row.col.f32.bf16.bf16.f32 "
        "{%0,%1,%2,%3}, {%4,%5,%6,%7}, {%8,%9}, {%0,%1,%2,%3};"
        : "+f"(c[0]), "+f"(c[1]), "+f"(c[2]), "+f"(c[3])
        : "r"(a[0]), "r"(a[1]), "r"(a[2]), "r"(a[3]), "r"(b[0]), "r"(b[1]));
}

__device__ __forceinline__ void ldsm_x4(uint32_t* r, uint32_t addr) {
    asm volatile("ldmatrix.sync.aligned.m8n8.x4.shared.b16 {%0,%1,%2,%3}, [%4];"
        : "=r"(r[0]), "=r"(r[1]), "=r"(r[2]), "=r"(r[3]) : "r"(addr));
}

__device__ __forceinline__ void ldsm_x2(uint32_t* r, uint32_t addr) {
    asm volatile("ldmatrix.sync.aligned.m8n8.x2.shared.b16 {%0,%1}, [%2];"
        : "=r"(r[0]), "=r"(r[1]) : "r"(addr));
}

__device__ __forceinline__ void red2(float* p, float x, float y) {
    asm volatile("red.global.add.v2.f32 [%0], {%1,%2};"
                 :: "l"(p), "f"(x), "f"(y) : "memory");
}

// ============================================================
// K1: zero z channels + counters
// ============================================================
__global__ void k_zero() {
    int i = blockIdx.x * blockDim.x + threadIdx.x;
    const int n4 = 3 * N_EROWS * K_ / 4;
    if (i < n4) ((float4*)g_z)[i] = make_float4(0.f, 0.f, 0.f, 0.f);
    if (i < 4) g_cnt[i] = 0;
}

// ============================================================
// K2: bin edges by type, dropping edges whose receiver is a nucleus
// ============================================================
__global__ void k_bin(const int* __restrict__ e_type,
                      const int* __restrict__ receivers) {
    int e = blockIdx.x * blockDim.x + threadIdx.x;
    if (e >= E_) return;
    int r = receivers[e];
    if ((r % N_PARTP) < N_NUCP) return;
    int ty = e_type[e];
    int slot = (ty == 3) ? 0 : ((ty == 4) ? 1 : 2);
    int pos = atomicAdd(&g_cnt[slot], 1);
    g_list[slot * E_ + pos] = e;
}

// ============================================================
// K3: hx nucleus rows (plain copy)
// ============================================================
__global__ void k_hx_nuc(const float* __restrict__ nuc) {
    int i = blockIdx.x * blockDim.x + threadIdx.x;
    const int n4 = B_ * N_NUCP * K_ / 4;
    if (i >= n4) return;
    int k4  = i & (K_ / 4 - 1);
    int row = i >> 5;
    int b = row >> 2, p = row & 3;
    ((float4*)g_hx)[((size_t)(b * N_PARTP + p)) * (K_ / 4) + k4] =
        ((const float4*)nuc)[i];
}

// ============================================================
// K4: hx electron rows via bf16-split tensor mma + ldmatrix
// ============================================================
#define SA_ 40   // padded smem row stride (bf16) for BK=32 (ldmatrix conflict-free)

__global__ void __launch_bounds__(256)
k_hx_mma(const float* __restrict__ elec,
         const float* __restrict__ hW,
         const float* __restrict__ hb) {
    __shared__ __align__(16) __nv_bfloat16 sAh[128 * SA_], sAl[128 * SA_];
    __shared__ __align__(16) __nv_bfloat16 sBh[64 * SA_],  sBl[64 * SA_];
    __shared__ float sBias[64];
    int tid = threadIdx.x, lane = tid & 31, w = tid >> 5;
    int wm = (w & 3) * 32, wn = (w >> 2) * 32;
    int g = lane >> 2, t = lane & 3;
    int m0 = blockIdx.x * 128, n0 = blockIdx.y * 64;
    if (tid < 64) sBias[tid] = hb[n0 + tid];

    // ldmatrix per-lane source rows
    int aRow = (lane & 7) + ((lane >> 3) & 1) * 8;
    int aK   = ((lane >> 4) & 1) * 8;
    int bRow = lane & 7;
    int bK   = ((lane >> 3) & 1) * 8;
    uint32_t uAh = (uint32_t)__cvta_generic_to_shared(&sAh[(wm + aRow) * SA_ + aK]);
    uint32_t uAl = (uint32_t)__cvta_generic_to_shared(&sAl[(wm + aRow) * SA_ + aK]);
    uint32_t uBh = (uint32_t)__cvta_generic_to_shared(&sBh[(wn + bRow) * SA_ + bK]);
    uint32_t uBl = (uint32_t)__cvta_generic_to_shared(&sBl[(wn + bRow) * SA_ + bK]);

    float acc[2][4][4];
#pragma unroll
    for (int a = 0; a < 2; a++)
#pragma unroll
        for (int b = 0; b < 4; b++)
#pragma unroll
            for (int c = 0; c < 4; c++) acc[a][b][c] = 0.f;

    float4 pA[4]; float pB[8];
    {
        const float* Ab = elec + (size_t)m0 * EMB_;
#pragma unroll
        for (int r = 0; r < 4; r++) {
            int idx = tid + r * 256, row = idx >> 3, c4 = idx & 7;
            pA[r] = *(const float4*)(Ab + (size_t)row * EMB_ + c4 * 4);
        }
#pragma unroll
        for (int r = 0; r < 8; r++) {
            int idx = tid + r * 256, n = idx & 63, k = idx >> 6;
            pB[r] = hW[(size_t)k * K_ + n0 + n];
        }
    }

    for (int it = 0; it < 8; it++) {
        __syncthreads();
#pragma unroll
        for (int r = 0; r < 4; r++) {
            int idx = tid + r * 256, row = idx >> 3, c = (idx & 7) * 4;
            float4 v = pA[r];
            __nv_bfloat16 h0, l0, h1, l1, h2, l2, h3, l3;
            splitbf(v.x, h0, l0); splitbf(v.y, h1, l1);
            splitbf(v.z, h2, l2); splitbf(v.w, h3, l3);
            *(__nv_bfloat162*)&sAh[row * SA_ + c]     = __halves2bfloat162(h0, h1);
            *(__nv_bfloat162*)&sAh[row * SA_ + c + 2] = __halves2bfloat162(h2, h3);
            *(__nv_bfloat162*)&sAl[row * SA_ + c]     = __halves2bfloat162(l0, l1);
            *(__nv_bfloat162*)&sAl[row * SA_ + c + 2] = __halves2bfloat162(l2, l3);
        }
#pragma unroll
        for (int r = 0; r < 8; r++) {
            int idx = tid + r * 256, n = idx & 63, k = idx >> 6;
            __nv_bfloat16 h, l; splitbf(pB[r], h, l);
            sBh[n * SA_ + k] = h; sBl[n * SA_ + k] = l;
        }
        __syncthreads();
        if (it < 7) {
            int k0 = (it + 1) * 32;
            const float* Ab = elec + (size_t)m0 * EMB_ + k0;
#pragma unroll
            for (int r = 0; r < 4; r++) {
                int idx = tid + r * 256, row = idx >> 3, c4 = idx & 7;
                pA[r] = *(const float4*)(Ab + (size_t)row * EMB_ + c4 * 4);
            }
#pragma unroll
            for (int r = 0; r < 8; r++) {
                int idx = tid + r * 256, n = idx & 63, k = idx >> 6;
                pB[r] = hW[(size_t)(k0 + k) * K_ + n0 + n];
            }
        }
#pragma unroll
        for (int s = 0; s < 2; s++) {
            uint32_t ah[2][4], al[2][4], bh[4][2], bl[4][2];
#pragma unroll
            for (int mt = 0; mt < 2; mt++) {
                uint32_t off = (uint32_t)((mt * 16 * SA_ + s * 16) * 2);
                ldsm_x4(ah[mt], uAh + off);
                ldsm_x4(al[mt], uAl + off);
            }
#pragma unroll
            for (int nt = 0; nt < 4; nt++) {
                uint32_t off = (uint32_t)((nt * 8 * SA_ + s * 16) * 2);
                ldsm_x2(bh[nt], uBh + off);
                ldsm_x2(bl[nt], uBl + off);
            }
#pragma unroll
            for (int mt = 0; mt < 2; mt++)
#pragma unroll
                for (int nt = 0; nt < 4; nt++) {
                    mma16816(acc[mt][nt], ah[mt], bh[nt]);
                    mma16816(acc[mt][nt], ah[mt], bl[nt]);
                    mma16816(acc[mt][nt], al[mt], bh[nt]);
                }
        }
    }
#pragma unroll
    for (int mt = 0; mt < 2; mt++) {
        int r0 = m0 + wm + mt * 16 + g;
        int r1 = r0 + 8;
        int node0 = (r0 >> 4) * N_PARTP + N_NUCP + (r0 & 15);
        int node1 = (r1 >> 4) * N_PARTP + N_NUCP + (r1 & 15);
#pragma unroll
        for (int nt = 0; nt < 4; nt++) {
            int cn = n0 + wn + nt * 8 + 2 * t;
            float bs0 = sBias[cn - n0], bs1 = sBias[cn - n0 + 1];
            float2 o0 = make_float2(acc[mt][nt][0] + bs0, acc[mt][nt][1] + bs1);
            float2 o1 = make_float2(acc[mt][nt][2] + bs0, acc[mt][nt][3] + bs1);
            *(float2*)(g_hx + (size_t)node0 * K_ + cn) = o0;
            *(float2*)(g_hx + (size_t)node1 * K_ + cn) = o1;
        }
    }
}

// ============================================================
// K5: PERSISTENT edge MLP (bf16-split mma + ldmatrix) + RED scatter
// ============================================================
#define SE_ 72           // padded smem row stride (bf16) for K=64 (ldmatrix conflict-free)
#define EDGE_BLOCKS 96   // blocks per type (x3 types)

struct EdgeParams {
    const float* W1[3]; const float* b1[3];
    const float* W2[3]; const float* b2[3];
};

__global__ void __launch_bounds__(256)
k_edge(EdgeParams P,
       const float* __restrict__ dist,
       const int* __restrict__ senders,
       const int* __restrict__ receivers) {
    extern __shared__ __align__(16) char smc[];
    __nv_bfloat16* sXh  = (__nv_bfloat16*)(smc);           // 64*72 (overlaid by Hh)
    __nv_bfloat16* sXl  = (__nv_bfloat16*)(smc + 9216);    // 64*72 (overlaid by Hl)
    __nv_bfloat16* sW1h = (__nv_bfloat16*)(smc + 18432);   // 64*72 [n][k]
    __nv_bfloat16* sW1l = (__nv_bfloat16*)(smc + 27648);
    __nv_bfloat16* sW2h = (__nv_bfloat16*)(smc + 36864);   // 128*72 [n][k]
    __nv_bfloat16* sW2l = (__nv_bfloat16*)(smc + 55296);
    float* sb1 = (float*)(smc + 73728);   // 64
    float* sb2 = (float*)(smc + 73984);   // 128
    int* sSend = (int*)(smc + 74496);     // 64
    int* sZrow = (int*)(smc + 74752);     // 64
    int* sEid  = (int*)(smc + 75008);     // 64  -> total 75264 B
    __nv_bfloat16* sHh = sXh;
    __nv_bfloat16* sHl = sXl;

    int ty_ = blockIdx.y;
    int cnt = g_cnt[ty_];
    int tid = threadIdx.x, lane = tid & 31, w = tid >> 5;
    int g = lane >> 2, t = lane & 3;

    // ---- weights ONCE per block ----
    {
        const float* W1 = P.W1[ty_]; const float* W2 = P.W2[ty_];
#pragma unroll
        for (int r = 0; r < 16; r++) {
            int idx = tid + r * 256;       // 4096 = 64n x 64k
            int n = idx >> 6, k = idx & 63;
            __nv_bfloat16 h, l; splitbf(W1[k * D_ + n], h, l);
            sW1h[n * SE_ + k] = h; sW1l[n * SE_ + k] = l;
        }
#pragma unroll
        for (int r = 0; r < 32; r++) {
            int idx = tid + r * 256;       // 8192 = 128n x 64k
            int n = idx >> 6, k = idx & 63;
            __nv_bfloat16 h, l; splitbf(W2[k * K_ + n], h, l);
            sW2h[n * SE_ + k] = h; sW2l[n * SE_ + k] = l;
        }
        if (tid < 64)  sb1[tid] = P.b1[ty_][tid];
        if (tid < 128) sb2[tid] = P.b2[ty_][tid];
    }

    int wm1 = (w & 1) * 32, wn1 = (w >> 1) * 16;   // stage-1 layout
    int wm2 = (w & 1) * 32, wn2 = (w >> 1) * 32;   // stage-2 layout
    float* zbase = g_z + (size_t)ty_ * N_EROWS * K_;

    // ldmatrix per-lane source rows
    int aRow = (lane & 7) + ((lane >> 3) & 1) * 8;
    int aK   = ((lane >> 4) & 1) * 8;
    int bRow = lane & 7;
    int bK   = ((lane >> 3) & 1) * 8;
    uint32_t uXh = (uint32_t)__cvta_generic_to_shared(&sXh[(wm1 + aRow) * SE_ + aK]);
    uint32_t uXl = (uint32_t)__cvta_generic_to_shared(&sXl[(wm1 + aRow) * SE_ + aK]);
    uint32_t uW1h = (uint32_t)__cvta_generic_to_shared(&sW1h[(wn1 + bRow) * SE_ + bK]);
    uint32_t uW1l = (uint32_t)__cvta_generic_to_shared(&sW1l[(wn1 + bRow) * SE_ + bK]);
    uint32_t uW2h = (uint32_t)__cvta_generic_to_shared(&sW2h[(wn2 + bRow) * SE_ + bK]);
    uint32_t uW2l = (uint32_t)__cvta_generic_to_shared(&sW2l[(wn2 + bRow) * SE_ + bK]);

    for (int e0 = blockIdx.x * 64; e0 < cnt; e0 += EDGE_BLOCKS * 64) {
        int ne = min(64, cnt - e0);
        __syncthreads();   // weights ready (1st iter) / prior-iter readers done

        // ---- metadata ----
        if (tid < 64) {
            int sv = 0, zr = 0, eid = 0;
            if (tid < ne) {
                eid = g_list[ty_ * E_ + e0 + tid];
                sv  = senders[eid];
                int r = receivers[eid];
                zr  = (r / N_PARTP) * N_ELECP + (r % N_PARTP) - N_NUCP;
            }
            sSend[tid] = sv; sZrow[tid] = zr; sEid[tid] = eid;
        }
        __syncthreads();

        // ---- X tile: 64 rows x 64 fp32 -> split into sXh/sXl ----
#pragma unroll
        for (int r = 0; r < 4; r++) {
            int idx = tid + r * 256;           // 1024 float4 total
            int row = idx >> 4, c4 = idx & 15;
            float4 v = make_float4(0.f, 0.f, 0.f, 0.f);
            if (row < ne)
                v = ((const float4*)(dist + (size_t)sEid[row] * D_))[c4];
            int c = c4 * 4;
            __nv_bfloat16 h0, l0, h1, l1, h2, l2, h3, l3;
            splitbf(v.x, h0, l0); splitbf(v.y, h1, l1);
            splitbf(v.z, h2, l2); splitbf(v.w, h3, l3);
            *(__nv_bfloat162*)&sXh[row * SE_ + c]     = __halves2bfloat162(h0, h1);
            *(__nv_bfloat162*)&sXh[row * SE_ + c + 2] = __halves2bfloat162(h2, h3);
            *(__nv_bfloat162*)&sXl[row * SE_ + c]     = __halves2bfloat162(l0, l1);
            *(__nv_bfloat162*)&sXl[row * SE_ + c + 2] = __halves2bfloat162(l2, l3);
        }
        __syncthreads();

        // ---- stage 1: H = ssp(X @ W1 + b1)  (64x64), warps 2(m) x 4(n=16) ----
        float acc1[2][2][4];
#pragma unroll
        for (int a = 0; a < 2; a++)
#pragma unroll
            for (int b = 0; b < 2; b++)
#pragma unroll
                for (int c = 0; c < 4; c++) acc1[a][b][c] = 0.f;
#pragma unroll
        for (int s = 0; s < 4; s++) {
            uint32_t ah[2][4], al[2][4], bh[2][2], bl[2][2];
#pragma unroll
            for (int mt = 0; mt < 2; mt++) {
                uint32_t off = (uint32_t)((mt * 16 * SE_ + s * 16) * 2);
                ldsm_x4(ah[mt], uXh + off);
                ldsm_x4(al[mt], uXl + off);
            }
#pragma unroll
            for (int nt = 0; nt < 2; nt++) {
                uint32_t off = (uint32_t)((nt * 8 * SE_ + s * 16) * 2);
                ldsm_x2(bh[nt], uW1h + off);
                ldsm_x2(bl[nt], uW1l + off);
            }
#pragma unroll
            for (int mt = 0; mt < 2; mt++)
#pragma unroll
                for (int nt = 0; nt < 2; nt++) {
                    mma16816(acc1[mt][nt], ah[mt], bh[nt]);
                    mma16816(acc1[mt][nt], ah[mt], bl[nt]);
                    mma16816(acc1[mt][nt], al[mt], bh[nt]);
                }
        }
        __syncthreads();   // all reads of sX done; safe to overlay H

        // ssp + split + write H (overlay over sX)
#pragma unroll
        for (int mt = 0; mt < 2; mt++) {
#pragma unroll
            for (int nt = 0; nt < 2; nt++) {
                int col = wn1 + nt * 8 + 2 * t;
                float b0 = sb1[col], b1v = sb1[col + 1];
                int r0 = wm1 + mt * 16 + g;
#pragma unroll
                for (int hr = 0; hr < 2; hr++) {
                    int row = r0 + hr * 8;
                    float x0 = acc1[mt][nt][hr * 2 + 0] + b0;
                    float x1 = acc1[mt][nt][hr * 2 + 1] + b1v;
                    float v0 = fmaxf(x0, 0.f) + log1pf(expf(-fabsf(x0))) - LOG2F_;
                    float v1 = fmaxf(x1, 0.f) + log1pf(expf(-fabsf(x1))) - LOG2F_;
                    __nv_bfloat16 h0, l0, h1, l1;
                    splitbf(v0, h0, l0); splitbf(v1, h1, l1);
                    *(__nv_bfloat162*)&sHh[row * SE_ + col] = __halves2bfloat162(h0, h1);
                    *(__nv_bfloat162*)&sHl[row * SE_ + col] = __halves2bfloat162(l0, l1);
                }
            }
        }
        __syncthreads();

        // ---- stage 2: WE = H @ W2 + b2  (64x128), warps 2(m) x 4(n=32) ----
        float acc2[2][4][4];
#pragma unroll
        for (int a = 0; a < 2; a++)
#pragma unroll
            for (int b = 0; b < 4; b++)
#pragma unroll
                for (int c = 0; c < 4; c++) acc2[a][b][c] = 0.f;
#pragma unroll
        for (int s = 0; s < 4; s++) {
            uint32_t ah[2][4], al[2][4], bh[4][2], bl[4][2];
#pragma unroll
            for (int mt = 0; mt < 2; mt++) {
                uint32_t off = (uint32_t)((mt * 16 * SE_ + s * 16) * 2);
                ldsm_x4(ah[mt], uXh + off);   // sHh == sXh region
                ldsm_x4(al[mt], uXl + off);
            }
#pragma unroll
            for (int nt = 0; nt < 4; nt++) {
                uint32_t off = (uint32_t)((nt * 8 * SE_ + s * 16) * 2);
                ldsm_x2(bh[nt], uW2h + off);
                ldsm_x2(bl[nt], uW2l + off);
            }
#pragma unroll
            for (int mt = 0; mt < 2; mt++)
#pragma unroll
                for (int nt = 0; nt < 4; nt++) {
                    mma16816(acc2[mt][nt], ah[mt], bh[nt]);
                    mma16816(acc2[mt][nt], ah[mt], bl[nt]);
                    mma16816(acc2[mt][nt], al[mt], bh[nt]);
                }
        }

        // ---- epilogue: weh = (WE + b2) * hx[sender]; vector RED scatter ----
#pragma unroll
        for (int mt = 0; mt < 2; mt++) {
#pragma unroll
            for (int hr = 0; hr < 2; hr++) {
                int e = wm2 + mt * 16 + g + hr * 8;
                if (e < ne) {
                    int sv = sSend[e], zr = sZrow[e];
                    const float* hx = g_hx + (size_t)sv * K_;
                    float* zp = zbase + (size_t)zr * K_;
#pragma unroll
                    for (int nt = 0; nt < 4; nt++) {
                        int col = wn2 + nt * 8 + 2 * t;
                        float2 h2 = *(const float2*)(hx + col);
                        float v0 = (acc2[mt][nt][hr * 2 + 0] + sb2[col])     * h2.x;
                        float v1 = (acc2[mt][nt][hr * 2 + 1] + sb2[col + 1]) * h2.y;
                        red2(zp + col, v0, v1);
                    }
                }
            }
        }
    }
}

// ============================================================
// K6: out = elec + [z0|z1|z2] @ [g..] + Σb  (bf16-split mma + ldmatrix)
// ============================================================
__global__ void __launch_bounds__(256)
k_out_mma(const float* __restrict__ elec,
          const float* __restrict__ gW0, const float* __restrict__ gW1,
          const float* __restrict__ gW2,
          const float* __restrict__ gb0, const float* __restrict__ gb1,
          const float* __restrict__ gb2,
          float* __restrict__ out) {
    __shared__ __align__(16) __nv_bfloat16 sAh[128 * SA_], sAl[128 * SA_];
    __shared__ __align__(16) __nv_bfloat16 sBh[64 * SA_],  sBl[64 * SA_];
    __shared__ float sBias[64];
    int tid = threadIdx.x, lane = tid & 31, w = tid >> 5;
    int wm = (w & 3) * 32, wn = (w >> 2) * 32;
    int g = lane >> 2, t = lane & 3;
    int m0 = blockIdx.x * 128, n0 = blockIdx.y * 64;
    if (tid < 64)
        sBias[tid] = gb0[n0 + tid] + gb1[n0 + tid] + gb2[n0 + tid];

    int aRow = (lane & 7) + ((lane >> 3) & 1) * 8;
    int aK   = ((lane >> 4) & 1) * 8;
    int bRow = lane & 7;
    int bK   = ((lane >> 3) & 1) * 8;
    uint32_t uAh = (uint32_t)__cvta_generic_to_shared(&sAh[(wm + aRow) * SA_ + aK]);
    uint32_t uAl = (uint32_t)__cvta_generic_to_shared(&sAl[(wm + aRow) * SA_ + aK]);
    uint32_t uBh = (uint32_t)__cvta_generic_to_shared(&sBh[(wn + bRow) * SA_ + bK]);
    uint32_t uBl = (uint32_t)__cvta_generic_to_shared(&sBl[(wn + bRow) * SA_ + bK]);

    float acc[2][4][4];
#pragma unroll
    for (int a = 0; a < 2; a++)
#pragma unroll
        for (int b = 0; b < 4; b++)
#pragma unroll
            for (int c = 0; c < 4; c++) acc[a][b][c] = 0.f;

    float4 pA[4]; float pB[8];
    {
        const float* Az = g_z + (size_t)m0 * K_;
#pragma unroll
        for (int r = 0; r < 4; r++) {
            int idx = tid + r * 256, row = idx >> 3, c4 = idx & 7;
            pA[r] = *(const float4*)(Az + (size_t)row * K_ + c4 * 4);
        }
#pragma unroll
        for (int r = 0; r < 8; r++) {
            int idx = tid + r * 256, n = idx & 63, k = idx >> 6;
            pB[r] = gW0[(size_t)k * EMB_ + n0 + n];
        }
    }

    for (int it = 0; it < 12; it++) {
        __syncthreads();
#pragma unroll
        for (int r = 0; r < 4; r++) {
            int idx = tid + r * 256, row = idx >> 3, c = (idx & 7) * 4;
            float4 v = pA[r];
            __nv_bfloat16 h0, l0, h1, l1, h2, l2, h3, l3;
            splitbf(v.x, h0, l0); splitbf(v.y, h1, l1);
            splitbf(v.z, h2, l2); splitbf(v.w, h3, l3);
            *(__nv_bfloat162*)&sAh[row * SA_ + c]     = __halves2bfloat162(h0, h1);
            *(__nv_bfloat162*)&sAh[row * SA_ + c + 2] = __halves2bfloat162(h2, h3);
            *(__nv_bfloat162*)&sAl[row * SA_ + c]     = __halves2bfloat162(l0, l1);
            *(__nv_bfloat162*)&sAl[row * SA_ + c + 2] = __halves2bfloat162(l2, l3);
        }
#pragma unroll
        for (int r = 0; r < 8; r++) {
            int idx = tid + r * 256, n = idx & 63, k = idx >> 6;
            __nv_bfloat16 h, l; splitbf(pB[r], h, l);
            sBh[n * SA_ + k] = h; sBl[n * SA_ + k] = l;
        }
        __syncthreads();
        if (it < 11) {
            int k0 = (it + 1) * 32;
            int tsel = k0 >> 7, kc = k0 & 127;
            const float* Az = g_z + (size_t)tsel * N_EROWS * K_ +
                              (size_t)m0 * K_ + kc;
            const float* Bw = (tsel == 0) ? gW0 : ((tsel == 1) ? gW1 : gW2);
#pragma unroll
            for (int r = 0; r < 4; r++) {
                int idx = tid + r * 256, row = idx >> 3, c4 = idx & 7;
                pA[r] = *(const float4*)(Az + (size_t)row * K_ + c4 * 4);
            }
#pragma unroll
            for (int r = 0; r < 8; r++) {
                int idx = tid + r * 256, n = idx & 63, k = idx >> 6;
                pB[r] = Bw[(size_t)(kc + k) * EMB_ + n0 + n];
            }
        }
#pragma unroll
        for (int s = 0; s < 2; s++) {
            uint32_t ah[2][4], al[2][4], bh[4][2], bl[4][2];
#pragma unroll
            for (int mt = 0; mt < 2; mt++) {
                uint32_t off = (uint32_t)((mt * 16 * SA_ + s * 16) * 2);
                ldsm_x4(ah[mt], uAh + off);
                ldsm_x4(al[mt], uAl + off);
            }
#pragma unroll
            for (int nt = 0; nt < 4; nt++) {
                uint32_t off = (uint32_t)((nt * 8 * SA_ + s * 16) * 2);
                ldsm_x2(bh[nt], uBh + off);
                ldsm_x2(bl[nt], uBl + off);
            }
#pragma unroll
            for (int mt = 0; mt < 2; mt++)
#pragma unroll
                for (int nt = 0; nt < 4; nt++) {
                    mma16816(acc[mt][nt], ah[mt], bh[nt]);
                    mma16816(acc[mt][nt], ah[mt], bl[nt]);
                    mma16816(acc[mt][nt], al[mt], bh[nt]);
                }
        }
    }
#pragma unroll
    for (int mt = 0; mt < 2; mt++) {
        int r0 = m0 + wm + mt * 16 + g;
        int r1 = r0 + 8;
#pragma unroll
        for (int nt = 0; nt < 4; nt++) {
            int cn = n0 + wn + nt * 8 + 2 * t;
            float2 e0 = *(const float2*)(elec + (size_t)r0 * EMB_ + cn);
            float2 e1 = *(const float2*)(elec + (size_t)r1 * EMB_ + cn);
            float bs0 = sBias[cn - n0], bs1 = sBias[cn - n0 + 1];
            float2 o0 = make_float2(acc[mt][nt][0] + e0.x + bs0,
                                    acc[mt][nt][1] + e0.y + bs1);
            float2 o1 = make_float2(acc[mt][nt][2] + e1.x + bs0,
                                    acc[mt][nt][3] + e1.y + bs1);
            *(float2*)(out + (size_t)r0 * EMB_ + cn) = o0;
            *(float2*)(out + (size_t)r1 * EMB_ + cn) = o1;
        }
    }
}

// ============================================================
// launch
// ============================================================
extern "C" void kernel_launch(void* const* d_in, const int* in_sizes, int n_in,
                              void* d_out, int out_size) {
    const float* nuc       = (const float*)d_in[0];
    const float* elec      = (const float*)d_in[1];
    const float* dist      = (const float*)d_in[2];
    const int*   e_type    = (const int*)d_in[3];
    const int*   senders   = (const int*)d_in[4];
    const int*   receivers = (const int*)d_in[5];
    EdgeParams P;
    P.W1[0] = (const float*)d_in[6];  P.b1[0] = (const float*)d_in[7];
    P.W2[0] = (const float*)d_in[8];  P.b2[0] = (const float*)d_in[9];
    P.W1[1] = (const float*)d_in[10]; P.b1[1] = (const float*)d_in[11];
    P.W2[1] = (const float*)d_in[12]; P.b2[1] = (const float*)d_in[13];
    P.W1[2] = (const float*)d_in[14]; P.b1[2] = (const float*)d_in[15];
    P.W2[2] = (const float*)d_in[16]; P.b2[2] = (const float*)d_in[17];
    const float* hW  = (const float*)d_in[18];
    const float* hb  = (const float*)d_in[19];
    const float* gsW = (const float*)d_in[20];
    const float* gsb = (const float*)d_in[21];
    const float* gaW = (const float*)d_in[22];
    const float* gab = (const float*)d_in[23];
    const float* gnW = (const float*)d_in[24];
    const float* gnb = (const float*)d_in[25];
    float* out = (float*)d_out;

    const int EDGE_SMEM = 75264;
    cudaFuncSetAttribute(k_edge, cudaFuncAttributeMaxDynamicSharedMemorySize,
                         EDGE_SMEM);

    k_zero<<<(3 * N_EROWS * K_ / 4 + 255) / 256, 256>>>();
    k_bin<<<(E_ + 255) / 256, 256>>>(e_type, receivers);
    k_hx_nuc<<<(B_ * N_NUCP * K_ / 4 + 255) / 256, 256>>>(nuc);
    dim3 gh(N_EROWS / 128, K_ / 64);
    k_hx_mma<<<gh, 256>>>(elec, hW, hb);
    dim3 ge(EDGE_BLOCKS, 3);
    k_edge<<<ge, 256, EDGE_SMEM>>>(P, dist, senders, receivers);
    dim3 go(N_EROWS / 128, EMB_ / 64);
    k_out_mma<<<go, 256>>>(elec, gsW, gaW, gnW, gsb, gab, gnb, out);
}

// round 15
// speedup vs baseline: 2.3680x; 1.0164x over previous
#include <cuda_runtime.h>
#include <cuda_bf16.h>
#include <math.h>
#include <stdint.h>

#define B_      2048
#define N_NUCP  4
#define N_ELECP 16
#define N_PARTP 20
#define N_NODES (B_ * N_PARTP)   // 40960
#define N_EROWS (B_ * N_ELECP)   // 32768
#define E_      307200
#define D_      64
#define K_      128
#define EMB_    256
#define LOG2F_  0.69314718055994530942f

// ---- scratch (static __device__ arrays; no allocation allowed) ----
__device__ float g_hx[N_NODES * K_];          // ~21 MB
__device__ float g_z[3 * N_EROWS * K_];       // ~50 MB
__device__ int   g_list[3 * E_];
__device__ int   g_cnt[4];

// ============================================================
// helpers
// ============================================================
__device__ __forceinline__ void splitbf(float x, __nv_bfloat16& h, __nv_bfloat16& l) {
    h = __float2bfloat16(x);
    l = __float2bfloat16(x - __bfloat162float(h));
}

__device__ __forceinline__ void mma16816(float* c, const uint32_t* a, const uint32_t* b) {
    asm volatile(
        "mma.sync.aligned.m16n8k16.row.col.f32.bf16.bf16.f32 "
        "{%0,%1,%2,%3}, {%4,%5,%6,%7}, {%8,%9}, {%0,%1,%2,%3};"
        : "+f"(c[0]), "+f"(c[1]), "+f"(c[2]), "+f"(c[3])
        : "r"(a[0]), "r"(a[1]), "r"(a[2]), "r"(a[3]), "r"(b[0]), "r"(b[1]));
}

__device__ __forceinline__ void ldsm_x4(uint32_t* r, uint32_t addr) {
    asm volatile("ldmatrix.sync.aligned.m8n8.x4.shared.b16 {%0,%1,%2,%3}, [%4];"
        : "=r"(r[0]), "=r"(r[1]), "=r"(r[2]), "=r"(r[3]) : "r"(addr));
}

__device__ __forceinline__ void ldsm_x2(uint32_t* r, uint32_t addr) {
    asm volatile("ldmatrix.sync.aligned.m8n8.x2.shared.b16 {%0,%1}, [%2];"
        : "=r"(r[0]), "=r"(r[1]) : "r"(addr));
}

__device__ __forceinline__ void red2(float* p, float x, float y) {
    asm volatile("red.global.add.v2.f32 [%0], {%1,%2};"
                 :: "l"(p), "f"(x), "f"(y) : "memory");
}

// ============================================================
// K1: zero z channels + counters
// ============================================================
__global__ void k_zero() {
    int i = blockIdx.x * blockDim.x + threadIdx.x;
    const int n4 = 3 * N_EROWS * K_ / 4;
    if (i < n4) ((float4*)g_z)[i] = make_float4(0.f, 0.f, 0.f, 0.f);
    if (i < 4) g_cnt[i] = 0;
}

// ============================================================
// K2: bin edges by type, dropping edges whose receiver is a nucleus
// ============================================================
__global__ void k_bin(const int* __restrict__ e_type,
                      const int* __restrict__ receivers) {
    int e = blockIdx.x * blockDim.x + threadIdx.x;
    if (e >= E_) return;
    int r = receivers[e];
    if ((r % N_PARTP) < N_NUCP) return;
    int ty = e_type[e];
    int slot = (ty == 3) ? 0 : ((ty == 4) ? 1 : 2);
    int pos = atomicAdd(&g_cnt[slot], 1);
    g_list[slot * E_ + pos] = e;
}

// ============================================================
// K3: hx nucleus rows (plain copy)
// ============================================================
__global__ void k_hx_nuc(const float* __restrict__ nuc) {
    int i = blockIdx.x * blockDim.x + threadIdx.x;
    const int n4 = B_ * N_NUCP * K_ / 4;
    if (i >= n4) return;
    int k4  = i & (K_ / 4 - 1);
    int row = i >> 5;
    int b = row >> 2, p = row & 3;
    ((float4*)g_hx)[((size_t)(b * N_PARTP + p)) * (K_ / 4) + k4] =
        ((const float4*)nuc)[i];
}

// ============================================================
// double-buffered smem layout for k_hx / k_out (BM=128, BN=64, BK=32)
// ============================================================
#define SA_      40                 // padded row stride (bf16), ldmatrix conflict-free
#define A_ELEMS  (128 * SA_)        // 5120 bf16 per A buffer
#define B_ELEMS  (64 * SA_)         // 2560 bf16 per B buffer
#define OFF_AL   (2 * A_ELEMS)      // 10240
#define OFF_BH   (4 * A_ELEMS)      // 20480
#define OFF_BL   (OFF_BH + 2 * B_ELEMS)  // 25600
#define DYN_ELEMS (OFF_BL + 2 * B_ELEMS) // 30720 bf16 = 61440 B

// ============================================================
// K4: hx electron rows: bf16-split mma + ldmatrix + DOUBLE BUFFER
// ============================================================
__global__ void __launch_bounds__(256)
k_hx_mma(const float* __restrict__ elec,
         const float* __restrict__ hW,
         const float* __restrict__ hb) {
    extern __shared__ __align__(16) __nv_bfloat16 dyn[];
    __shared__ float sBias[64];
    int tid = threadIdx.x, lane = tid & 31, w = tid >> 5;
    int wm = (w & 3) * 32, wn = (w >> 2) * 32;
    int g = lane >> 2, t = lane & 3;
    int m0 = blockIdx.x * 128, n0 = blockIdx.y * 64;
    if (tid < 64) sBias[tid] = hb[n0 + tid];

    int aRow = (lane & 7) + ((lane >> 3) & 1) * 8;
    int aK   = ((lane >> 4) & 1) * 8;
    int bRow = lane & 7;
    int bK   = ((lane >> 3) & 1) * 8;
    uint32_t uAh = (uint32_t)__cvta_generic_to_shared(&dyn[(wm + aRow) * SA_ + aK]);
    uint32_t uAl = uAh + OFF_AL * 2;
    uint32_t uBh = (uint32_t)__cvta_generic_to_shared(&dyn[OFF_BH + (wn + bRow) * SA_ + bK]);
    uint32_t uBl = uBh + 2 * B_ELEMS * 2;

    float acc[2][4][4];
#pragma unroll
    for (int a = 0; a < 2; a++)
#pragma unroll
        for (int b = 0; b < 4; b++)
#pragma unroll
            for (int c = 0; c < 4; c++) acc[a][b][c] = 0.f;

    float4 pA[4]; float pB[8];
    {
        const float* Ab = elec + (size_t)m0 * EMB_;
#pragma unroll
        for (int r = 0; r < 4; r++) {
            int idx = tid + r * 256, row = idx >> 3, c4 = idx & 7;
            pA[r] = *(const float4*)(Ab + (size_t)row * EMB_ + c4 * 4);
        }
#pragma unroll
        for (int r = 0; r < 8; r++) {
            int idx = tid + r * 256, n = idx & 63, k = idx >> 6;
            pB[r] = hW[(size_t)k * K_ + n0 + n];
        }
    }
    {
        __nv_bfloat16* pAh = dyn;
        __nv_bfloat16* pAl = dyn + OFF_AL;
        __nv_bfloat16* pBh = dyn + OFF_BH;
        __nv_bfloat16* pBl = dyn + OFF_BL;
#pragma unroll
        for (int r = 0; r < 4; r++) {
            int idx = tid + r * 256, row = idx >> 3, c = (idx & 7) * 4;
            float4 v = pA[r];
            __nv_bfloat16 h0, l0, h1, l1, h2, l2, h3, l3;
            splitbf(v.x, h0, l0); splitbf(v.y, h1, l1);
            splitbf(v.z, h2, l2); splitbf(v.w, h3, l3);
            *(__nv_bfloat162*)&pAh[row * SA_ + c]     = __halves2bfloat162(h0, h1);
            *(__nv_bfloat162*)&pAh[row * SA_ + c + 2] = __halves2bfloat162(h2, h3);
            *(__nv_bfloat162*)&pAl[row * SA_ + c]     = __halves2bfloat162(l0, l1);
            *(__nv_bfloat162*)&pAl[row * SA_ + c + 2] = __halves2bfloat162(l2, l3);
        }
#pragma unroll
        for (int r = 0; r < 8; r++) {
            int idx = tid + r * 256, n = idx & 63, k = idx >> 6;
            __nv_bfloat16 h, l; splitbf(pB[r], h, l);
            pBh[n * SA_ + k] = h; pBl[n * SA_ + k] = l;
        }
    }
    __syncthreads();

    for (int it = 0; it < 8; it++) {
        int cur = it & 1;
        if (it < 7) {
            int k0 = (it + 1) * 32;
            const float* Ab = elec + (size_t)m0 * EMB_ + k0;
#pragma unroll
            for (int r = 0; r < 4; r++) {
                int idx = tid + r * 256, row = idx >> 3, c4 = idx & 7;
                pA[r] = *(const float4*)(Ab + (size_t)row * EMB_ + c4 * 4);
            }
#pragma unroll
            for (int r = 0; r < 8; r++) {
                int idx = tid + r * 256, n = idx & 63, k = idx >> 6;
                pB[r] = hW[(size_t)(k0 + k) * K_ + n0 + n];
            }
        }
        uint32_t aoff = (uint32_t)cur * (A_ELEMS * 2);
        uint32_t boff = (uint32_t)cur * (B_ELEMS * 2);
#pragma unroll
        for (int s = 0; s < 2; s++) {
            uint32_t ah[2][4], al[2][4], bh[4][2], bl[4][2];
#pragma unroll
            for (int mt = 0; mt < 2; mt++) {
                uint32_t off = (uint32_t)((mt * 16 * SA_ + s * 16) * 2);
                ldsm_x4(ah[mt], uAh + aoff + off);
                ldsm_x4(al[mt], uAl + aoff + off);
            }
#pragma unroll
            for (int nt = 0; nt < 4; nt++) {
                uint32_t off = (uint32_t)((nt * 8 * SA_ + s * 16) * 2);
                ldsm_x2(bh[nt], uBh + boff + off);
                ldsm_x2(bl[nt], uBl + boff + off);
            }
#pragma unroll
            for (int mt = 0; mt < 2; mt++)
#pragma unroll
                for (int nt = 0; nt < 4; nt++) {
                    mma16816(acc[mt][nt], ah[mt], bh[nt]);
                    mma16816(acc[mt][nt], ah[mt], bl[nt]);
                    mma16816(acc[mt][nt], al[mt], bh[nt]);
                }
        }
        if (it < 7) {
            int bb = (it + 1) & 1;
            __nv_bfloat16* pAh = dyn + bb * A_ELEMS;
            __nv_bfloat16* pAl = dyn + OFF_AL + bb * A_ELEMS;
            __nv_bfloat16* pBh = dyn + OFF_BH + bb * B_ELEMS;
            __nv_bfloat16* pBl = dyn + OFF_BL + bb * B_ELEMS;
#pragma unroll
            for (int r = 0; r < 4; r++) {
                int idx = tid + r * 256, row = idx >> 3, c = (idx & 7) * 4;
                float4 v = pA[r];
                __nv_bfloat16 h0, l0, h1, l1, h2, l2, h3, l3;
                splitbf(v.x, h0, l0); splitbf(v.y, h1, l1);
                splitbf(v.z, h2, l2); splitbf(v.w, h3, l3);
                *(__nv_bfloat162*)&pAh[row * SA_ + c]     = __halves2bfloat162(h0, h1);
                *(__nv_bfloat162*)&pAh[row * SA_ + c + 2] = __halves2bfloat162(h2, h3);
                *(__nv_bfloat162*)&pAl[row * SA_ + c]     = __halves2bfloat162(l0, l1);
                *(__nv_bfloat162*)&pAl[row * SA_ + c + 2] = __halves2bfloat162(l2, l3);
            }
#pragma unroll
            for (int r = 0; r < 8; r++) {
                int idx = tid + r * 256, n = idx & 63, k = idx >> 6;
                __nv_bfloat16 h, l; splitbf(pB[r], h, l);
                pBh[n * SA_ + k] = h; pBl[n * SA_ + k] = l;
            }
            __syncthreads();
        }
    }
#pragma unroll
    for (int mt = 0; mt < 2; mt++) {
        int r0 = m0 + wm + mt * 16 + g;
        int r1 = r0 + 8;
        int node0 = (r0 >> 4) * N_PARTP + N_NUCP + (r0 & 15);
        int node1 = (r1 >> 4) * N_PARTP + N_NUCP + (r1 & 15);
#pragma unroll
        for (int nt = 0; nt < 4; nt++) {
            int cn = n0 + wn + nt * 8 + 2 * t;
            float bs0 = sBias[cn - n0], bs1 = sBias[cn - n0 + 1];
            float2 o0 = make_float2(acc[mt][nt][0] + bs0, acc[mt][nt][1] + bs1);
            float2 o1 = make_float2(acc[mt][nt][2] + bs0, acc[mt][nt][3] + bs1);
            *(float2*)(g_hx + (size_t)node0 * K_ + cn) = o0;
            *(float2*)(g_hx + (size_t)node1 * K_ + cn) = o1;
        }
    }
}

// ============================================================
// K5: PERSISTENT edge MLP (bf16-split mma + ldmatrix) + RED scatter
// [verified R12 — unchanged]
// ============================================================
#define SE_ 72
#define EDGE_BLOCKS 96

struct EdgeParams {
    const float* W1[3]; const float* b1[3];
    const float* W2[3]; const float* b2[3];
};

__global__ void __launch_bounds__(256)
k_edge(EdgeParams P,
       const float* __restrict__ dist,
       const int* __restrict__ senders,
       const int* __restrict__ receivers) {
    extern __shared__ __align__(16) char smc[];
    __nv_bfloat16* sXh  = (__nv_bfloat16*)(smc);
    __nv_bfloat16* sXl  = (__nv_bfloat16*)(smc + 9216);
    __nv_bfloat16* sW1h = (__nv_bfloat16*)(smc + 18432);
    __nv_bfloat16* sW1l = (__nv_bfloat16*)(smc + 27648);
    __nv_bfloat16* sW2h = (__nv_bfloat16*)(smc + 36864);
    __nv_bfloat16* sW2l = (__nv_bfloat16*)(smc + 55296);
    float* sb1 = (float*)(smc + 73728);
    float* sb2 = (float*)(smc + 73984);
    int* sSend = (int*)(smc + 74496);
    int* sZrow = (int*)(smc + 74752);
    int* sEid  = (int*)(smc + 75008);
    __nv_bfloat16* sHh = sXh;
    __nv_bfloat16* sHl = sXl;

    int ty_ = blockIdx.y;
    int cnt = g_cnt[ty_];
    int tid = threadIdx.x, lane = tid & 31, w = tid >> 5;
    int g = lane >> 2, t = lane & 3;

    {
        const float* W1 = P.W1[ty_]; const float* W2 = P.W2[ty_];
#pragma unroll
        for (int r = 0; r < 16; r++) {
            int idx = tid + r * 256;
            int n = idx >> 6, k = idx & 63;
            __nv_bfloat16 h, l; splitbf(W1[k * D_ + n], h, l);
            sW1h[n * SE_ + k] = h; sW1l[n * SE_ + k] = l;
        }
#pragma unroll
        for (int r = 0; r < 32; r++) {
            int idx = tid + r * 256;
            int n = idx >> 6, k = idx & 63;
            __nv_bfloat16 h, l; splitbf(W2[k * K_ + n], h, l);
            sW2h[n * SE_ + k] = h; sW2l[n * SE_ + k] = l;
        }
        if (tid < 64)  sb1[tid] = P.b1[ty_][tid];
        if (tid < 128) sb2[tid] = P.b2[ty_][tid];
    }

    int wm1 = (w & 1) * 32, wn1 = (w >> 1) * 16;
    int wm2 = (w & 1) * 32, wn2 = (w >> 1) * 32;
    float* zbase = g_z + (size_t)ty_ * N_EROWS * K_;

    int aRow = (lane & 7) + ((lane >> 3) & 1) * 8;
    int aK   = ((lane >> 4) & 1) * 8;
    int bRow = lane & 7;
    int bK   = ((lane >> 3) & 1) * 8;
    uint32_t uXh = (uint32_t)__cvta_generic_to_shared(&sXh[(wm1 + aRow) * SE_ + aK]);
    uint32_t uXl = (uint32_t)__cvta_generic_to_shared(&sXl[(wm1 + aRow) * SE_ + aK]);
    uint32_t uW1h = (uint32_t)__cvta_generic_to_shared(&sW1h[(wn1 + bRow) * SE_ + bK]);
    uint32_t uW1l = (uint32_t)__cvta_generic_to_shared(&sW1l[(wn1 + bRow) * SE_ + bK]);
    uint32_t uW2h = (uint32_t)__cvta_generic_to_shared(&sW2h[(wn2 + bRow) * SE_ + bK]);
    uint32_t uW2l = (uint32_t)__cvta_generic_to_shared(&sW2l[(wn2 + bRow) * SE_ + bK]);

    for (int e0 = blockIdx.x * 64; e0 < cnt; e0 += EDGE_BLOCKS * 64) {
        int ne = min(64, cnt - e0);
        __syncthreads();

        if (tid < 64) {
            int sv = 0, zr = 0, eid = 0;
            if (tid < ne) {
                eid = g_list[ty_ * E_ + e0 + tid];
                sv  = senders[eid];
                int r = receivers[eid];
                zr  = (r / N_PARTP) * N_ELECP + (r % N_PARTP) - N_NUCP;
            }
            sSend[tid] = sv; sZrow[tid] = zr; sEid[tid] = eid;
        }
        __syncthreads();

#pragma unroll
        for (int r = 0; r < 4; r++) {
            int idx = tid + r * 256;
            int row = idx >> 4, c4 = idx & 15;
            float4 v = make_float4(0.f, 0.f, 0.f, 0.f);
            if (row < ne)
                v = ((const float4*)(dist + (size_t)sEid[row] * D_))[c4];
            int c = c4 * 4;
            __nv_bfloat16 h0, l0, h1, l1, h2, l2, h3, l3;
            splitbf(v.x, h0, l0); splitbf(v.y, h1, l1);
            splitbf(v.z, h2, l2); splitbf(v.w, h3, l3);
            *(__nv_bfloat162*)&sXh[row * SE_ + c]     = __halves2bfloat162(h0, h1);
            *(__nv_bfloat162*)&sXh[row * SE_ + c + 2] = __halves2bfloat162(h2, h3);
            *(__nv_bfloat162*)&sXl[row * SE_ + c]     = __halves2bfloat162(l0, l1);
            *(__nv_bfloat162*)&sXl[row * SE_ + c + 2] = __halves2bfloat162(l2, l3);
        }
        __syncthreads();

        float acc1[2][2][4];
#pragma unroll
        for (int a = 0; a < 2; a++)
#pragma unroll
            for (int b = 0; b < 2; b++)
#pragma unroll
                for (int c = 0; c < 4; c++) acc1[a][b][c] = 0.f;
#pragma unroll
        for (int s = 0; s < 4; s++) {
            uint32_t ah[2][4], al[2][4], bh[2][2], bl[2][2];
#pragma unroll
            for (int mt = 0; mt < 2; mt++) {
                uint32_t off = (uint32_t)((mt * 16 * SE_ + s * 16) * 2);
                ldsm_x4(ah[mt], uXh + off);
                ldsm_x4(al[mt], uXl + off);
            }
#pragma unroll
            for (int nt = 0; nt < 2; nt++) {
                uint32_t off = (uint32_t)((nt * 8 * SE_ + s * 16) * 2);
                ldsm_x2(bh[nt], uW1h + off);
                ldsm_x2(bl[nt], uW1l + off);
            }
#pragma unroll
            for (int mt = 0; mt < 2; mt++)
#pragma unroll
                for (int nt = 0; nt < 2; nt++) {
                    mma16816(acc1[mt][nt], ah[mt], bh[nt]);
                    mma16816(acc1[mt][nt], ah[mt], bl[nt]);
                    mma16816(acc1[mt][nt], al[mt], bh[nt]);
                }
        }
        __syncthreads();

#pragma unroll
        for (int mt = 0; mt < 2; mt++) {
#pragma unroll
            for (int nt = 0; nt < 2; nt++) {
                int col = wn1 + nt * 8 + 2 * t;
                float b0 = sb1[col], b1v = sb1[col + 1];
                int r0 = wm1 + mt * 16 + g;
#pragma unroll
                for (int hr = 0; hr < 2; hr++) {
                    int row = r0 + hr * 8;
                    float x0 = acc1[mt][nt][hr * 2 + 0] + b0;
                    float x1 = acc1[mt][nt][hr * 2 + 1] + b1v;
                    float v0 = fmaxf(x0, 0.f) + log1pf(expf(-fabsf(x0))) - LOG2F_;
                    float v1 = fmaxf(x1, 0.f) + log1pf(expf(-fabsf(x1))) - LOG2F_;
                    __nv_bfloat16 h0, l0, h1, l1;
                    splitbf(v0, h0, l0); splitbf(v1, h1, l1);
                    *(__nv_bfloat162*)&sHh[row * SE_ + col] = __halves2bfloat162(h0, h1);
                    *(__nv_bfloat162*)&sHl[row * SE_ + col] = __halves2bfloat162(l0, l1);
                }
            }
        }
        __syncthreads();

        float acc2[2][4][4];
#pragma unroll
        for (int a = 0; a < 2; a++)
#pragma unroll
            for (int b = 0; b < 4; b++)
#pragma unroll
                for (int c = 0; c < 4; c++) acc2[a][b][c] = 0.f;
#pragma unroll
        for (int s = 0; s < 4; s++) {
            uint32_t ah[2][4], al[2][4], bh[4][2], bl[4][2];
#pragma unroll
            for (int mt = 0; mt < 2; mt++) {
                uint32_t off = (uint32_t)((mt * 16 * SE_ + s * 16) * 2);
                ldsm_x4(ah[mt], uXh + off);
                ldsm_x4(al[mt], uXl + off);
            }
#pragma unroll
            for (int nt = 0; nt < 4; nt++) {
                uint32_t off = (uint32_t)((nt * 8 * SE_ + s * 16) * 2);
                ldsm_x2(bh[nt], uW2h + off);
                ldsm_x2(bl[nt], uW2l + off);
            }
#pragma unroll
            for (int mt = 0; mt < 2; mt++)
#pragma unroll
                for (int nt = 0; nt < 4; nt++) {
                    mma16816(acc2[mt][nt], ah[mt], bh[nt]);
                    mma16816(acc2[mt][nt], ah[mt], bl[nt]);
                    mma16816(acc2[mt][nt], al[mt], bh[nt]);
                }
        }

#pragma unroll
        for (int mt = 0; mt < 2; mt++) {
#pragma unroll
            for (int hr = 0; hr < 2; hr++) {
                int e = wm2 + mt * 16 + g + hr * 8;
                if (e < ne) {
                    int sv = sSend[e], zr = sZrow[e];
                    const float* hx = g_hx + (size_t)sv * K_;
                    float* zp = zbase + (size_t)zr * K_;
#pragma unroll
                    for (int nt = 0; nt < 4; nt++) {
                        int col = wn2 + nt * 8 + 2 * t;
                        float2 h2 = *(const float2*)(hx + col);
                        float v0 = (acc2[mt][nt][hr * 2 + 0] + sb2[col])     * h2.x;
                        float v1 = (acc2[mt][nt][hr * 2 + 1] + sb2[col + 1]) * h2.y;
                        red2(zp + col, v0, v1);
                    }
                }
            }
        }
    }
}

// ============================================================
// K6: out = elec + [z] @ [g..] + Σb  — bf16-split mma + ldmatrix + DOUBLE BUFFER
// ============================================================
__global__ void __launch_bounds__(256)
k_out_mma(const float* __restrict__ elec,
          const float* __restrict__ gW0, const float* __restrict__ gW1,
          const float* __restrict__ gW2,
          const float* __restrict__ gb0, const float* __restrict__ gb1,
          const float* __restrict__ gb2,
          float* __restrict__ out) {
    extern __shared__ __align__(16) __nv_bfloat16 dyn[];
    __shared__ float sBias[64];
    int tid = threadIdx.x, lane = tid & 31, w = tid >> 5;
    int wm = (w & 3) * 32, wn = (w >> 2) * 32;
    int g = lane >> 2, t = lane & 3;
    int m0 = blockIdx.x * 128, n0 = blockIdx.y * 64;
    if (tid < 64)
        sBias[tid] = gb0[n0 + tid] + gb1[n0 + tid] + gb2[n0 + tid];

    int aRow = (lane & 7) + ((lane >> 3) & 1) * 8;
    int aK   = ((lane >> 4) & 1) * 8;
    int bRow = lane & 7;
    int bK   = ((lane >> 3) & 1) * 8;
    uint32_t uAh = (uint32_t)__cvta_generic_to_shared(&dyn[(wm + aRow) * SA_ + aK]);
    uint32_t uAl = uAh + OFF_AL * 2;
    uint32_t uBh = (uint32_t)__cvta_generic_to_shared(&dyn[OFF_BH + (wn + bRow) * SA_ + bK]);
    uint32_t uBl = uBh + 2 * B_ELEMS * 2;

    float acc[2][4][4];
#pragma unroll
    for (int a = 0; a < 2; a++)
#pragma unroll
        for (int b = 0; b < 4; b++)
#pragma unroll
            for (int c = 0; c < 4; c++) acc[a][b][c] = 0.f;

    float4 pA[4]; float pB[8];
    {
        const float* Az = g_z + (size_t)m0 * K_;
#pragma unroll
        for (int r = 0; r < 4; r++) {
            int idx = tid + r * 256, row = idx >> 3, c4 = idx & 7;
            pA[r] = *(const float4*)(Az + (size_t)row * K_ + c4 * 4);
        }
#pragma unroll
        for (int r = 0; r < 8; r++) {
            int idx = tid + r * 256, n = idx & 63, k = idx >> 6;
            pB[r] = gW0[(size_t)k * EMB_ + n0 + n];
        }
    }
    {
        __nv_bfloat16* pAh = dyn;
        __nv_bfloat16* pAl = dyn + OFF_AL;
        __nv_bfloat16* pBh = dyn + OFF_BH;
        __nv_bfloat16* pBl = dyn + OFF_BL;
#pragma unroll
        for (int r = 0; r < 4; r++) {
            int idx = tid + r * 256, row = idx >> 3, c = (idx & 7) * 4;
            float4 v = pA[r];
            __nv_bfloat16 h0, l0, h1, l1, h2, l2, h3, l3;
            splitbf(v.x, h0, l0); splitbf(v.y, h1, l1);
            splitbf(v.z, h2, l2); splitbf(v.w, h3, l3);
            *(__nv_bfloat162*)&pAh[row * SA_ + c]     = __halves2bfloat162(h0, h1);
            *(__nv_bfloat162*)&pAh[row * SA_ + c + 2] = __halves2bfloat162(h2, h3);
            *(__nv_bfloat162*)&pAl[row * SA_ + c]     = __halves2bfloat162(l0, l1);
            *(__nv_bfloat162*)&pAl[row * SA_ + c + 2] = __halves2bfloat162(l2, l3);
        }
#pragma unroll
        for (int r = 0; r < 8; r++) {
            int idx = tid + r * 256, n = idx & 63, k = idx >> 6;
            __nv_bfloat16 h, l; splitbf(pB[r], h, l);
            pBh[n * SA_ + k] = h; pBl[n * SA_ + k] = l;
        }
    }
    __syncthreads();

    for (int it = 0; it < 12; it++) {
        int cur = it & 1;
        if (it < 11) {
            int k0 = (it + 1) * 32;
            int tsel = k0 >> 7, kc = k0 & 127;
            const float* Az = g_z + (size_t)tsel * N_EROWS * K_ +
                              (size_t)m0 * K_ + kc;
            const float* Bw = (tsel == 0) ? gW0 : ((tsel == 1) ? gW1 : gW2);
#pragma unroll
            for (int r = 0; r < 4; r++) {
                int idx = tid + r * 256, row = idx >> 3, c4 = idx & 7;
                pA[r] = *(const float4*)(Az + (size_t)row * K_ + c4 * 4);
            }
#pragma unroll
            for (int r = 0; r < 8; r++) {
                int idx = tid + r * 256, n = idx & 63, k = idx >> 6;
                pB[r] = Bw[(size_t)(kc + k) * EMB_ + n0 + n];
            }
        }
        uint32_t aoff = (uint32_t)cur * (A_ELEMS * 2);
        uint32_t boff = (uint32_t)cur * (B_ELEMS * 2);
#pragma unroll
        for (int s = 0; s < 2; s++) {
            uint32_t ah[2][4], al[2][4], bh[4][2], bl[4][2];
#pragma unroll
            for (int mt = 0; mt < 2; mt++) {
                uint32_t off = (uint32_t)((mt * 16 * SA_ + s * 16) * 2);
                ldsm_x4(ah[mt], uAh + aoff + off);
                ldsm_x4(al[mt], uAl + aoff + off);
            }
#pragma unroll
            for (int nt = 0; nt < 4; nt++) {
                uint32_t off = (uint32_t)((nt * 8 * SA_ + s * 16) * 2);
                ldsm_x2(bh[nt], uBh + boff + off);
                ldsm_x2(bl[nt], uBl + boff + off);
            }
#pragma unroll
            for (int mt = 0; mt < 2; mt++)
#pragma unroll
                for (int nt = 0; nt < 4; nt++) {
                    mma16816(acc[mt][nt], ah[mt], bh[nt]);
                    mma16816(acc[mt][nt], ah[mt], bl[nt]);
                    mma16816(acc[mt][nt], al[mt], bh[nt]);
                }
        }
        if (it < 11) {
            int bb = (it + 1) & 1;
            __nv_bfloat16* pAh = dyn + bb * A_ELEMS;
            __nv_bfloat16* pAl = dyn + OFF_AL + bb * A_ELEMS;
            __nv_bfloat16* pBh = dyn + OFF_BH + bb * B_ELEMS;
            __nv_bfloat16* pBl = dyn + OFF_BL + bb * B_ELEMS;
#pragma unroll
            for (int r = 0; r < 4; r++) {
                int idx = tid + r * 256, row = idx >> 3, c = (idx & 7) * 4;
                float4 v = pA[r];
                __nv_bfloat16 h0, l0, h1, l1, h2, l2, h3, l3;
                splitbf(v.x, h0, l0); splitbf(v.y, h1, l1);
                splitbf(v.z, h2, l2); splitbf(v.w, h3, l3);
                *(__nv_bfloat162*)&pAh[row * SA_ + c]     = __halves2bfloat162(h0, h1);
                *(__nv_bfloat162*)&pAh[row * SA_ + c + 2] = __halves2bfloat162(h2, h3);
                *(__nv_bfloat162*)&pAl[row * SA_ + c]     = __halves2bfloat162(l0, l1);
                *(__nv_bfloat162*)&pAl[row * SA_ + c + 2] = __halves2bfloat162(l2, l3);
            }
#pragma unroll
            for (int r = 0; r < 8; r++) {
                int idx = tid + r * 256, n = idx & 63, k = idx >> 6;
                __nv_bfloat16 h, l; splitbf(pB[r], h, l);
                pBh[n * SA_ + k] = h; pBl[n * SA_ + k] = l;
            }
            __syncthreads();
        }
    }
#pragma unroll
    for (int mt = 0; mt < 2; mt++) {
        int r0 = m0 + wm + mt * 16 + g;
        int r1 = r0 + 8;
#pragma unroll
        for (int nt = 0; nt < 4; nt++) {
            int cn = n0 + wn + nt * 8 + 2 * t;
            float2 e0 = *(const float2*)(elec + (size_t)r0 * EMB_ + cn);
            float2 e1 = *(const float2*)(elec + (size_t)r1 * EMB_ + cn);
            float bs0 = sBias[cn - n0], bs1 = sBias[cn - n0 + 1];
            float2 o0 = make_float2(acc[mt][nt][0] + e0.x + bs0,
                                    acc[mt][nt][1] + e0.y + bs1);
            float2 o1 = make_float2(acc[mt][nt][2] + e1.x + bs0,
                                    acc[mt][nt][3] + e1.y + bs1);
            *(float2*)(out + (size_t)r0 * EMB_ + cn) = o0;
            *(float2*)(out + (size_t)r1 * EMB_ + cn) = o1;
        }
    }
}

// ============================================================
// launch
// ============================================================
extern "C" void kernel_launch(void* const* d_in, const int* in_sizes, int n_in,
                              void* d_out, int out_size) {
    const float* nuc       = (const float*)d_in[0];
    const float* elec      = (const float*)d_in[1];
    const float* dist      = (const float*)d_in[2];
    const int*   e_type    = (const int*)d_in[3];
    const int*   senders   = (const int*)d_in[4];
    const int*   receivers = (const int*)d_in[5];
    EdgeParams P;
    P.W1[0] = (const float*)d_in[6];  P.b1[0] = (const float*)d_in[7];
    P.W2[0] = (const float*)d_in[8];  P.b2[0] = (const float*)d_in[9];
    P.W1[1] = (const float*)d_in[10]; P.b1[1] = (const float*)d_in[11];
    P.W2[1] = (const float*)d_in[12]; P.b2[1] = (const float*)d_in[13];
    P.W1[2] = (const float*)d_in[14]; P.b1[2] = (const float*)d_in[15];
    P.W2[2] = (const float*)d_in[16]; P.b2[2] = (const float*)d_in[17];
    const float* hW  = (const float*)d_in[18];
    const float* hb  = (const float*)d_in[19];
    const float* gsW = (const float*)d_in[20];
    const float* gsb = (const float*)d_in[21];
    const float* gaW = (const float*)d_in[22];
    const float* gab = (const float*)d_in[23];
    const float* gnW = (const float*)d_in[24];
    const float* gnb = (const float*)d_in[25];
    float* out = (float*)d_out;

    const int EDGE_SMEM = 75264;
    const int GEMM_SMEM = DYN_ELEMS * 2;   // 61440 B
    cudaFuncSetAttribute(k_edge, cudaFuncAttributeMaxDynamicSharedMemorySize,
                         EDGE_SMEM);
    cudaFuncSetAttribute(k_hx_mma, cudaFuncAttributeMaxDynamicSharedMemorySize,
                         GEMM_SMEM);
    cudaFuncSetAttribute(k_out_mma, cudaFuncAttributeMaxDynamicSharedMemorySize,
                         GEMM_SMEM);

    k_zero<<<(3 * N_EROWS * K_ / 4 + 255) / 256, 256>>>();
    k_bin<<<(E_ + 255) / 256, 256>>>(e_type, receivers);
    k_hx_nuc<<<(B_ * N_NUCP * K_ / 4 + 255) / 256, 256>>>(nuc);
    dim3 gh(N_EROWS / 128, K_ / 64);
    k_hx_mma<<<gh, 256, GEMM_SMEM>>>(elec, hW, hb);
    dim3 ge(EDGE_BLOCKS, 3);
    k_edge<<<ge, 256, EDGE_SMEM>>>(P, dist, senders, receivers);
    dim3 go(N_EROWS / 128, EMB_ / 64);
    k_out_mma<<<go, 256, GEMM_SMEM>>>(elec, gsW, gaW, gnW, gsb, gab, gnb, out);
}

// round 17
// speedup vs baseline: 2.4120x; 1.0186x over previous
#include <cuda_runtime.h>
#include <cuda_bf16.h>
#include <math.h>
#include <stdint.h>

#define B_      2048
#define N_NUCP  4
#define N_ELECP 16
#define N_PARTP 20
#define N_NODES (B_ * N_PARTP)   // 40960
#define N_EROWS (B_ * N_ELECP)   // 32768
#define E_      307200
#define D_      64
#define K_      128
#define EMB_    256
#define LOG2F_  0.69314718055994530942f

// ---- scratch (static __device__ arrays; no allocation allowed) ----
__device__ float g_hx[N_NODES * K_];          // ~21 MB
__device__ float g_z[3 * N_EROWS * K_];       // ~50 MB
__device__ int   g_list[3 * E_];
__device__ int   g_cnt[4];

// ============================================================
// helpers
// ============================================================
__device__ __forceinline__ void splitbf(float x, __nv_bfloat16& h, __nv_bfloat16& l) {
    h = __float2bfloat16(x);
    l = __float2bfloat16(x - __bfloat162float(h));
}

__device__ __forceinline__ void mma16816(float* c, const uint32_t* a, const uint32_t* b) {
    asm volatile(
        "mma.sync.aligned.m16n8k16.row.col.f32.bf16.bf16.f32 "
        "{%0,%1,%2,%3}, {%4,%5,%6,%7}, {%8,%9}, {%0,%1,%2,%3};"
        : "+f"(c[0]), "+f"(c[1]), "+f"(c[2]), "+f"(c[3])
        : "r"(a[0]), "r"(a[1]), "r"(a[2]), "r"(a[3]), "r"(b[0]), "r"(b[1]));
}

__device__ __forceinline__ void ldsm_x4(uint32_t* r, uint32_t addr) {
    asm volatile("ldmatrix.sync.aligned.m8n8.x4.shared.b16 {%0,%1,%2,%3}, [%4];"
        : "=r"(r[0]), "=r"(r[1]), "=r"(r[2]), "=r"(r[3]) : "r"(addr));
}

__device__ __forceinline__ void ldsm_x2(uint32_t* r, uint32_t addr) {
    asm volatile("ldmatrix.sync.aligned.m8n8.x2.shared.b16 {%0,%1}, [%2];"
        : "=r"(r[0]), "=r"(r[1]) : "r"(addr));
}

__device__ __forceinline__ void red2(float* p, float x, float y) {
    asm volatile("red.global.add.v2.f32 [%0], {%1,%2};"
                 :: "l"(p), "f"(x), "f"(y) : "memory");
}

// ============================================================
// K1: zero z channels + counters
// ============================================================
__global__ void k_zero() {
    int i = blockIdx.x * blockDim.x + threadIdx.x;
    const int n4 = 3 * N_EROWS * K_ / 4;
    if (i < n4) ((float4*)g_z)[i] = make_float4(0.f, 0.f, 0.f, 0.f);
    if (i < 4) g_cnt[i] = 0;
}

// ============================================================
// K2: bin edges by type, dropping edges whose receiver is a nucleus
// ============================================================
__global__ void k_bin(const int* __restrict__ e_type,
                      const int* __restrict__ receivers) {
    int e = blockIdx.x * blockDim.x + threadIdx.x;
    if (e >= E_) return;
    int r = receivers[e];
    if ((r % N_PARTP) < N_NUCP) return;
    int ty = e_type[e];
    int slot = (ty == 3) ? 0 : ((ty == 4) ? 1 : 2);
    int pos = atomicAdd(&g_cnt[slot], 1);
    g_list[slot * E_ + pos] = e;
}

// ============================================================
// K3: hx nucleus rows (plain copy)
// ============================================================
__global__ void k_hx_nuc(const float* __restrict__ nuc) {
    int i = blockIdx.x * blockDim.x + threadIdx.x;
    const int n4 = B_ * N_NUCP * K_ / 4;
    if (i >= n4) return;
    int k4  = i & (K_ / 4 - 1);
    int row = i >> 5;
    int b = row >> 2, p = row & 3;
    ((float4*)g_hx)[((size_t)(b * N_PARTP + p)) * (K_ / 4) + k4] =
        ((const float4*)nuc)[i];
}

// ============================================================
// double-buffered smem layout for k_hx / k_out (BM=128, BN=64, BK=32)
// ============================================================
#define SA_      40                 // padded row stride (bf16), ldmatrix conflict-free
#define A_ELEMS  (128 * SA_)        // 5120 bf16 per A buffer
#define B_ELEMS  (64 * SA_)         // 2560 bf16 per B buffer
#define OFF_AL   (2 * A_ELEMS)      // 10240
#define OFF_BH   (4 * A_ELEMS)      // 20480
#define OFF_BL   (OFF_BH + 2 * B_ELEMS)  // 25600
#define DYN_ELEMS (OFF_BL + 2 * B_ELEMS) // 30720 bf16 = 61440 B

// ============================================================
// K4: hx electron rows: bf16-split mma + ldmatrix + DOUBLE BUFFER [verified R15]
// ============================================================
__global__ void __launch_bounds__(256)
k_hx_mma(const float* __restrict__ elec,
         const float* __restrict__ hW,
         const float* __restrict__ hb) {
    extern __shared__ __align__(16) __nv_bfloat16 dyn[];
    __shared__ float sBias[64];
    int tid = threadIdx.x, lane = tid & 31, w = tid >> 5;
    int wm = (w & 3) * 32, wn = (w >> 2) * 32;
    int g = lane >> 2, t = lane & 3;
    int m0 = blockIdx.x * 128, n0 = blockIdx.y * 64;
    if (tid < 64) sBias[tid] = hb[n0 + tid];

    int aRow = (lane & 7) + ((lane >> 3) & 1) * 8;
    int aK   = ((lane >> 4) & 1) * 8;
    int bRow = lane & 7;
    int bK   = ((lane >> 3) & 1) * 8;
    uint32_t uAh = (uint32_t)__cvta_generic_to_shared(&dyn[(wm + aRow) * SA_ + aK]);
    uint32_t uAl = uAh + OFF_AL * 2;
    uint32_t uBh = (uint32_t)__cvta_generic_to_shared(&dyn[OFF_BH + (wn + bRow) * SA_ + bK]);
    uint32_t uBl = uBh + 2 * B_ELEMS * 2;

    float acc[2][4][4];
#pragma unroll
    for (int a = 0; a < 2; a++)
#pragma unroll
        for (int b = 0; b < 4; b++)
#pragma unroll
            for (int c = 0; c < 4; c++) acc[a][b][c] = 0.f;

    float4 pA[4]; float pB[8];
    {
        const float* Ab = elec + (size_t)m0 * EMB_;
#pragma unroll
        for (int r = 0; r < 4; r++) {
            int idx = tid + r * 256, row = idx >> 3, c4 = idx & 7;
            pA[r] = *(const float4*)(Ab + (size_t)row * EMB_ + c4 * 4);
        }
#pragma unroll
        for (int r = 0; r < 8; r++) {
            int idx = tid + r * 256, n = idx & 63, k = idx >> 6;
            pB[r] = hW[(size_t)k * K_ + n0 + n];
        }
    }
    {
        __nv_bfloat16* pAh = dyn;
        __nv_bfloat16* pAl = dyn + OFF_AL;
        __nv_bfloat16* pBh = dyn + OFF_BH;
        __nv_bfloat16* pBl = dyn + OFF_BL;
#pragma unroll
        for (int r = 0; r < 4; r++) {
            int idx = tid + r * 256, row = idx >> 3, c = (idx & 7) * 4;
            float4 v = pA[r];
            __nv_bfloat16 h0, l0, h1, l1, h2, l2, h3, l3;
            splitbf(v.x, h0, l0); splitbf(v.y, h1, l1);
            splitbf(v.z, h2, l2); splitbf(v.w, h3, l3);
            *(__nv_bfloat162*)&pAh[row * SA_ + c]     = __halves2bfloat162(h0, h1);
            *(__nv_bfloat162*)&pAh[row * SA_ + c + 2] = __halves2bfloat162(h2, h3);
            *(__nv_bfloat162*)&pAl[row * SA_ + c]     = __halves2bfloat162(l0, l1);
            *(__nv_bfloat162*)&pAl[row * SA_ + c + 2] = __halves2bfloat162(l2, l3);
        }
#pragma unroll
        for (int r = 0; r < 8; r++) {
            int idx = tid + r * 256, n = idx & 63, k = idx >> 6;
            __nv_bfloat16 h, l; splitbf(pB[r], h, l);
            pBh[n * SA_ + k] = h; pBl[n * SA_ + k] = l;
        }
    }
    __syncthreads();

    for (int it = 0; it < 8; it++) {
        int cur = it & 1;
        if (it < 7) {
            int k0 = (it + 1) * 32;
            const float* Ab = elec + (size_t)m0 * EMB_ + k0;
#pragma unroll
            for (int r = 0; r < 4; r++) {
                int idx = tid + r * 256, row = idx >> 3, c4 = idx & 7;
                pA[r] = *(const float4*)(Ab + (size_t)row * EMB_ + c4 * 4);
            }
#pragma unroll
            for (int r = 0; r < 8; r++) {
                int idx = tid + r * 256, n = idx & 63, k = idx >> 6;
                pB[r] = hW[(size_t)(k0 + k) * K_ + n0 + n];
            }
        }
        uint32_t aoff = (uint32_t)cur * (A_ELEMS * 2);
        uint32_t boff = (uint32_t)cur * (B_ELEMS * 2);
#pragma unroll
        for (int s = 0; s < 2; s++) {
            uint32_t ah[2][4], al[2][4], bh[4][2], bl[4][2];
#pragma unroll
            for (int mt = 0; mt < 2; mt++) {
                uint32_t off = (uint32_t)((mt * 16 * SA_ + s * 16) * 2);
                ldsm_x4(ah[mt], uAh + aoff + off);
                ldsm_x4(al[mt], uAl + aoff + off);
            }
#pragma unroll
            for (int nt = 0; nt < 4; nt++) {
                uint32_t off = (uint32_t)((nt * 8 * SA_ + s * 16) * 2);
                ldsm_x2(bh[nt], uBh + boff + off);
                ldsm_x2(bl[nt], uBl + boff + off);
            }
#pragma unroll
            for (int mt = 0; mt < 2; mt++)
#pragma unroll
                for (int nt = 0; nt < 4; nt++) {
                    mma16816(acc[mt][nt], ah[mt], bh[nt]);
                    mma16816(acc[mt][nt], ah[mt], bl[nt]);
                    mma16816(acc[mt][nt], al[mt], bh[nt]);
                }
        }
        if (it < 7) {
            int bb = (it + 1) & 1;
            __nv_bfloat16* pAh = dyn + bb * A_ELEMS;
            __nv_bfloat16* pAl = dyn + OFF_AL + bb * A_ELEMS;
            __nv_bfloat16* pBh = dyn + OFF_BH + bb * B_ELEMS;
            __nv_bfloat16* pBl = dyn + OFF_BL + bb * B_ELEMS;
#pragma unroll
            for (int r = 0; r < 4; r++) {
                int idx = tid + r * 256, row = idx >> 3, c = (idx & 7) * 4;
                float4 v = pA[r];
                __nv_bfloat16 h0, l0, h1, l1, h2, l2, h3, l3;
                splitbf(v.x, h0, l0); splitbf(v.y, h1, l1);
                splitbf(v.z, h2, l2); splitbf(v.w, h3, l3);
                *(__nv_bfloat162*)&pAh[row * SA_ + c]     = __halves2bfloat162(h0, h1);
                *(__nv_bfloat162*)&pAh[row * SA_ + c + 2] = __halves2bfloat162(h2, h3);
                *(__nv_bfloat162*)&pAl[row * SA_ + c]     = __halves2bfloat162(l0, l1);
                *(__nv_bfloat162*)&pAl[row * SA_ + c + 2] = __halves2bfloat162(l2, l3);
            }
#pragma unroll
            for (int r = 0; r < 8; r++) {
                int idx = tid + r * 256, n = idx & 63, k = idx >> 6;
                __nv_bfloat16 h, l; splitbf(pB[r], h, l);
                pBh[n * SA_ + k] = h; pBl[n * SA_ + k] = l;
            }
            __syncthreads();
        }
    }
#pragma unroll
    for (int mt = 0; mt < 2; mt++) {
        int r0 = m0 + wm + mt * 16 + g;
        int r1 = r0 + 8;
        int node0 = (r0 >> 4) * N_PARTP + N_NUCP + (r0 & 15);
        int node1 = (r1 >> 4) * N_PARTP + N_NUCP + (r1 & 15);
#pragma unroll
        for (int nt = 0; nt < 4; nt++) {
            int cn = n0 + wn + nt * 8 + 2 * t;
            float bs0 = sBias[cn - n0], bs1 = sBias[cn - n0 + 1];
            float2 o0 = make_float2(acc[mt][nt][0] + bs0, acc[mt][nt][1] + bs1);
            float2 o1 = make_float2(acc[mt][nt][2] + bs0, acc[mt][nt][3] + bs1);
            *(float2*)(g_hx + (size_t)node0 * K_ + cn) = o0;
            *(float2*)(g_hx + (size_t)node1 * K_ + cn) = o1;
        }
    }
}

// ============================================================
// K5: PERSISTENT edge MLP — 128-edge tiles, 4m x 2n warps,
// stage-2 in two N=64 passes; bf16-split mma + ldmatrix + RED scatter
// ============================================================
#define SE_ 72
#define EDGE_BLOCKS 96
// smem byte offsets
#define EO_XH   0
#define EO_XL   18432
#define EO_W1H  36864
#define EO_W1L  46080
#define EO_W2H  55296
#define EO_W2L  73728
#define EO_B1   92160
#define EO_B2   92416
#define EO_SEND 92928
#define EO_ZROW 93440
#define EO_EID  93952
#define EDGE_SMEM_BYTES 94464

struct EdgeParams {
    const float* W1[3]; const float* b1[3];
    const float* W2[3]; const float* b2[3];
};

__global__ void __launch_bounds__(256)
k_edge(EdgeParams P,
       const float* __restrict__ dist,
       const int* __restrict__ senders,
       const int* __restrict__ receivers) {
    extern __shared__ __align__(16) char smc[];
    __nv_bfloat16* sXh  = (__nv_bfloat16*)(smc + EO_XH);    // 128*72 (overlay Hh)
    __nv_bfloat16* sXl  = (__nv_bfloat16*)(smc + EO_XL);    // 128*72 (overlay Hl)
    __nv_bfloat16* sW1h = (__nv_bfloat16*)(smc + EO_W1H);   // 64n x 72
    __nv_bfloat16* sW1l = (__nv_bfloat16*)(smc + EO_W1L);
    __nv_bfloat16* sW2h = (__nv_bfloat16*)(smc + EO_W2H);   // 128n x 72
    __nv_bfloat16* sW2l = (__nv_bfloat16*)(smc + EO_W2L);
    float* sb1 = (float*)(smc + EO_B1);   // 64
    float* sb2 = (float*)(smc + EO_B2);   // 128
    int* sSend = (int*)(smc + EO_SEND);   // 128
    int* sZrow = (int*)(smc + EO_ZROW);   // 128
    int* sEid  = (int*)(smc + EO_EID);    // 128
    __nv_bfloat16* sHh = sXh;
    __nv_bfloat16* sHl = sXl;

    int ty_ = blockIdx.y;
    int cnt = g_cnt[ty_];
    int tid = threadIdx.x, lane = tid & 31, w = tid >> 5;
    int g = lane >> 2, t = lane & 3;

    // ---- weights ONCE per block ----
    {
        const float* W1 = P.W1[ty_]; const float* W2 = P.W2[ty_];
#pragma unroll
        for (int r = 0; r < 16; r++) {
            int idx = tid + r * 256;       // 4096 = 64n x 64k
            int n = idx >> 6, k = idx & 63;
            __nv_bfloat16 h, l; splitbf(W1[k * D_ + n], h, l);
            sW1h[n * SE_ + k] = h; sW1l[n * SE_ + k] = l;
        }
#pragma unroll
        for (int r = 0; r < 32; r++) {
            int idx = tid + r * 256;       // 8192 = 128n x 64k
            int n = idx >> 6, k = idx & 63;
            __nv_bfloat16 h, l; splitbf(W2[k * K_ + n], h, l);
            sW2h[n * SE_ + k] = h; sW2l[n * SE_ + k] = l;
        }
        if (tid < 64)  sb1[tid] = P.b1[ty_][tid];
        if (tid < 128) sb2[tid] = P.b2[ty_][tid];
    }

    // warp layout: 4(m) x 2(n); m-range 32 rows, n-range 32 cols
    int wm = (w & 3) * 32;
    int wn = (w >> 2) * 32;
    float* zbase = g_z + (size_t)ty_ * N_EROWS * K_;

    // ldmatrix per-lane source rows
    int aRow = (lane & 7) + ((lane >> 3) & 1) * 8;
    int aK   = ((lane >> 4) & 1) * 8;
    int bRow = lane & 7;
    int bK   = ((lane >> 3) & 1) * 8;
    uint32_t uXh = (uint32_t)__cvta_generic_to_shared(&sXh[(wm + aRow) * SE_ + aK]);
    uint32_t uXl = (uint32_t)__cvta_generic_to_shared(&sXl[(wm + aRow) * SE_ + aK]);
    uint32_t uW1h = (uint32_t)__cvta_generic_to_shared(&sW1h[(wn + bRow) * SE_ + bK]);
    uint32_t uW1l = (uint32_t)__cvta_generic_to_shared(&sW1l[(wn + bRow) * SE_ + bK]);
    uint32_t uW2h = (uint32_t)__cvta_generic_to_shared(&sW2h[(wn + bRow) * SE_ + bK]);
    uint32_t uW2l = (uint32_t)__cvta_generic_to_shared(&sW2l[(wn + bRow) * SE_ + bK]);

    for (int e0 = blockIdx.x * 128; e0 < cnt; e0 += EDGE_BLOCKS * 128) {
        int ne = min(128, cnt - e0);
        __syncthreads();   // weights ready (1st iter) / prior-iter readers done

        // ---- metadata (128 edges) ----
        if (tid < 128) {
            int sv = 0, zr = 0, eid = 0;
            if (tid < ne) {
                eid = g_list[ty_ * E_ + e0 + tid];
                sv  = senders[eid];
                int r = receivers[eid];
                zr  = (r / N_PARTP) * N_ELECP + (r % N_PARTP) - N_NUCP;
            }
            sSend[tid] = sv; sZrow[tid] = zr; sEid[tid] = eid;
        }
        __syncthreads();

        // ---- X tile: 128 rows x 64 fp32 -> split into sXh/sXl ----
#pragma unroll
        for (int r = 0; r < 8; r++) {
            int idx = tid + r * 256;           // 2048 float4 total
            int row = idx >> 4, c4 = idx & 15;
            float4 v = make_float4(0.f, 0.f, 0.f, 0.f);
            if (row < ne)
                v = ((const float4*)(dist + (size_t)sEid[row] * D_))[c4];
            int c = c4 * 4;
            __nv_bfloat16 h0, l0, h1, l1, h2, l2, h3, l3;
            splitbf(v.x, h0, l0); splitbf(v.y, h1, l1);
            splitbf(v.z, h2, l2); splitbf(v.w, h3, l3);
            *(__nv_bfloat162*)&sXh[row * SE_ + c]     = __halves2bfloat162(h0, h1);
            *(__nv_bfloat162*)&sXh[row * SE_ + c + 2] = __halves2bfloat162(h2, h3);
            *(__nv_bfloat162*)&sXl[row * SE_ + c]     = __halves2bfloat162(l0, l1);
            *(__nv_bfloat162*)&sXl[row * SE_ + c + 2] = __halves2bfloat162(l2, l3);
        }
        __syncthreads();

        // ---- stage 1: H = ssp(X @ W1 + b1)  (128x64), warp tile 32x32 ----
        float acc1[2][4][4];
#pragma unroll
        for (int a = 0; a < 2; a++)
#pragma unroll
            for (int b = 0; b < 4; b++)
#pragma unroll
                for (int c = 0; c < 4; c++) acc1[a][b][c] = 0.f;
#pragma unroll
        for (int s = 0; s < 4; s++) {
            uint32_t ah[2][4], al[2][4], bh[4][2], bl[4][2];
#pragma unroll
            for (int mt = 0; mt < 2; mt++) {
                uint32_t off = (uint32_t)((mt * 16 * SE_ + s * 16) * 2);
                ldsm_x4(ah[mt], uXh + off);
                ldsm_x4(al[mt], uXl + off);
            }
#pragma unroll
            for (int nt = 0; nt < 4; nt++) {
                uint32_t off = (uint32_t)((nt * 8 * SE_ + s * 16) * 2);
                ldsm_x2(bh[nt], uW1h + off);
                ldsm_x2(bl[nt], uW1l + off);
            }
#pragma unroll
            for (int mt = 0; mt < 2; mt++)
#pragma unroll
                for (int nt = 0; nt < 4; nt++) {
                    mma16816(acc1[mt][nt], ah[mt], bh[nt]);
                    mma16816(acc1[mt][nt], ah[mt], bl[nt]);
                    mma16816(acc1[mt][nt], al[mt], bh[nt]);
                }
        }
        __syncthreads();   // all reads of sX done; safe to overlay H

        // ssp + split + write H (overlay over sX)
#pragma unroll
        for (int mt = 0; mt < 2; mt++) {
#pragma unroll
            for (int nt = 0; nt < 4; nt++) {
                int col = wn + nt * 8 + 2 * t;
                float b0 = sb1[col], b1v = sb1[col + 1];
                int r0 = wm + mt * 16 + g;
#pragma unroll
                for (int hr = 0; hr < 2; hr++) {
                    int row = r0 + hr * 8;
                    float x0 = acc1[mt][nt][hr * 2 + 0] + b0;
                    float x1 = acc1[mt][nt][hr * 2 + 1] + b1v;
                    float v0 = fmaxf(x0, 0.f) + log1pf(expf(-fabsf(x0))) - LOG2F_;
                    float v1 = fmaxf(x1, 0.f) + log1pf(expf(-fabsf(x1))) - LOG2F_;
                    __nv_bfloat16 h0, l0, h1, l1;
                    splitbf(v0, h0, l0); splitbf(v1, h1, l1);
                    *(__nv_bfloat162*)&sHh[row * SE_ + col] = __halves2bfloat162(h0, h1);
                    *(__nv_bfloat162*)&sHl[row * SE_ + col] = __halves2bfloat162(l0, l1);
                }
            }
        }
        __syncthreads();

        // ---- stage 2: WE = H @ W2 + b2 (128x128), two N=64 passes ----
#pragma unroll
        for (int np = 0; np < 2; np++) {
            float acc2[2][4][4];
#pragma unroll
            for (int a = 0; a < 2; a++)
#pragma unroll
                for (int b = 0; b < 4; b++)
#pragma unroll
                    for (int c = 0; c < 4; c++) acc2[a][b][c] = 0.f;
            uint32_t wOff = (uint32_t)(np * 64 * SE_ * 2);
#pragma unroll
            for (int s = 0; s < 4; s++) {
                uint32_t ah[2][4], al[2][4], bh[4][2], bl[4][2];
#pragma unroll
                for (int mt = 0; mt < 2; mt++) {
                    uint32_t off = (uint32_t)((mt * 16 * SE_ + s * 16) * 2);
                    ldsm_x4(ah[mt], uXh + off);   // sHh overlays sXh
                    ldsm_x4(al[mt], uXl + off);
                }
#pragma unroll
                for (int nt = 0; nt < 4; nt++) {
                    uint32_t off = (uint32_t)((nt * 8 * SE_ + s * 16) * 2);
                    ldsm_x2(bh[nt], uW2h + wOff + off);
                    ldsm_x2(bl[nt], uW2l + wOff + off);
                }
#pragma unroll
                for (int mt = 0; mt < 2; mt++)
#pragma unroll
                    for (int nt = 0; nt < 4; nt++) {
                        mma16816(acc2[mt][nt], ah[mt], bh[nt]);
                        mma16816(acc2[mt][nt], ah[mt], bl[nt]);
                        mma16816(acc2[mt][nt], al[mt], bh[nt]);
                    }
            }
            // epilogue for this N-half: weh = (WE+b2)*hx[sender]; RED scatter
#pragma unroll
            for (int mt = 0; mt < 2; mt++) {
#pragma unroll
                for (int hr = 0; hr < 2; hr++) {
                    int e = wm + mt * 16 + g + hr * 8;
                    if (e < ne) {
                        int sv = sSend[e], zr = sZrow[e];
                        const float* hx = g_hx + (size_t)sv * K_;
                        float* zp = zbase + (size_t)zr * K_;
#pragma unroll
                        for (int nt = 0; nt < 4; nt++) {
                            int col = np * 64 + wn + nt * 8 + 2 * t;
                            float2 h2 = *(const float2*)(hx + col);
                            float v0 = (acc2[mt][nt][hr * 2 + 0] + sb2[col])     * h2.x;
                            float v1 = (acc2[mt][nt][hr * 2 + 1] + sb2[col + 1]) * h2.y;
                            red2(zp + col, v0, v1);
                        }
                    }
                }
            }
        }
    }
}

// ============================================================
// K6: out = elec + [z] @ [g..] + Σb — bf16-split mma + ldmatrix + DOUBLE BUFFER [verified R15]
// ============================================================
__global__ void __launch_bounds__(256)
k_out_mma(const float* __restrict__ elec,
          const float* __restrict__ gW0, const float* __restrict__ gW1,
          const float* __restrict__ gW2,
          const float* __restrict__ gb0, const float* __restrict__ gb1,
          const float* __restrict__ gb2,
          float* __restrict__ out) {
    extern __shared__ __align__(16) __nv_bfloat16 dyn[];
    __shared__ float sBias[64];
    int tid = threadIdx.x, lane = tid & 31, w = tid >> 5;
    int wm = (w & 3) * 32, wn = (w >> 2) * 32;
    int g = lane >> 2, t = lane & 3;
    int m0 = blockIdx.x * 128, n0 = blockIdx.y * 64;
    if (tid < 64)
        sBias[tid] = gb0[n0 + tid] + gb1[n0 + tid] + gb2[n0 + tid];

    int aRow = (lane & 7) + ((lane >> 3) & 1) * 8;
    int aK   = ((lane >> 4) & 1) * 8;
    int bRow = lane & 7;
    int bK   = ((lane >> 3) & 1) * 8;
    uint32_t uAh = (uint32_t)__cvta_generic_to_shared(&dyn[(wm + aRow) * SA_ + aK]);
    uint32_t uAl = uAh + OFF_AL * 2;
    uint32_t uBh = (uint32_t)__cvta_generic_to_shared(&dyn[OFF_BH + (wn + bRow) * SA_ + bK]);
    uint32_t uBl = uBh + 2 * B_ELEMS * 2;

    float acc[2][4][4];
#pragma unroll
    for (int a = 0; a < 2; a++)
#pragma unroll
        for (int b = 0; b < 4; b++)
#pragma unroll
            for (int c = 0; c < 4; c++) acc[a][b][c] = 0.f;

    float4 pA[4]; float pB[8];
    {
        const float* Az = g_z + (size_t)m0 * K_;
#pragma unroll
        for (int r = 0; r < 4; r++) {
            int idx = tid + r * 256, row = idx >> 3, c4 = idx & 7;
            pA[r] = *(const float4*)(Az + (size_t)row * K_ + c4 * 4);
        }
#pragma unroll
        for (int r = 0; r < 8; r++) {
            int idx = tid + r * 256, n = idx & 63, k = idx >> 6;
            pB[r] = gW0[(size_t)k * EMB_ + n0 + n];
        }
    }
    {
        __nv_bfloat16* pAh = dyn;
        __nv_bfloat16* pAl = dyn + OFF_AL;
        __nv_bfloat16* pBh = dyn + OFF_BH;
        __nv_bfloat16* pBl = dyn + OFF_BL;
#pragma unroll
        for (int r = 0; r < 4; r++) {
            int idx = tid + r * 256, row = idx >> 3, c = (idx & 7) * 4;
            float4 v = pA[r];
            __nv_bfloat16 h0, l0, h1, l1, h2, l2, h3, l3;
            splitbf(v.x, h0, l0); splitbf(v.y, h1, l1);
            splitbf(v.z, h2, l2); splitbf(v.w, h3, l3);
            *(__nv_bfloat162*)&pAh[row * SA_ + c]     = __halves2bfloat162(h0, h1);
            *(__nv_bfloat162*)&pAh[row * SA_ + c + 2] = __halves2bfloat162(h2, h3);
            *(__nv_bfloat162*)&pAl[row * SA_ + c]     = __halves2bfloat162(l0, l1);
            *(__nv_bfloat162*)&pAl[row * SA_ + c + 2] = __halves2bfloat162(l2, l3);
        }
#pragma unroll
        for (int r = 0; r < 8; r++) {
            int idx = tid + r * 256, n = idx & 63, k = idx >> 6;
            __nv_bfloat16 h, l; splitbf(pB[r], h, l);
            pBh[n * SA_ + k] = h; pBl[n * SA_ + k] = l;
        }
    }
    __syncthreads();

    for (int it = 0; it < 12; it++) {
        int cur = it & 1;
        if (it < 11) {
            int k0 = (it + 1) * 32;
            int tsel = k0 >> 7, kc = k0 & 127;
            const float* Az = g_z + (size_t)tsel * N_EROWS * K_ +
                              (size_t)m0 * K_ + kc;
            const float* Bw = (tsel == 0) ? gW0 : ((tsel == 1) ? gW1 : gW2);
#pragma unroll
            for (int r = 0; r < 4; r++) {
                int idx = tid + r * 256, row = idx >> 3, c4 = idx & 7;
                pA[r] = *(const float4*)(Az + (size_t)row * K_ + c4 * 4);
            }
#pragma unroll
            for (int r = 0; r < 8; r++) {
                int idx = tid + r * 256, n = idx & 63, k = idx >> 6;
                pB[r] = Bw[(size_t)(kc + k) * EMB_ + n0 + n];
            }
        }
        uint32_t aoff = (uint32_t)cur * (A_ELEMS * 2);
        uint32_t boff = (uint32_t)cur * (B_ELEMS * 2);
#pragma unroll
        for (int s = 0; s < 2; s++) {
            uint32_t ah[2][4], al[2][4], bh[4][2], bl[4][2];
#pragma unroll
            for (int mt = 0; mt < 2; mt++) {
                uint32_t off = (uint32_t)((mt * 16 * SA_ + s * 16) * 2);
                ldsm_x4(ah[mt], uAh + aoff + off);
                ldsm_x4(al[mt], uAl + aoff + off);
            }
#pragma unroll
            for (int nt = 0; nt < 4; nt++) {
                uint32_t off = (uint32_t)((nt * 8 * SA_ + s * 16) * 2);
                ldsm_x2(bh[nt], uBh + boff + off);
                ldsm_x2(bl[nt], uBl + boff + off);
            }
#pragma unroll
            for (int mt = 0; mt < 2; mt++)
#pragma unroll
                for (int nt = 0; nt < 4; nt++) {
                    mma16816(acc[mt][nt], ah[mt], bh[nt]);
                    mma16816(acc[mt][nt], ah[mt], bl[nt]);
                    mma16816(acc[mt][nt], al[mt], bh[nt]);
                }
        }
        if (it < 11) {
            int bb = (it + 1) & 1;
            __nv_bfloat16* pAh = dyn + bb * A_ELEMS;
            __nv_bfloat16* pAl = dyn + OFF_AL + bb * A_ELEMS;
            __nv_bfloat16* pBh = dyn + OFF_BH + bb * B_ELEMS;
            __nv_bfloat16* pBl = dyn + OFF_BL + bb * B_ELEMS;
#pragma unroll
            for (int r = 0; r < 4; r++) {
                int idx = tid + r * 256, row = idx >> 3, c = (idx & 7) * 4;
                float4 v = pA[r];
                __nv_bfloat16 h0, l0, h1, l1, h2, l2, h3, l3;
                splitbf(v.x, h0, l0); splitbf(v.y, h1, l1);
                splitbf(v.z, h2, l2); splitbf(v.w, h3, l3);
                *(__nv_bfloat162*)&pAh[row * SA_ + c]     = __halves2bfloat162(h0, h1);
                *(__nv_bfloat162*)&pAh[row * SA_ + c + 2] = __halves2bfloat162(h2, h3);
                *(__nv_bfloat162*)&pAl[row * SA_ + c]     = __halves2bfloat162(l0, l1);
                *(__nv_bfloat162*)&pAl[row * SA_ + c + 2] = __halves2bfloat162(l2, l3);
            }
#pragma unroll
            for (int r = 0; r < 8; r++) {
                int idx = tid + r * 256, n = idx & 63, k = idx >> 6;
                __nv_bfloat16 h, l; splitbf(pB[r], h, l);
                pBh[n * SA_ + k] = h; pBl[n * SA_ + k] = l;
            }
            __syncthreads();
        }
    }
#pragma unroll
    for (int mt = 0; mt < 2; mt++) {
        int r0 = m0 + wm + mt * 16 + g;
        int r1 = r0 + 8;
#pragma unroll
        for (int nt = 0; nt < 4; nt++) {
            int cn = n0 + wn + nt * 8 + 2 * t;
            float2 e0 = *(const float2*)(elec + (size_t)r0 * EMB_ + cn);
            float2 e1 = *(const float2*)(elec + (size_t)r1 * EMB_ + cn);
            float bs0 = sBias[cn - n0], bs1 = sBias[cn - n0 + 1];
            float2 o0 = make_float2(acc[mt][nt][0] + e0.x + bs0,
                                    acc[mt][nt][1] + e0.y + bs1);
            float2 o1 = make_float2(acc[mt][nt][2] + e1.x + bs0,
                                    acc[mt][nt][3] + e1.y + bs1);
            *(float2*)(out + (size_t)r0 * EMB_ + cn) = o0;
            *(float2*)(out + (size_t)r1 * EMB_ + cn) = o1;
        }
    }
}

// ============================================================
// launch
// ============================================================
extern "C" void kernel_launch(void* const* d_in, const int* in_sizes, int n_in,
                              void* d_out, int out_size) {
    const float* nuc       = (const float*)d_in[0];
    const float* elec      = (const float*)d_in[1];
    const float* dist      = (const float*)d_in[2];
    const int*   e_type    = (const int*)d_in[3];
    const int*   senders   = (const int*)d_in[4];
    const int*   receivers = (const int*)d_in[5];
    EdgeParams P;
    P.W1[0] = (const float*)d_in[6];  P.b1[0] = (const float*)d_in[7];
    P.W2[0] = (const float*)d_in[8];  P.b2[0] = (const float*)d_in[9];
    P.W1[1] = (const float*)d_in[10]; P.b1[1] = (const float*)d_in[11];
    P.W2[1] = (const float*)d_in[12]; P.b2[1] = (const float*)d_in[13];
    P.W1[2] = (const float*)d_in[14]; P.b1[2] = (const float*)d_in[15];
    P.W2[2] = (const float*)d_in[16]; P.b2[2] = (const float*)d_in[17];
    const float* hW  = (const float*)d_in[18];
    const float* hb  = (const float*)d_in[19];
    const float* gsW = (const float*)d_in[20];
    const float* gsb = (const float*)d_in[21];
    const float* gaW = (const float*)d_in[22];
    const float* gab = (const float*)d_in[23];
    const float* gnW = (const float*)d_in[24];
    const float* gnb = (const float*)d_in[25];
    float* out = (float*)d_out;

    const int GEMM_SMEM = DYN_ELEMS * 2;   // 61440 B
    cudaFuncSetAttribute(k_edge, cudaFuncAttributeMaxDynamicSharedMemorySize,
                         EDGE_SMEM_BYTES);
    cudaFuncSetAttribute(k_hx_mma, cudaFuncAttributeMaxDynamicSharedMemorySize,
                         GEMM_SMEM);
    cudaFuncSetAttribute(k_out_mma, cudaFuncAttributeMaxDynamicSharedMemorySize,
                         GEMM_SMEM);

    k_zero<<<(3 * N_EROWS * K_ / 4 + 255) / 256, 256>>>();
    k_bin<<<(E_ + 255) / 256, 256>>>(e_type, receivers);
    k_hx_nuc<<<(B_ * N_NUCP * K_ / 4 + 255) / 256, 256>>>(nuc);
    dim3 gh(N_EROWS / 128, K_ / 64);
    k_hx_mma<<<gh, 256, GEMM_SMEM>>>(elec, hW, hb);
    dim3 ge(EDGE_BLOCKS, 3);
    k_edge<<<ge, 256, EDGE_SMEM_BYTES>>>(P, dist, senders, receivers);
    dim3 go(N_EROWS / 128, EMB_ / 64);
    k_out_mma<<<go, 256, GEMM_SMEM>>>(elec, gsW, gaW, gnW, gsb, gab, gnb, out);
}